// round 8
// baseline (speedup 1.0000x reference)
#include <cuda_runtime.h>
#include <cuda_fp16.h>
#include <cstdint>

#define NB  2
#define SEQ 1024
#define DIM 1024
#define NH  16
#define DK  64
#define FF  4096
#define NL  4
#define MROWS (NB*SEQ)
#define QKVW 3072
#define QMAX 16256.0f

// ---------------- PTX helpers ------------------------------------------------
__device__ __forceinline__ uint32_t smem_to_u32(const void* p) {
    uint32_t a;
    asm("{ .reg .u64 t; cvta.to.shared.u64 t, %1; cvt.u32.u64 %0, t; }" : "=r"(a) : "l"(p));
    return a;
}
__device__ __forceinline__ void cpasync16(uint32_t dst, const void* src) {
    asm volatile("cp.async.cg.shared.global [%0], [%1], 16;"
                 :: "r"(dst), "l"(__cvta_generic_to_global(src)) : "memory");
}
__device__ __forceinline__ void cpcommit() { asm volatile("cp.async.commit_group;" ::: "memory"); }
__device__ __forceinline__ void cpwait0()  { asm volatile("cp.async.wait_group 0;" ::: "memory"); }
__device__ __forceinline__ void cpwait1()  { asm volatile("cp.async.wait_group 1;" ::: "memory"); }
__device__ __forceinline__ void ldsm4(uint32_t& r0, uint32_t& r1, uint32_t& r2, uint32_t& r3, uint32_t a) {
    asm volatile("ldmatrix.sync.aligned.m8n8.x4.shared.b16 {%0,%1,%2,%3}, [%4];"
                 : "=r"(r0), "=r"(r1), "=r"(r2), "=r"(r3) : "r"(a));
}
__device__ __forceinline__ void ldsm2(uint32_t& r0, uint32_t& r1, uint32_t a) {
    asm volatile("ldmatrix.sync.aligned.m8n8.x2.shared.b16 {%0,%1}, [%2];"
                 : "=r"(r0), "=r"(r1) : "r"(a));
}
__device__ __forceinline__ void ldsm4t(uint32_t& r0, uint32_t& r1, uint32_t& r2, uint32_t& r3, uint32_t a) {
    asm volatile("ldmatrix.sync.aligned.m8n8.x4.trans.shared.b16 {%0,%1,%2,%3}, [%4];"
                 : "=r"(r0), "=r"(r1), "=r"(r2), "=r"(r3) : "r"(a));
}
__device__ __forceinline__ void mmaF(float* d, const uint32_t* a, const uint32_t* b) {
    asm volatile("mma.sync.aligned.m16n8k16.row.col.f32.f16.f16.f32 "
                 "{%0,%1,%2,%3}, {%4,%5,%6,%7}, {%8,%9}, {%0,%1,%2,%3};"
                 : "+f"(d[0]), "+f"(d[1]), "+f"(d[2]), "+f"(d[3])
                 : "r"(a[0]), "r"(a[1]), "r"(a[2]), "r"(a[3]), "r"(b[0]), "r"(b[1]));
}
__device__ __forceinline__ void imma(int* d, const uint32_t* a, const uint32_t* b) {
    asm volatile("mma.sync.aligned.m16n8k32.row.col.s32.s8.s8.s32 "
                 "{%0,%1,%2,%3}, {%4,%5,%6,%7}, {%8,%9}, {%0,%1,%2,%3};"
                 : "+r"(d[0]), "+r"(d[1]), "+r"(d[2]), "+r"(d[3])
                 : "r"(a[0]), "r"(a[1]), "r"(a[2]), "r"(a[3]), "r"(b[0]), "r"(b[1]));
}
__device__ __forceinline__ uint32_t packh(float a, float b) {
    __half2 h = __floats2half2_rn(a, b);
    return *(uint32_t*)&h;
}
__device__ __forceinline__ uint32_t pack4b(int a, int b, int c, int d) {
    return (uint32_t)(a & 0xff) | ((uint32_t)(b & 0xff) << 8) |
           ((uint32_t)(c & 0xff) << 16) | ((uint32_t)(d & 0xff) << 24);
}
__device__ __forceinline__ void dig2(int q, int& hi, int& lo) {
    hi = (q + 64) >> 7;
    lo = q - (hi << 7);
}

// ---------------- scratch -----------------------------------------------------
__device__ float g_X  [MROWS*DIM];
__device__ float g_X1 [MROWS*DIM];
__device__ float g_Yb [MROWS*DIM];
__device__ float g_O  [MROWS*DIM];
__device__ float g_Hid[MROWS*FF];
__device__ __half g_QKVhi[MROWS*QKVW], g_QKVlo[MROWS*QKVW];
__device__ int8_t g_Aq1[MROWS*FF], g_Aq0[MROWS*FF];
__device__ int8_t g_Xq1[MROWS*DIM], g_Xq0[MROWS*DIM];
__device__ int8_t g_X1q1[MROWS*DIM], g_X1q0[MROWS*DIM];
__device__ float  g_saA[MROWS], g_saX[MROWS], g_saX1[MROWS];
__device__ int8_t g_W1d[64u*1024*1024];
__device__ int8_t g_W0d[64u*1024*1024];
__device__ uint32_t g_sbBits[NL*13312];
__device__ float    g_sbW [NL*13312];
__device__ float    g_sbInv[NL*13312];
__device__ float    g_bQKV1[NL*QKVW], g_bQKV2[NL*QKVW];

#define LAYER_W (16u*1024*1024)
#define OFF_Q1  (0u)
#define OFF_O1  (3u*1024*1024)
#define OFF_Q2  (4u*1024*1024)
#define OFF_O2  (7u*1024*1024)
#define OFF_W1  (8u*1024*1024)
#define OFF_W2  (12u*1024*1024)
#define LAYER_S 13312
#define S_Q1 0
#define S_O1 3072
#define S_Q2 4096
#define S_O2 7168
#define S_W1 8192
#define S_W2 12288

// ---------------- per-row quantize -------------------------------------------
__global__ __launch_bounds__(256) void quant_row(const float* __restrict__ X,
        int8_t* __restrict__ q1, int8_t* __restrict__ q0, float* __restrict__ sa, int N)
{
    const int row = blockIdx.x, tid = threadIdx.x;
    const float* xr = X + (size_t)row * N;
    const int nc = N >> 10;
    float4 v[4];
    float mx = 0.f;
#pragma unroll 4
    for (int c = 0; c < nc; c++) {
        v[c] = ((const float4*)(xr + (c << 10)))[tid];
        mx = fmaxf(mx, fmaxf(fmaxf(fabsf(v[c].x), fabsf(v[c].y)),
                             fmaxf(fabsf(v[c].z), fabsf(v[c].w))));
    }
#pragma unroll
    for (int off = 16; off; off >>= 1)
        mx = fmaxf(mx, __shfl_xor_sync(0xffffffffu, mx, off));
    __shared__ float sm[8];
    if ((tid & 31) == 0) sm[tid >> 5] = mx;
    __syncthreads();
    mx = 1e-30f;
#pragma unroll
    for (int w = 0; w < 8; w++) mx = fmaxf(mx, sm[w]);
    if (tid == 0) sa[row] = mx / QMAX;
    const float inv = QMAX / mx;
#pragma unroll 4
    for (int c = 0; c < nc; c++) {
        int qa = __float2int_rn(v[c].x*inv), qb = __float2int_rn(v[c].y*inv);
        int qd = __float2int_rn(v[c].z*inv), qe = __float2int_rn(v[c].w*inv);
        int h0,l0,h1,l1,h2,l2,h3,l3;
        dig2(qa,h0,l0); dig2(qb,h1,l1); dig2(qd,h2,l2); dig2(qe,h3,l3);
        size_t base = (size_t)row * N + (c << 10);
        ((uint32_t*)(q1 + base))[tid] = pack4b(h0,h1,h2,h3);
        ((uint32_t*)(q0 + base))[tid] = pack4b(l0,l1,l2,l3);
    }
}

// ---------------- weight prep -------------------------------------------------
__global__ __launch_bounds__(256) void wmax_t(const float* __restrict__ W,
        uint32_t* __restrict__ bits, int K, int N, size_t inStride, int scaleOff, int headMode)
{
    int tx = threadIdx.x & 31, ty = threadIdx.x >> 5;
    int k0 = blockIdx.x * 32, n0 = blockIdx.y * 32;
    const float* Win = W + (size_t)blockIdx.z * inStride;
    float m = 0.f;
#pragma unroll
    for (int i = 0; i < 4; i++) {
        int k = k0 + ty + 8*i, n = n0 + tx;
        size_t idx = headMode ? ((size_t)(n >> 6) * K * 64 + (size_t)k * 64 + (n & 63))
                              : ((size_t)k * N + n);
        m = fmaxf(m, fabsf(Win[idx]));
    }
    __shared__ float sm[8][32];
    sm[ty][tx] = m;
    __syncthreads();
    if (ty == 0) {
        float mm = 0.f;
#pragma unroll
        for (int w = 0; w < 8; w++) mm = fmaxf(mm, sm[w][tx]);
        atomicMax(&bits[blockIdx.z * LAYER_S + scaleOff + n0 + tx], __float_as_uint(mm));
    }
}

__global__ __launch_bounds__(256) void wscale(const uint32_t* __restrict__ bits,
        float* __restrict__ s, float* __restrict__ inv, int n)
{
    int i = blockIdx.x * 256 + threadIdx.x;
    if (i >= n) return;
    float m = fmaxf(__uint_as_float(bits[i]), 1e-30f);
    s[i] = m / QMAX;
    inv[i] = QMAX / m;
}

__global__ __launch_bounds__(256) void wquant_t(const float* __restrict__ W,
        int8_t* __restrict__ o1, int8_t* __restrict__ o0, const float* __restrict__ inv,
        int K, int N, size_t inStride, size_t outOff, int scaleOff, int headMode)
{
    __shared__ float t[32][33];
    int tx = threadIdx.x & 31, ty = threadIdx.x >> 5;
    int k0 = blockIdx.x * 32, n0 = blockIdx.y * 32;
    const float* Win = W + (size_t)blockIdx.z * inStride;
    size_t ob = (size_t)blockIdx.z * LAYER_W + outOff;
    const float* invL = inv + blockIdx.z * LAYER_S + scaleOff;
#pragma unroll
    for (int i = 0; i < 4; i++) {
        int k = k0 + ty + 8*i, n = n0 + tx;
        size_t idx = headMode ? ((size_t)(n >> 6) * K * 64 + (size_t)k * 64 + (n & 63))
                              : ((size_t)k * N + n);
        t[ty + 8*i][tx] = Win[idx];
    }
    __syncthreads();
    int nl = threadIdx.x >> 3, kq = threadIdx.x & 7;
    int n = n0 + nl;
    float iv = invL[n];
    int h[4], l[4];
#pragma unroll
    for (int j = 0; j < 4; j++) {
        int q = __float2int_rn(t[4*kq + j][nl] * iv);
        dig2(q, h[j], l[j]);
    }
    size_t base = ob + (size_t)n * K + k0 + 4*kq;
    *(uint32_t*)(o1 + base) = pack4b(h[0], h[1], h[2], h[3]);
    *(uint32_t*)(o0 + base) = pack4b(l[0], l[1], l[2], l[3]);
}

__global__ __launch_bounds__(256) void pack_bias(const float* __restrict__ bq,
        const float* __restrict__ bk, const float* __restrict__ bv, float* __restrict__ out)
{
    int l = blockIdx.y;
    int i = blockIdx.x * 256 + threadIdx.x;
    out[l*QKVW + i]        = bq[l*1024 + i];
    out[l*QKVW + 1024 + i] = bk[l*1024 + i];
    out[l*QKVW + 2048 + i] = bv[l*1024 + i];
}

// ---------------- int8 two-digit IMMA GEMM (register-safe: CTA 64x128) ---------
// Per-thread accs: 4x2x4x2 = 64 regs. Warp tile 64x16, 8 warps across N.
#define QRS 80
#define IA0 5120
#define IB1 10240
#define IB0 20480
#define ISTAGE 30720
#define GEMM_I8_SMEM (2*ISTAGE)   // 61440

__global__ __launch_bounds__(256, 1) void gemm_i8(
        const int8_t* __restrict__ A1, const int8_t* __restrict__ A0,
        const float* __restrict__ saA,
        const int8_t* __restrict__ B1, const int8_t* __restrict__ B0,
        const float* __restrict__ sbB,
        const float* __restrict__ bias, const float* __restrict__ R,
        float* __restrict__ C, __half* __restrict__ Chi, __half* __restrict__ Clo,
        int N, int K, int relu, const int* __restrict__ mskp)
{
    const int m0 = blockIdx.y * 64, n0 = blockIdx.x * 128;
    if (mskp && ((m0 & 1023) >= *mskp) && (n0 >= 1024)) return;
    extern __shared__ char smem[];
    const uint32_t sb = smem_to_u32(smem);
    const int tid = threadIdx.x, lane = tid & 31, wn = tid >> 5;

    int accH[4][2][4], accM[4][2][4];
#pragma unroll
    for (int i = 0; i < 4; i++)
#pragma unroll
        for (int j = 0; j < 2; j++)
#pragma unroll
            for (int q = 0; q < 4; q++) { accH[i][j][q] = 0; accM[i][j][q] = 0; }

    const int nch = K >> 6;
    auto issue = [&](int ch, int stg) {
        const int k0 = ch << 6;
        const uint32_t base = sb + stg * ISTAGE;
#pragma unroll
        for (int i = tid; i < 1536; i += 256) {
            const int8_t* src;
            int row;
            uint32_t doff;
            if (i < 512) {                       // A digits: 64 rows x 4 vec x 2
                int t = i >> 8, j = i & 255, r = j >> 2, c = j & 3;
                src = t ? A0 : A1;
                row = m0 + r;
                doff = t * IA0 + r * QRS + c * 16;
                cpasync16(base + doff, src + (size_t)row * K + k0 + c * 16);
            } else {                             // B digits: 128 rows x 4 vec x 2
                int j = i - 512, t = j >> 9, jj = j & 511, r = jj >> 2, c = jj & 3;
                src = t ? B0 : B1;
                row = n0 + r;
                doff = IB1 + t * 10240 + r * QRS + c * 16;
                cpasync16(base + doff, src + (size_t)row * K + k0 + c * 16);
            }
        }
        cpcommit();
    };
    issue(0, 0);

    for (int ch = 0; ch < nch; ch++) {
        cpwait0();
        __syncthreads();
        if (ch + 1 < nch) issue(ch + 1, (ch + 1) & 1);
        const uint32_t stg = sb + (ch & 1) * ISTAGE;
#pragma unroll
        for (int ks = 0; ks < 2; ks++) {
            uint32_t a1[4][4], a0[4][4], b1[2][2], b0[2][2];
#pragma unroll
            for (int mt = 0; mt < 4; mt++) {
                uint32_t ad = stg + (mt*16 + (lane & 15)) * QRS + ks * 32 + (lane >> 4) * 16;
                ldsm4(a1[mt][0], a1[mt][1], a1[mt][2], a1[mt][3], ad);
                ldsm4(a0[mt][0], a0[mt][1], a0[mt][2], a0[mt][3], ad + IA0);
            }
#pragma unroll
            for (int ng = 0; ng < 2; ng++) {
                uint32_t bd = stg + IB1 + (wn*16 + ng*8 + (lane & 7)) * QRS
                              + ks * 32 + ((lane >> 3) & 1) * 16;
                ldsm2(b1[ng][0], b1[ng][1], bd);
                ldsm2(b0[ng][0], b0[ng][1], bd + 10240);
            }
#pragma unroll
            for (int mt = 0; mt < 4; mt++)
#pragma unroll
                for (int ng = 0; ng < 2; ng++) {
                    imma(accH[mt][ng], a1[mt], b1[ng]);
                    imma(accM[mt][ng], a1[mt], b0[ng]);
                    imma(accM[mt][ng], a0[mt], b1[ng]);
                }
        }
    }

    const int g = lane >> 2, qc = (lane & 3) * 2;
#pragma unroll
    for (int mt = 0; mt < 4; mt++) {
        const int row0 = m0 + mt*16 + g;
        const int row1 = row0 + 8;
        const float sa0 = saA[row0], sa1 = saA[row1];
#pragma unroll
        for (int ng = 0; ng < 2; ng++) {
            const int col = n0 + wn*16 + ng*8 + qc;
            const float sb0 = sbB[col], sb1 = sbB[col + 1];
            float v00 = (16384.f*accH[mt][ng][0] + 128.f*accM[mt][ng][0])*(sa0*sb0) + bias[col];
            float v01 = (16384.f*accH[mt][ng][1] + 128.f*accM[mt][ng][1])*(sa0*sb1) + bias[col+1];
            float v10 = (16384.f*accH[mt][ng][2] + 128.f*accM[mt][ng][2])*(sa1*sb0) + bias[col];
            float v11 = (16384.f*accH[mt][ng][3] + 128.f*accM[mt][ng][3])*(sa1*sb1) + bias[col+1];
            if (R) {
                float2 r0 = *(const float2*)&R[(size_t)row0 * N + col];
                float2 r1 = *(const float2*)&R[(size_t)row1 * N + col];
                v00 += r0.x; v01 += r0.y; v10 += r1.x; v11 += r1.y;
            }
            if (relu) {
                v00 = fmaxf(v00, 0.f); v01 = fmaxf(v01, 0.f);
                v10 = fmaxf(v10, 0.f); v11 = fmaxf(v11, 0.f);
            }
            if (Chi) {
                float h00 = __half2float(__float2half(v00));
                float h01 = __half2float(__float2half(v01));
                float h10 = __half2float(__float2half(v10));
                float h11 = __half2float(__float2half(v11));
                *(uint32_t*)&Chi[(size_t)row0 * N + col] = packh(v00, v01);
                *(uint32_t*)&Chi[(size_t)row1 * N + col] = packh(v10, v11);
                *(uint32_t*)&Clo[(size_t)row0 * N + col] = packh(v00-h00, v01-h01);
                *(uint32_t*)&Clo[(size_t)row1 * N + col] = packh(v10-h10, v11-h11);
            } else {
                *(float2*)&C[(size_t)row0 * N + col] = make_float2(v00, v01);
                *(float2*)&C[(size_t)row1 * N + col] = make_float2(v10, v11);
            }
        }
    }
}

// ---------------- HMMA flash attention (split-f16, all f32-acc) ----------------
#define ARS 144
#define AQ_LO 18432
#define AKV0  36864
#define AKV_STAGE 36864
#define ATT_SMEM (AKV0 + 2*AKV_STAGE)

__global__ __launch_bounds__(256, 2) void attn_tc(
        const __half* __restrict__ QKVh, const __half* __restrict__ QKVl,
        float* __restrict__ Og, const int* __restrict__ mask_ptr)
{
    extern __shared__ char smem[];
    const uint32_t sb = smem_to_u32(smem);
    const int tid = threadIdx.x, lane = tid & 31, w = tid >> 5;
    const int q0 = blockIdx.x * 128, h = blockIdx.y, b = blockIdx.z;
    const int lim = mask_ptr ? *mask_ptr : SEQ;
    const size_t tokbase = (size_t)b * SEQ;
    const int cq = h * DK, ck = 1024 + h * DK, cv = 2048 + h * DK;

    for (int i = tid; i < 1024; i += 256) {
        int r = i >> 3, c = i & 7;
        uint32_t qd = sb + r * ARS + c * 16;
        size_t gi = (tokbase + q0 + r) * QKVW + cq + c * 8;
        cpasync16(qd, QKVh + gi);
        cpasync16(qd + AQ_LO, QKVl + gi);
    }
    auto ldkv = [&](int t, int stg) {
        uint32_t base = sb + AKV0 + stg * AKV_STAGE;
        for (int i = tid; i < 512; i += 256) {
            int r = i >> 3, c = i & 7;
            uint32_t off = r * ARS + c * 16;
            size_t row = (tokbase + t * 64 + r) * QKVW;
            cpasync16(base + off,         QKVh + row + ck + c * 8);
            cpasync16(base + 9216 + off,  QKVl + row + ck + c * 8);
            cpasync16(base + 18432 + off, QKVh + row + cv + c * 8);
            cpasync16(base + 27648 + off, QKVl + row + cv + c * 8);
        }
        cpcommit();
    };
    ldkv(0, 0);

    const int nt = (lim + 63) >> 6;
    const int g = lane >> 2, qc = (lane & 3) * 2;
    const int wq = w * 16;

    float m[2] = {-1e30f, -1e30f}, l[2] = {0.f, 0.f};
    float o[8][4];
#pragma unroll
    for (int i = 0; i < 8; i++)
#pragma unroll
        for (int j = 0; j < 4; j++) o[i][j] = 0.f;

    for (int t = 0; t < nt; t++) {
        __syncthreads();
        if (t + 1 < nt) { ldkv(t + 1, (t + 1) & 1); cpwait1(); }
        else           { cpwait0(); }
        __syncthreads();
        const uint32_t kb = sb + AKV0 + (t & 1) * AKV_STAGE;

        float sc[8][4];
#pragma unroll
        for (int i = 0; i < 8; i++)
#pragma unroll
            for (int j = 0; j < 4; j++) sc[i][j] = 0.f;

#pragma unroll
        for (int ks = 0; ks < 4; ks++) {
            uint32_t qa = sb + (wq + (lane & 15)) * ARS + (lane >> 4) * 16 + ks * 32;
            uint32_t qh[4], ql[4];
            ldsm4(qh[0], qh[1], qh[2], qh[3], qa);
            ldsm4(ql[0], ql[1], ql[2], ql[3], qa + AQ_LO);
#pragma unroll
            for (int p = 0; p < 4; p++) {
                uint32_t ka = kb + (p*16 + (lane & 7) + ((lane >> 4) & 1) * 8) * ARS
                              + ((lane >> 3) & 1) * 16 + ks * 32;
                uint32_t kh[4], kl[4];
                ldsm4(kh[0], kh[1], kh[2], kh[3], ka);
                ldsm4(kl[0], kl[1], kl[2], kl[3], ka + 9216);
                const uint32_t kh01[2] = {kh[0], kh[1]}, kh23[2] = {kh[2], kh[3]};
                const uint32_t kl01[2] = {kl[0], kl[1]}, kl23[2] = {kl[2], kl[3]};
                mmaF(sc[2*p],   qh, kh01);
                mmaF(sc[2*p],   qh, kl01);
                mmaF(sc[2*p],   ql, kh01);
                mmaF(sc[2*p+1], qh, kh23);
                mmaF(sc[2*p+1], qh, kl23);
                mmaF(sc[2*p+1], ql, kh23);
            }
        }

        const int t0 = t * 64;
#pragma unroll
        for (int na = 0; na < 8; na++) {
            int c0 = t0 + na*8 + qc, c1 = c0 + 1;
#pragma unroll
            for (int j = 0; j < 2; j++) {
                float s0 = sc[na][2*j]   * 0.125f;
                float s1 = sc[na][2*j+1] * 0.125f;
                sc[na][2*j]   = (c0 < lim) ? s0 : -1e30f;
                sc[na][2*j+1] = (c1 < lim) ? s1 : -1e30f;
            }
        }

#pragma unroll
        for (int j = 0; j < 2; j++) {
            float mx = -1e30f;
#pragma unroll
            for (int na = 0; na < 8; na++)
                mx = fmaxf(mx, fmaxf(sc[na][2*j], sc[na][2*j+1]));
            mx = fmaxf(mx, __shfl_xor_sync(0xffffffffu, mx, 1));
            mx = fmaxf(mx, __shfl_xor_sync(0xffffffffu, mx, 2));
            float mnew = fmaxf(m[j], mx);
            float corr = __expf(m[j] - mnew);
            l[j] *= corr;
            m[j] = mnew;
#pragma unroll
            for (int nd = 0; nd < 8; nd++) { o[nd][2*j] *= corr; o[nd][2*j+1] *= corr; }
            float sum = 0.f;
#pragma unroll
            for (int na = 0; na < 8; na++) {
                float p0 = __expf(sc[na][2*j]   - mnew);
                float p1 = __expf(sc[na][2*j+1] - mnew);
                sc[na][2*j] = p0; sc[na][2*j+1] = p1;
                sum += p0 + p1;
            }
            sum += __shfl_xor_sync(0xffffffffu, sum, 1);
            sum += __shfl_xor_sync(0xffffffffu, sum, 2);
            l[j] += sum;
        }

#pragma unroll
        for (int kp = 0; kp < 4; kp++) {
            float p00 = sc[2*kp][0],   p01 = sc[2*kp][1];
            float p02 = sc[2*kp][2],   p03 = sc[2*kp][3];
            float p10 = sc[2*kp+1][0], p11 = sc[2*kp+1][1];
            float p12 = sc[2*kp+1][2], p13 = sc[2*kp+1][3];
            float h00 = __half2float(__float2half(p00));
            float h01 = __half2float(__float2half(p01));
            float h02 = __half2float(__float2half(p02));
            float h03 = __half2float(__float2half(p03));
            float h10 = __half2float(__float2half(p10));
            float h11 = __half2float(__float2half(p11));
            float h12 = __half2float(__float2half(p12));
            float h13 = __half2float(__float2half(p13));
            uint32_t aph[4] = { packh(p00, p01), packh(p02, p03),
                                packh(p10, p11), packh(p12, p13) };
            uint32_t apl[4] = { packh(p00-h00, p01-h01), packh(p02-h02, p03-h03),
                                packh(p10-h10, p11-h11), packh(p12-h12, p13-h13) };
#pragma unroll
            for (int vp = 0; vp < 4; vp++) {
                uint32_t va = kb + 18432 + (kp*16 + (lane & 15)) * ARS
                              + (vp*2 + (lane >> 4)) * 16;
                uint32_t vh[4], vl[4];
                ldsm4t(vh[0], vh[1], vh[2], vh[3], va);
                ldsm4t(vl[0], vl[1], vl[2], vl[3], va + 9216);
                const uint32_t vh01[2] = {vh[0], vh[1]}, vh23[2] = {vh[2], vh[3]};
                const uint32_t vl01[2] = {vl[0], vl[1]}, vl23[2] = {vl[2], vl[3]};
                mmaF(o[2*vp],   aph, vh01);
                mmaF(o[2*vp],   aph, vl01);
                mmaF(o[2*vp],   apl, vh01);
                mmaF(o[2*vp+1], aph, vh23);
                mmaF(o[2*vp+1], aph, vl23);
                mmaF(o[2*vp+1], apl, vh23);
            }
        }
    }

#pragma unroll
    for (int j = 0; j < 2; j++) {
        float inv = 1.f / l[j];
        int row = q0 + wq + g + j*8;
        size_t gb = (tokbase + row) * DIM + h * DK;
#pragma unroll
        for (int nd = 0; nd < 8; nd++)
            *(float2*)&Og[gb + nd*8 + qc] = make_float2(o[nd][2*j]*inv, o[nd][2*j+1]*inv);
    }
}

// ---------------- BatchNorm1d + fused int8 quantization ------------------------
__global__ __launch_bounds__(256)
void bn_q(float* __restrict__ X, const float* __restrict__ g, const float* __restrict__ be,
          int8_t* __restrict__ q1, int8_t* __restrict__ q0, float* __restrict__ sa)
{
    const int s = blockIdx.x, tid = threadIdx.x;
    const int lane = tid & 31, w = tid >> 5;
    const size_t r0 = (size_t)s * DIM, r1 = (size_t)(SEQ + s) * DIM;
    float4 v0 = ((const float4*)(X + r0))[tid];
    float4 v1 = ((const float4*)(X + r1))[tid];
    float sum = v0.x+v0.y+v0.z+v0.w + v1.x+v1.y+v1.z+v1.w;
    float sq  = v0.x*v0.x+v0.y*v0.y+v0.z*v0.z+v0.w*v0.w
              + v1.x*v1.x+v1.y*v1.y+v1.z*v1.z+v1.w*v1.w;
#pragma unroll
    for (int off = 16; off; off >>= 1) {
        sum += __shfl_xor_sync(0xffffffffu, sum, off);
        sq  += __shfl_xor_sync(0xffffffffu, sq,  off);
    }
    __shared__ float s1[8], s2[8];
    if (lane == 0) { s1[w] = sum; s2[w] = sq; }
    __syncthreads();
    sum = 0.f; sq = 0.f;
#pragma unroll
    for (int k = 0; k < 8; k++) { sum += s1[k]; sq += s2[k]; }
    const float mean = sum * (1.f/2048.f);
    const float var  = sq  * (1.f/2048.f) - mean*mean;
    const float scl  = g[s] * rsqrtf(var + 1e-5f);
    const float sh   = be[s] - mean * scl;
    v0.x = v0.x*scl + sh; v0.y = v0.y*scl + sh; v0.z = v0.z*scl + sh; v0.w = v0.w*scl + sh;
    v1.x = v1.x*scl + sh; v1.y = v1.y*scl + sh; v1.z = v1.z*scl + sh; v1.w = v1.w*scl + sh;
    float m0 = fmaxf(fmaxf(fabsf(v0.x), fabsf(v0.y)), fmaxf(fabsf(v0.z), fabsf(v0.w)));
    float m1 = fmaxf(fmaxf(fabsf(v1.x), fabsf(v1.y)), fmaxf(fabsf(v1.z), fabsf(v1.w)));
#pragma unroll
    for (int off = 16; off; off >>= 1) {
        m0 = fmaxf(m0, __shfl_xor_sync(0xffffffffu, m0, off));
        m1 = fmaxf(m1, __shfl_xor_sync(0xffffffffu, m1, off));
    }
    __syncthreads();
    if (lane == 0) { s1[w] = m0; s2[w] = m1; }
    __syncthreads();
    m0 = 1e-30f; m1 = 1e-30f;
#pragma unroll
    for (int k = 0; k < 8; k++) { m0 = fmaxf(m0, s1[k]); m1 = fmaxf(m1, s2[k]); }
    if (tid == 0) { sa[s] = m0 / QMAX; sa[SEQ + s] = m1 / QMAX; }
    const float i0 = QMAX / m0, i1 = QMAX / m1;
    ((float4*)(X + r0))[tid] = v0;
    ((float4*)(X + r1))[tid] = v1;
    int qa, qb, qc2, qd, h0,l0,h1,l1,h2,l2,h3,l3;
    qa = __float2int_rn(v0.x*i0); qb = __float2int_rn(v0.y*i0);
    qc2 = __float2int_rn(v0.z*i0); qd = __float2int_rn(v0.w*i0);
    dig2(qa,h0,l0); dig2(qb,h1,l1); dig2(qc2,h2,l2); dig2(qd,h3,l3);
    ((uint32_t*)(q1 + r0))[tid] = pack4b(h0,h1,h2,h3);
    ((uint32_t*)(q0 + r0))[tid] = pack4b(l0,l1,l2,l3);
    qa = __float2int_rn(v1.x*i1); qb = __float2int_rn(v1.y*i1);
    qc2 = __float2int_rn(v1.z*i1); qd = __float2int_rn(v1.w*i1);
    dig2(qa,h0,l0); dig2(qb,h1,l1); dig2(qc2,h2,l2); dig2(qd,h3,l3);
    ((uint32_t*)(q1 + r1))[tid] = pack4b(h0,h1,h2,h3);
    ((uint32_t*)(q0 + r1))[tid] = pack4b(l0,l1,l2,l3);
}

// ---------------- host orchestration -------------------------------------------
extern "C" void kernel_launch(void* const* d_in, const int* in_sizes, int n_in,
                              void* d_out, int out_size)
{
    const float* x   = (const float*)d_in[0];
    const float* Wq1 = (const float*)d_in[1];  const float* bq1 = (const float*)d_in[2];
    const float* Wk1 = (const float*)d_in[3];  const float* bk1 = (const float*)d_in[4];
    const float* Wv1 = (const float*)d_in[5];  const float* bv1 = (const float*)d_in[6];
    const float* Wo1 = (const float*)d_in[7];  const float* bo1 = (const float*)d_in[8];
    const float* Wq2 = (const float*)d_in[9];  const float* bq2 = (const float*)d_in[10];
    const float* Wk2 = (const float*)d_in[11]; const float* bk2 = (const float*)d_in[12];
    const float* Wv2 = (const float*)d_in[13]; const float* bv2 = (const float*)d_in[14];
    const float* Wo2 = (const float*)d_in[15]; const float* bo2 = (const float*)d_in[16];
    const float* g1  = (const float*)d_in[17]; const float* be1 = (const float*)d_in[18];
    const float* g2  = (const float*)d_in[19]; const float* be2 = (const float*)d_in[20];
    const float* g3  = (const float*)d_in[21]; const float* be3 = (const float*)d_in[22];
    const float* W1  = (const float*)d_in[23]; const float* bf1 = (const float*)d_in[24];
    const float* W2  = (const float*)d_in[25]; const float* bf2 = (const float*)d_in[26];
    const int*   msk = (const int*)d_in[27];

    float *X, *X1, *Y, *O, *Hid, *bQ1, *bQ2, *sbW, *sbInv, *saA, *saX, *saX1;
    __half *QKVhi, *QKVlo;
    int8_t *W1d, *W0d, *Aq1, *Aq0, *Xq1, *Xq0, *X1q1, *X1q0;
    uint32_t* sbBits;
    cudaGetSymbolAddress((void**)&X, g_X);       cudaGetSymbolAddress((void**)&X1, g_X1);
    cudaGetSymbolAddress((void**)&Y, g_Yb);      cudaGetSymbolAddress((void**)&O, g_O);
    cudaGetSymbolAddress((void**)&Hid, g_Hid);
    cudaGetSymbolAddress((void**)&QKVhi, g_QKVhi); cudaGetSymbolAddress((void**)&QKVlo, g_QKVlo);
    cudaGetSymbolAddress((void**)&W1d, g_W1d);   cudaGetSymbolAddress((void**)&W0d, g_W0d);
    cudaGetSymbolAddress((void**)&sbBits, g_sbBits);
    cudaGetSymbolAddress((void**)&sbW, g_sbW);   cudaGetSymbolAddress((void**)&sbInv, g_sbInv);
    cudaGetSymbolAddress((void**)&Aq1, g_Aq1);   cudaGetSymbolAddress((void**)&Aq0, g_Aq0);
    cudaGetSymbolAddress((void**)&Xq1, g_Xq1);   cudaGetSymbolAddress((void**)&Xq0, g_Xq0);
    cudaGetSymbolAddress((void**)&X1q1, g_X1q1); cudaGetSymbolAddress((void**)&X1q0, g_X1q0);
    cudaGetSymbolAddress((void**)&saA, g_saA);   cudaGetSymbolAddress((void**)&saX, g_saX);
    cudaGetSymbolAddress((void**)&saX1, g_saX1);
    cudaGetSymbolAddress((void**)&bQ1, g_bQKV1); cudaGetSymbolAddress((void**)&bQ2, g_bQKV2);

    cudaFuncSetAttribute(gemm_i8, cudaFuncAttributeMaxDynamicSharedMemorySize, GEMM_I8_SMEM);
    cudaFuncSetAttribute(attn_tc, cudaFuncAttributeMaxDynamicSharedMemorySize, ATT_SMEM);

    const size_t bytesD = (size_t)MROWS * DIM * sizeof(float);
    cudaMemcpyAsync(X, x, bytesD, cudaMemcpyDeviceToDevice);
    cudaMemsetAsync(sbBits, 0, NL * LAYER_S * sizeof(uint32_t));

    // ---- weight prep: max -> scale -> quantize ----
    {
        dim3 b(256);
        dim3 gQ(32, 32, NL);
        size_t sQ = (size_t)NH * DIM * DK, sO = (size_t)DIM * DIM;
        wmax_t<<<gQ, b>>>(Wq1, sbBits, 1024, 1024, sQ, S_Q1 + 0,    1);
        wmax_t<<<gQ, b>>>(Wk1, sbBits, 1024, 1024, sQ, S_Q1 + 1024, 1);
        wmax_t<<<gQ, b>>>(Wv1, sbBits, 1024, 1024, sQ, S_Q1 + 2048, 1);
        wmax_t<<<gQ, b>>>(Wo1, sbBits, 1024, 1024, sO, S_O1, 0);
        wmax_t<<<gQ, b>>>(Wq2, sbBits, 1024, 1024, sQ, S_Q2 + 0,    1);
        wmax_t<<<gQ, b>>>(Wk2, sbBits, 1024, 1024, sQ, S_Q2 + 1024, 1);
        wmax_t<<<gQ, b>>>(Wv2, sbBits, 1024, 1024, sQ, S_Q2 + 2048, 1);
        wmax_t<<<gQ, b>>>(Wo2, sbBits, 1024, 1024, sO, S_O2, 0);
        wmax_t<<<dim3(32, 128, NL), b>>>(W1, sbBits, 1024, 4096, (size_t)DIM*FF, S_W1, 0);
        wmax_t<<<dim3(128, 32, NL), b>>>(W2, sbBits, 4096, 1024, (size_t)FF*DIM, S_W2, 0);
        wscale<<<(NL*LAYER_S + 255)/256, b>>>(sbBits, sbW, sbInv, NL*LAYER_S);
        wquant_t<<<gQ, b>>>(Wq1, W1d, W0d, sbInv, 1024, 1024, sQ, OFF_Q1 + 0u,       S_Q1 + 0,    1);
        wquant_t<<<gQ, b>>>(Wk1, W1d, W0d, sbInv, 1024, 1024, sQ, OFF_Q1 + (1u<<20), S_Q1 + 1024, 1);
        wquant_t<<<gQ, b>>>(Wv1, W1d, W0d, sbInv, 1024, 1024, sQ, OFF_Q1 + (2u<<20), S_Q1 + 2048, 1);
        wquant_t<<<gQ, b>>>(Wo1, W1d, W0d, sbInv, 1024, 1024, sO, OFF_O1, S_O1, 0);
        wquant_t<<<gQ, b>>>(Wq2, W1d, W0d, sbInv, 1024, 1024, sQ, OFF_Q2 + 0u,       S_Q2 + 0,    1);
        wquant_t<<<gQ, b>>>(Wk2, W1d, W0d, sbInv, 1024, 1024, sQ, OFF_Q2 + (1u<<20), S_Q2 + 1024, 1);
        wquant_t<<<gQ, b>>>(Wv2, W1d, W0d, sbInv, 1024, 1024, sQ, OFF_Q2 + (2u<<20), S_Q2 + 2048, 1);
        wquant_t<<<gQ, b>>>(Wo2, W1d, W0d, sbInv, 1024, 1024, sO, OFF_O2, S_O2, 0);
        wquant_t<<<dim3(32, 128, NL), b>>>(W1, W1d, W0d, sbInv, 1024, 4096, (size_t)DIM*FF, OFF_W1, S_W1, 0);
        wquant_t<<<dim3(128, 32, NL), b>>>(W2, W1d, W0d, sbInv, 4096, 1024, (size_t)FF*DIM, OFF_W2, S_W2, 0);
        pack_bias<<<dim3(4, NL), b>>>(bq1, bk1, bv1, bQ1);
        pack_bias<<<dim3(4, NL), b>>>(bq2, bk2, bv2, bQ2);
    }

    quant_row<<<MROWS, 256>>>(X, Xq1, Xq0, saX, DIM);

    dim3 gQKV(QKVW/128, MROWS/64);    // (24,32)
    dim3 gGD(DIM/128,  MROWS/64);     // (8,32)
    dim3 gGF(FF/128,   MROWS/64);     // (32,32)
    dim3 gA(SEQ/128, NH, NB);

    for (int l = 0; l < NL; l++) {
        const int8_t* W1L = W1d + (size_t)l * LAYER_W;
        const int8_t* W0L = W0d + (size_t)l * LAYER_W;
        const float*  sbL = sbW + (size_t)l * LAYER_S;
        const size_t dO = (size_t)l * DIM, f1O = (size_t)l * FF;

        // masked self-attention (fused QKV, masked K/V tiles skipped)
        gemm_i8<<<gQKV, 256, GEMM_I8_SMEM>>>(Xq1, Xq0, saX, W1L+OFF_Q1, W0L+OFF_Q1, sbL+S_Q1,
                bQ1 + l*QKVW, nullptr, nullptr, QKVhi, QKVlo, QKVW, DIM, 0, msk);
        attn_tc<<<gA, 256, ATT_SMEM>>>(QKVhi, QKVlo, O, msk);
        quant_row<<<MROWS, 256>>>(O, Aq1, Aq0, saA, DIM);
        gemm_i8<<<gGD, 256, GEMM_I8_SMEM>>>(Aq1, Aq0, saA, W1L+OFF_O1, W0L+OFF_O1, sbL+S_O1,
                bo1+dO, X, X1, nullptr, nullptr, DIM, DIM, 0, nullptr);
        bn_q<<<SEQ, 256>>>(X1, g1+dO, be1+dO, X1q1, X1q0, saX1);

        // second (unmasked) attention; residual from block input X
        gemm_i8<<<gQKV, 256, GEMM_I8_SMEM>>>(X1q1, X1q0, saX1, W1L+OFF_Q2, W0L+OFF_Q2, sbL+S_Q2,
                bQ2 + l*QKVW, nullptr, nullptr, QKVhi, QKVlo, QKVW, DIM, 0, nullptr);
        attn_tc<<<gA, 256, ATT_SMEM>>>(QKVhi, QKVlo, O, nullptr);
        quant_row<<<MROWS, 256>>>(O, Aq1, Aq0, saA, DIM);
        gemm_i8<<<gGD, 256, GEMM_I8_SMEM>>>(Aq1, Aq0, saA, W1L+OFF_O2, W0L+OFF_O2, sbL+S_O2,
                bo2+dO, X, Y, nullptr, nullptr, DIM, DIM, 0, nullptr);
        bn_q<<<SEQ, 256>>>(Y, g2+dO, be2+dO, Aq1, Aq0, saA);

        // FFN; residual from X1
        gemm_i8<<<gGF, 256, GEMM_I8_SMEM>>>(Aq1, Aq0, saA, W1L+OFF_W1, W0L+OFF_W1, sbL+S_W1,
                bf1+f1O, nullptr, Hid, nullptr, nullptr, FF, DIM, 1, nullptr);
        quant_row<<<MROWS, 256>>>(Hid, Aq1, Aq0, saA, FF);
        gemm_i8<<<gGD, 256, GEMM_I8_SMEM>>>(Aq1, Aq0, saA, W1L+OFF_W2, W0L+OFF_W2, sbL+S_W2,
                bf2+dO, X1, X, nullptr, nullptr, DIM, FF, 0, nullptr);
        bn_q<<<SEQ, 256>>>(X, g3+dO, be3+dO, Xq1, Xq0, saX);
    }

    cudaMemcpyAsync(d_out, X, bytesD, cudaMemcpyDeviceToDevice);
}

// round 9
// speedup vs baseline: 2.2945x; 2.2945x over previous
#include <cuda_runtime.h>
#include <cuda_fp16.h>
#include <cstdint>

#define NB  2
#define SEQ 1024
#define DIM 1024
#define NH  16
#define DK  64
#define FF  4096
#define NL  4
#define MROWS (NB*SEQ)
#define QKVW 3072

// ---------------- PTX helpers ------------------------------------------------
__device__ __forceinline__ uint32_t smem_to_u32(const void* p) {
    uint32_t a;
    asm("{ .reg .u64 t; cvta.to.shared.u64 t, %1; cvt.u32.u64 %0, t; }" : "=r"(a) : "l"(p));
    return a;
}
__device__ __forceinline__ void cpasync16(uint32_t dst, const void* src) {
    asm volatile("cp.async.cg.shared.global [%0], [%1], 16;"
                 :: "r"(dst), "l"(__cvta_generic_to_global(src)) : "memory");
}
__device__ __forceinline__ void cpcommit() { asm volatile("cp.async.commit_group;" ::: "memory"); }
__device__ __forceinline__ void cpwait0()  { asm volatile("cp.async.wait_group 0;" ::: "memory"); }
__device__ __forceinline__ void cpwait1()  { asm volatile("cp.async.wait_group 1;" ::: "memory"); }
__device__ __forceinline__ void ldsm4(uint32_t& r0, uint32_t& r1, uint32_t& r2, uint32_t& r3, uint32_t a) {
    asm volatile("ldmatrix.sync.aligned.m8n8.x4.shared.b16 {%0,%1,%2,%3}, [%4];"
                 : "=r"(r0), "=r"(r1), "=r"(r2), "=r"(r3) : "r"(a));
}
__device__ __forceinline__ void ldsm2(uint32_t& r0, uint32_t& r1, uint32_t a) {
    asm volatile("ldmatrix.sync.aligned.m8n8.x2.shared.b16 {%0,%1}, [%2];"
                 : "=r"(r0), "=r"(r1) : "r"(a));
}
__device__ __forceinline__ void ldsm4t(uint32_t& r0, uint32_t& r1, uint32_t& r2, uint32_t& r3, uint32_t a) {
    asm volatile("ldmatrix.sync.aligned.m8n8.x4.trans.shared.b16 {%0,%1,%2,%3}, [%4];"
                 : "=r"(r0), "=r"(r1), "=r"(r2), "=r"(r3) : "r"(a));
}
__device__ __forceinline__ void mmaF(float* d, const uint32_t* a, const uint32_t* b) {
    asm volatile("mma.sync.aligned.m16n8k16.row.col.f32.f16.f16.f32 "
                 "{%0,%1,%2,%3}, {%4,%5,%6,%7}, {%8,%9}, {%0,%1,%2,%3};"
                 : "+f"(d[0]), "+f"(d[1]), "+f"(d[2]), "+f"(d[3])
                 : "r"(a[0]), "r"(a[1]), "r"(a[2]), "r"(a[3]), "r"(b[0]), "r"(b[1]));
}
__device__ __forceinline__ uint32_t packh(float a, float b) {
    __half2 h = __floats2half2_rn(a, b);
    return *(uint32_t*)&h;
}

// ---------------- scratch -----------------------------------------------------
__device__ float g_X  [MROWS*DIM];
__device__ float g_X1 [MROWS*DIM];
__device__ float g_Yb [MROWS*DIM];
__device__ __half g_Xhi [MROWS*DIM],  g_Xlo [MROWS*DIM];
__device__ __half g_X1hi[MROWS*DIM],  g_X1lo[MROWS*DIM];
__device__ __half g_Yhi [MROWS*DIM],  g_Ylo [MROWS*DIM];
__device__ __half g_QKVhi[MROWS*QKVW], g_QKVlo[MROWS*QKVW];
__device__ __half g_Ohi [MROWS*DIM],  g_Olo [MROWS*DIM];
__device__ __half g_Hhi [MROWS*FF],   g_Hlo [MROWS*FF];
__device__ __half g_Whi[64u*1024*1024];
__device__ __half g_Wlo[64u*1024*1024];
__device__ float  g_bQKV1[NL*QKVW], g_bQKV2[NL*QKVW];

#define LAYER_W  (16u*1024*1024)
#define OFF_Q1   (0u)
#define OFF_O1   (3u*1024*1024)
#define OFF_Q2   (4u*1024*1024)
#define OFF_O2   (7u*1024*1024)
#define OFF_W1   (8u*1024*1024)
#define OFF_W2   (12u*1024*1024)

// ---------------- activation split: fp32 -> (hi, lo) f16 ----------------------
__global__ __launch_bounds__(256) void split_f32(const float* __restrict__ x,
        __half* __restrict__ h, __half* __restrict__ l, int n4)
{
    int i = blockIdx.x * 256 + threadIdx.x;
    if (i >= n4) return;
    float4 v = ((const float4*)x)[i];
    __half h0 = __float2half(v.x), h1 = __float2half(v.y);
    __half h2 = __float2half(v.z), h3 = __float2half(v.w);
    uint2 hp, lp;
    hp.x = packh(v.x, v.y); hp.y = packh(v.z, v.w);
    lp.x = packh(v.x - __half2float(h0), v.y - __half2float(h1));
    lp.y = packh(v.z - __half2float(h2), v.w - __half2float(h3));
    ((uint2*)h)[i] = hp;
    ((uint2*)l)[i] = lp;
}

// ------------- weight transpose+split ------------------------------------------
__global__ __launch_bounds__(256) void wsplit_t(const float* __restrict__ W,
        __half* __restrict__ oh, __half* __restrict__ ol,
        int K, int N, size_t inLayerStride, size_t outOff, int headMode)
{
    __shared__ float t[32][33];
    int tx = threadIdx.x & 31, ty = threadIdx.x >> 5;
    int k0 = blockIdx.x * 32, n0 = blockIdx.y * 32;
    const float* Win = W + (size_t)blockIdx.z * inLayerStride;
    size_t ob = (size_t)blockIdx.z * LAYER_W + outOff;
#pragma unroll
    for (int i = 0; i < 4; i++) {
        int k = k0 + ty + 8*i, n = n0 + tx;
        size_t idx = headMode ? ((size_t)(n >> 6) * K * 64 + (size_t)k * 64 + (n & 63))
                              : ((size_t)k * N + n);
        t[ty + 8*i][tx] = Win[idx];
    }
    __syncthreads();
#pragma unroll
    for (int i = 0; i < 4; i++) {
        int n = n0 + ty + 8*i, k = k0 + tx;
        float v = t[tx][ty + 8*i];
        __half hi = __float2half(v);
        oh[ob + (size_t)n * K + k] = hi;
        ol[ob + (size_t)n * K + k] = __float2half(v - __half2float(hi));
    }
}

__global__ __launch_bounds__(256) void pack_bias(const float* __restrict__ bq,
        const float* __restrict__ bk, const float* __restrict__ bv, float* __restrict__ out)
{
    int l = blockIdx.y;
    int i = blockIdx.x * 256 + threadIdx.x;
    out[l*QKVW + i]        = bq[l*1024 + i];
    out[l*QKVW + 1024 + i] = bk[l*1024 + i];
    out[l*QKVW + 2048 + i] = bv[l*1024 + i];
}

// ---------------- split-f16 HMMA GEMM: CTA 64x128, 2 CTAs/SM -------------------
#define RSB 144
#define SA_LO 9216
#define SB_HI 18432
#define SB_LO 36864
#define STAGE 55296
#define GEMM_SMEM (2*STAGE)   // 110592

__global__ __launch_bounds__(256, 2) void gemm_tc(
        const __half* __restrict__ Ah, const __half* __restrict__ Al,
        const __half* __restrict__ Bh, const __half* __restrict__ Bl,
        const float* __restrict__ bias, const float* __restrict__ R,
        float* __restrict__ C,
        __half* __restrict__ Chi, __half* __restrict__ Clo,
        int N, int K, int relu, const int* __restrict__ mskp)
{
    const int m0 = blockIdx.y * 64, n0 = blockIdx.x * 128;
    if (mskp && ((m0 & 1023) >= *mskp) && (n0 >= 1024)) return;  // masked K/V tokens
    extern __shared__ char smem[];
    const uint32_t sb = smem_to_u32(smem);
    const int tid = threadIdx.x, lane = tid & 31, wn = tid >> 5;

    float acc[4][2][4];
#pragma unroll
    for (int i = 0; i < 4; i++)
#pragma unroll
        for (int j = 0; j < 2; j++)
#pragma unroll
            for (int q = 0; q < 4; q++) acc[i][j][q] = 0.f;

    const int nch = K >> 6;
    auto issue = [&](int ch, int stg) {
        const int k0 = ch << 6;
        const uint32_t base = sb + stg * STAGE;
#pragma unroll
        for (int i = tid; i < 3072; i += 256) {
            if (i < 1024) {                       // A hi/lo: 64 rows x 8 vecs
                int t = i >> 9, j = i & 511, r = j >> 3, c = j & 7;
                const __half* src = (t ? Al : Ah) + (size_t)(m0 + r) * K + k0 + c * 8;
                cpasync16(base + t * SA_LO + r * RSB + c * 16, src);
            } else {                              // B hi/lo: 128 rows x 8 vecs
                int j = i - 1024, t = j >> 10, jj = j & 1023, r = jj >> 3, c = jj & 7;
                const __half* src = (t ? Bl : Bh) + (size_t)(n0 + r) * K + k0 + c * 8;
                cpasync16(base + SB_HI + t * (SB_LO - SB_HI) + r * RSB + c * 16, src);
            }
        }
        cpcommit();
    };
    issue(0, 0);

    for (int ch = 0; ch < nch; ch++) {
        cpwait0();
        __syncthreads();
        if (ch + 1 < nch) issue(ch + 1, (ch + 1) & 1);
        const uint32_t stg = sb + (ch & 1) * STAGE;
#pragma unroll
        for (int ks = 0; ks < 4; ks++) {
            uint32_t ah[4][4], al[4][4], bh[2][2], bl[2][2];
#pragma unroll
            for (int mt = 0; mt < 4; mt++) {
                uint32_t ad = stg + (mt*16 + (lane & 15)) * RSB + (lane >> 4) * 16 + ks * 32;
                ldsm4(ah[mt][0], ah[mt][1], ah[mt][2], ah[mt][3], ad);
                ldsm4(al[mt][0], al[mt][1], al[mt][2], al[mt][3], ad + SA_LO);
            }
#pragma unroll
            for (int ng = 0; ng < 2; ng++) {
                uint32_t bd = stg + SB_HI + (wn*16 + ng*8 + (lane & 7)) * RSB
                              + ((lane >> 3) & 1) * 16 + ks * 32;
                ldsm2(bh[ng][0], bh[ng][1], bd);
                ldsm2(bl[ng][0], bl[ng][1], bd + (SB_LO - SB_HI));
            }
#pragma unroll
            for (int mt = 0; mt < 4; mt++)
#pragma unroll
                for (int ng = 0; ng < 2; ng++) {
                    mmaF(acc[mt][ng], ah[mt], bh[ng]);
                    mmaF(acc[mt][ng], ah[mt], bl[ng]);
                    mmaF(acc[mt][ng], al[mt], bh[ng]);
                }
        }
    }

    const int g = lane >> 2, qc = (lane & 3) * 2;
#pragma unroll
    for (int mt = 0; mt < 4; mt++) {
        const int row0 = m0 + mt*16 + g;
        const int row1 = row0 + 8;
#pragma unroll
        for (int ng = 0; ng < 2; ng++) {
            const int col = n0 + wn*16 + ng*8 + qc;
            const float b0 = bias[col], b1 = bias[col + 1];
            float v00 = acc[mt][ng][0] + b0, v01 = acc[mt][ng][1] + b1;
            float v10 = acc[mt][ng][2] + b0, v11 = acc[mt][ng][3] + b1;
            if (R) {
                float2 r0 = *(const float2*)&R[(size_t)row0 * N + col];
                float2 r1 = *(const float2*)&R[(size_t)row1 * N + col];
                v00 += r0.x; v01 += r0.y; v10 += r1.x; v11 += r1.y;
            }
            if (relu) {
                v00 = fmaxf(v00, 0.f); v01 = fmaxf(v01, 0.f);
                v10 = fmaxf(v10, 0.f); v11 = fmaxf(v11, 0.f);
            }
            if (Chi) {
                float h00 = __half2float(__float2half(v00));
                float h01 = __half2float(__float2half(v01));
                float h10 = __half2float(__float2half(v10));
                float h11 = __half2float(__float2half(v11));
                *(uint32_t*)&Chi[(size_t)row0 * N + col] = packh(v00, v01);
                *(uint32_t*)&Chi[(size_t)row1 * N + col] = packh(v10, v11);
                *(uint32_t*)&Clo[(size_t)row0 * N + col] = packh(v00-h00, v01-h01);
                *(uint32_t*)&Clo[(size_t)row1 * N + col] = packh(v10-h10, v11-h11);
            } else {
                *(float2*)&C[(size_t)row0 * N + col] = make_float2(v00, v01);
                *(float2*)&C[(size_t)row1 * N + col] = make_float2(v10, v11);
            }
        }
    }
}

// ---------------- HMMA flash attention (split-f16, all f32-acc) ----------------
#define ARS 144
#define AQ_LO 18432
#define AKV0  36864
#define AKV_STAGE 36864
#define ATT_SMEM (AKV0 + 2*AKV_STAGE)

__global__ __launch_bounds__(256, 2) void attn_tc(
        const __half* __restrict__ QKVh, const __half* __restrict__ QKVl,
        __half* __restrict__ Ohi, __half* __restrict__ Olo,
        const int* __restrict__ mask_ptr)
{
    extern __shared__ char smem[];
    const uint32_t sb = smem_to_u32(smem);
    const int tid = threadIdx.x, lane = tid & 31, w = tid >> 5;
    const int q0 = blockIdx.x * 128, h = blockIdx.y, b = blockIdx.z;
    const int lim = mask_ptr ? *mask_ptr : SEQ;
    const size_t tokbase = (size_t)b * SEQ;
    const int cq = h * DK, ck = 1024 + h * DK, cv = 2048 + h * DK;

    for (int i = tid; i < 1024; i += 256) {
        int r = i >> 3, c = i & 7;
        uint32_t qd = sb + r * ARS + c * 16;
        size_t gi = (tokbase + q0 + r) * QKVW + cq + c * 8;
        cpasync16(qd, QKVh + gi);
        cpasync16(qd + AQ_LO, QKVl + gi);
    }
    auto ldkv = [&](int t, int stg) {
        uint32_t base = sb + AKV0 + stg * AKV_STAGE;
        for (int i = tid; i < 512; i += 256) {
            int r = i >> 3, c = i & 7;
            uint32_t off = r * ARS + c * 16;
            size_t row = (tokbase + t * 64 + r) * QKVW;
            cpasync16(base + off,         QKVh + row + ck + c * 8);
            cpasync16(base + 9216 + off,  QKVl + row + ck + c * 8);
            cpasync16(base + 18432 + off, QKVh + row + cv + c * 8);
            cpasync16(base + 27648 + off, QKVl + row + cv + c * 8);
        }
        cpcommit();
    };
    ldkv(0, 0);

    const int nt = (lim + 63) >> 6;
    const int g = lane >> 2, qc = (lane & 3) * 2;
    const int wq = w * 16;

    float m[2] = {-1e30f, -1e30f}, l[2] = {0.f, 0.f};
    float o[8][4];
#pragma unroll
    for (int i = 0; i < 8; i++)
#pragma unroll
        for (int j = 0; j < 4; j++) o[i][j] = 0.f;

    for (int t = 0; t < nt; t++) {
        __syncthreads();
        if (t + 1 < nt) { ldkv(t + 1, (t + 1) & 1); cpwait1(); }
        else           { cpwait0(); }
        __syncthreads();
        const uint32_t kb = sb + AKV0 + (t & 1) * AKV_STAGE;

        float sc[8][4];
#pragma unroll
        for (int i = 0; i < 8; i++)
#pragma unroll
            for (int j = 0; j < 4; j++) sc[i][j] = 0.f;

#pragma unroll
        for (int ks = 0; ks < 4; ks++) {
            uint32_t qa = sb + (wq + (lane & 15)) * ARS + (lane >> 4) * 16 + ks * 32;
            uint32_t qh[4], ql[4];
            ldsm4(qh[0], qh[1], qh[2], qh[3], qa);
            ldsm4(ql[0], ql[1], ql[2], ql[3], qa + AQ_LO);
#pragma unroll
            for (int p = 0; p < 4; p++) {
                uint32_t ka = kb + (p*16 + (lane & 7) + ((lane >> 4) & 1) * 8) * ARS
                              + ((lane >> 3) & 1) * 16 + ks * 32;
                uint32_t kh[4], kl[4];
                ldsm4(kh[0], kh[1], kh[2], kh[3], ka);
                ldsm4(kl[0], kl[1], kl[2], kl[3], ka + 9216);
                const uint32_t kh01[2] = {kh[0], kh[1]}, kh23[2] = {kh[2], kh[3]};
                const uint32_t kl01[2] = {kl[0], kl[1]}, kl23[2] = {kl[2], kl[3]};
                mmaF(sc[2*p],   qh, kh01);
                mmaF(sc[2*p],   qh, kl01);
                mmaF(sc[2*p],   ql, kh01);
                mmaF(sc[2*p+1], qh, kh23);
                mmaF(sc[2*p+1], qh, kl23);
                mmaF(sc[2*p+1], ql, kh23);
            }
        }

        const int t0 = t * 64;
#pragma unroll
        for (int na = 0; na < 8; na++) {
            int c0 = t0 + na*8 + qc, c1 = c0 + 1;
#pragma unroll
            for (int j = 0; j < 2; j++) {
                float s0 = sc[na][2*j]   * 0.125f;
                float s1 = sc[na][2*j+1] * 0.125f;
                sc[na][2*j]   = (c0 < lim) ? s0 : -1e30f;
                sc[na][2*j+1] = (c1 < lim) ? s1 : -1e30f;
            }
        }

#pragma unroll
        for (int j = 0; j < 2; j++) {
            float mx = -1e30f;
#pragma unroll
            for (int na = 0; na < 8; na++)
                mx = fmaxf(mx, fmaxf(sc[na][2*j], sc[na][2*j+1]));
            mx = fmaxf(mx, __shfl_xor_sync(0xffffffffu, mx, 1));
            mx = fmaxf(mx, __shfl_xor_sync(0xffffffffu, mx, 2));
            float mnew = fmaxf(m[j], mx);
            float corr = __expf(m[j] - mnew);
            l[j] *= corr;
            m[j] = mnew;
#pragma unroll
            for (int nd = 0; nd < 8; nd++) { o[nd][2*j] *= corr; o[nd][2*j+1] *= corr; }
            float sum = 0.f;
#pragma unroll
            for (int na = 0; na < 8; na++) {
                float p0 = __expf(sc[na][2*j]   - mnew);
                float p1 = __expf(sc[na][2*j+1] - mnew);
                sc[na][2*j] = p0; sc[na][2*j+1] = p1;
                sum += p0 + p1;
            }
            sum += __shfl_xor_sync(0xffffffffu, sum, 1);
            sum += __shfl_xor_sync(0xffffffffu, sum, 2);
            l[j] += sum;
        }

#pragma unroll
        for (int kp = 0; kp < 4; kp++) {
            float p00 = sc[2*kp][0],   p01 = sc[2*kp][1];
            float p02 = sc[2*kp][2],   p03 = sc[2*kp][3];
            float p10 = sc[2*kp+1][0], p11 = sc[2*kp+1][1];
            float p12 = sc[2*kp+1][2], p13 = sc[2*kp+1][3];
            float h00 = __half2float(__float2half(p00));
            float h01 = __half2float(__float2half(p01));
            float h02 = __half2float(__float2half(p02));
            float h03 = __half2float(__float2half(p03));
            float h10 = __half2float(__float2half(p10));
            float h11 = __half2float(__float2half(p11));
            float h12 = __half2float(__float2half(p12));
            float h13 = __half2float(__float2half(p13));
            uint32_t aph[4] = { packh(p00, p01), packh(p02, p03),
                                packh(p10, p11), packh(p12, p13) };
            uint32_t apl[4] = { packh(p00-h00, p01-h01), packh(p02-h02, p03-h03),
                                packh(p10-h10, p11-h11), packh(p12-h12, p13-h13) };
#pragma unroll
            for (int vp = 0; vp < 4; vp++) {
                uint32_t va = kb + 18432 + (kp*16 + (lane & 15)) * ARS
                              + (vp*2 + (lane >> 4)) * 16;
                uint32_t vh[4], vl[4];
                ldsm4t(vh[0], vh[1], vh[2], vh[3], va);
                ldsm4t(vl[0], vl[1], vl[2], vl[3], va + 9216);
                const uint32_t vh01[2] = {vh[0], vh[1]}, vh23[2] = {vh[2], vh[3]};
                const uint32_t vl01[2] = {vl[0], vl[1]}, vl23[2] = {vl[2], vl[3]};
                mmaF(o[2*vp],   aph, vh01);
                mmaF(o[2*vp],   aph, vl01);
                mmaF(o[2*vp],   apl, vh01);
                mmaF(o[2*vp+1], aph, vh23);
                mmaF(o[2*vp+1], aph, vl23);
                mmaF(o[2*vp+1], apl, vh23);
            }
        }
    }

#pragma unroll
    for (int j = 0; j < 2; j++) {
        float inv = 1.f / l[j];
        int row = q0 + wq + g + j*8;
        size_t gb = (tokbase + row) * DIM + h * DK;
#pragma unroll
        for (int nd = 0; nd < 8; nd++) {
            float v0 = o[nd][2*j] * inv, v1 = o[nd][2*j+1] * inv;
            float h0 = __half2float(__float2half(v0));
            float h1 = __half2float(__float2half(v1));
            *(uint32_t*)&Ohi[gb + nd*8 + qc] = packh(v0, v1);
            *(uint32_t*)&Olo[gb + nd*8 + qc] = packh(v0-h0, v1-h1);
        }
    }
}

// ---------------- BatchNorm1d + fused f16 split --------------------------------
__global__ __launch_bounds__(256)
void bn_q(float* __restrict__ X, const float* __restrict__ g, const float* __restrict__ be,
          __half* __restrict__ Xh, __half* __restrict__ Xl)
{
    const int s = blockIdx.x, tid = threadIdx.x;
    const int lane = tid & 31, w = tid >> 5;
    const size_t r0 = (size_t)s * DIM, r1 = (size_t)(SEQ + s) * DIM;
    float4 v0 = ((const float4*)(X + r0))[tid];
    float4 v1 = ((const float4*)(X + r1))[tid];
    float sum = v0.x+v0.y+v0.z+v0.w + v1.x+v1.y+v1.z+v1.w;
    float sq  = v0.x*v0.x+v0.y*v0.y+v0.z*v0.z+v0.w*v0.w
              + v1.x*v1.x+v1.y*v1.y+v1.z*v1.z+v1.w*v1.w;
#pragma unroll
    for (int off = 16; off; off >>= 1) {
        sum += __shfl_xor_sync(0xffffffffu, sum, off);
        sq  += __shfl_xor_sync(0xffffffffu, sq,  off);
    }
    __shared__ float s1[8], s2[8];
    if (lane == 0) { s1[w] = sum; s2[w] = sq; }
    __syncthreads();
    sum = 0.f; sq = 0.f;
#pragma unroll
    for (int k = 0; k < 8; k++) { sum += s1[k]; sq += s2[k]; }
    const float mean = sum * (1.f/2048.f);
    const float var  = sq  * (1.f/2048.f) - mean*mean;
    const float scl  = g[s] * rsqrtf(var + 1e-5f);
    const float sh   = be[s] - mean * scl;
    v0.x = v0.x*scl + sh; v0.y = v0.y*scl + sh; v0.z = v0.z*scl + sh; v0.w = v0.w*scl + sh;
    v1.x = v1.x*scl + sh; v1.y = v1.y*scl + sh; v1.z = v1.z*scl + sh; v1.w = v1.w*scl + sh;
    ((float4*)(X + r0))[tid] = v0;
    ((float4*)(X + r1))[tid] = v1;
    float h0 = __half2float(__float2half(v0.x)), h1 = __half2float(__float2half(v0.y));
    float h2 = __half2float(__float2half(v0.z)), h3 = __half2float(__float2half(v0.w));
    uint2 hp, lp;
    hp.x = packh(v0.x, v0.y); hp.y = packh(v0.z, v0.w);
    lp.x = packh(v0.x-h0, v0.y-h1); lp.y = packh(v0.z-h2, v0.w-h3);
    ((uint2*)(Xh + r0))[tid] = hp;
    ((uint2*)(Xl + r0))[tid] = lp;
    h0 = __half2float(__float2half(v1.x)); h1 = __half2float(__float2half(v1.y));
    h2 = __half2float(__float2half(v1.z)); h3 = __half2float(__float2half(v1.w));
    hp.x = packh(v1.x, v1.y); hp.y = packh(v1.z, v1.w);
    lp.x = packh(v1.x-h0, v1.y-h1); lp.y = packh(v1.z-h2, v1.w-h3);
    ((uint2*)(Xh + r1))[tid] = hp;
    ((uint2*)(Xl + r1))[tid] = lp;
}

// ---------------- host orchestration -------------------------------------------
extern "C" void kernel_launch(void* const* d_in, const int* in_sizes, int n_in,
                              void* d_out, int out_size)
{
    const float* x   = (const float*)d_in[0];
    const float* Wq1 = (const float*)d_in[1];  const float* bq1 = (const float*)d_in[2];
    const float* Wk1 = (const float*)d_in[3];  const float* bk1 = (const float*)d_in[4];
    const float* Wv1 = (const float*)d_in[5];  const float* bv1 = (const float*)d_in[6];
    const float* Wo1 = (const float*)d_in[7];  const float* bo1 = (const float*)d_in[8];
    const float* Wq2 = (const float*)d_in[9];  const float* bq2 = (const float*)d_in[10];
    const float* Wk2 = (const float*)d_in[11]; const float* bk2 = (const float*)d_in[12];
    const float* Wv2 = (const float*)d_in[13]; const float* bv2 = (const float*)d_in[14];
    const float* Wo2 = (const float*)d_in[15]; const float* bo2 = (const float*)d_in[16];
    const float* g1  = (const float*)d_in[17]; const float* be1 = (const float*)d_in[18];
    const float* g2  = (const float*)d_in[19]; const float* be2 = (const float*)d_in[20];
    const float* g3  = (const float*)d_in[21]; const float* be3 = (const float*)d_in[22];
    const float* W1  = (const float*)d_in[23]; const float* bf1 = (const float*)d_in[24];
    const float* W2  = (const float*)d_in[25]; const float* bf2 = (const float*)d_in[26];
    const int*   msk = (const int*)d_in[27];

    float *X, *X1, *Y, *bQ1, *bQ2;
    __half *Whi, *Wlo, *Xhi, *Xlo, *X1hi, *X1lo, *Yhi, *Ylo;
    __half *QKVhi, *QKVlo, *Ohi, *Olo, *Hhi, *Hlo;
    cudaGetSymbolAddress((void**)&X, g_X);       cudaGetSymbolAddress((void**)&X1, g_X1);
    cudaGetSymbolAddress((void**)&Y, g_Yb);
    cudaGetSymbolAddress((void**)&Whi, g_Whi);   cudaGetSymbolAddress((void**)&Wlo, g_Wlo);
    cudaGetSymbolAddress((void**)&Xhi, g_Xhi);   cudaGetSymbolAddress((void**)&Xlo, g_Xlo);
    cudaGetSymbolAddress((void**)&X1hi, g_X1hi); cudaGetSymbolAddress((void**)&X1lo, g_X1lo);
    cudaGetSymbolAddress((void**)&Yhi, g_Yhi);   cudaGetSymbolAddress((void**)&Ylo, g_Ylo);
    cudaGetSymbolAddress((void**)&QKVhi, g_QKVhi); cudaGetSymbolAddress((void**)&QKVlo, g_QKVlo);
    cudaGetSymbolAddress((void**)&Ohi, g_Ohi);   cudaGetSymbolAddress((void**)&Olo, g_Olo);
    cudaGetSymbolAddress((void**)&Hhi, g_Hhi);   cudaGetSymbolAddress((void**)&Hlo, g_Hlo);
    cudaGetSymbolAddress((void**)&bQ1, g_bQKV1); cudaGetSymbolAddress((void**)&bQ2, g_bQKV2);

    cudaFuncSetAttribute(gemm_tc, cudaFuncAttributeMaxDynamicSharedMemorySize, GEMM_SMEM);
    cudaFuncSetAttribute(attn_tc, cudaFuncAttributeMaxDynamicSharedMemorySize, ATT_SMEM);

    const size_t bytesD = (size_t)MROWS * DIM * sizeof(float);
    cudaMemcpyAsync(X, x, bytesD, cudaMemcpyDeviceToDevice);

    {
        dim3 b(256);
        dim3 gQ(32, 32, NL);
        size_t sQ = (size_t)NH * DIM * DK;
        wsplit_t<<<gQ, b>>>(Wq1, Whi, Wlo, 1024, 1024, sQ, OFF_Q1 + 0u,       1);
        wsplit_t<<<gQ, b>>>(Wk1, Whi, Wlo, 1024, 1024, sQ, OFF_Q1 + (1u<<20), 1);
        wsplit_t<<<gQ, b>>>(Wv1, Whi, Wlo, 1024, 1024, sQ, OFF_Q1 + (2u<<20), 1);
        wsplit_t<<<gQ, b>>>(Wo1, Whi, Wlo, 1024, 1024, (size_t)DIM*DIM, OFF_O1, 0);
        wsplit_t<<<gQ, b>>>(Wq2, Whi, Wlo, 1024, 1024, sQ, OFF_Q2 + 0u,       1);
        wsplit_t<<<gQ, b>>>(Wk2, Whi, Wlo, 1024, 1024, sQ, OFF_Q2 + (1u<<20), 1);
        wsplit_t<<<gQ, b>>>(Wv2, Whi, Wlo, 1024, 1024, sQ, OFF_Q2 + (2u<<20), 1);
        wsplit_t<<<gQ, b>>>(Wo2, Whi, Wlo, 1024, 1024, (size_t)DIM*DIM, OFF_O2, 0);
        wsplit_t<<<dim3(32, 128, NL), b>>>(W1, Whi, Wlo, 1024, 4096, (size_t)DIM*FF, OFF_W1, 0);
        wsplit_t<<<dim3(128, 32, NL), b>>>(W2, Whi, Wlo, 4096, 1024, (size_t)FF*DIM, OFF_W2, 0);
        pack_bias<<<dim3(4, NL), b>>>(bq1, bk1, bv1, bQ1);
        pack_bias<<<dim3(4, NL), b>>>(bq2, bk2, bv2, bQ2);
    }

    const int n4D = MROWS * DIM / 4;
    split_f32<<<n4D/256, 256>>>(X, Xhi, Xlo, n4D);

    dim3 gQKV(QKVW/128, MROWS/64);   // (24,32)
    dim3 gGD(DIM/128,  MROWS/64);    // (8,32)
    dim3 gGF(FF/128,   MROWS/64);    // (32,32)
    dim3 gA(SEQ/128, NH, NB);        // (8,16,2)

    for (int l = 0; l < NL; l++) {
        const __half* WH = Whi + (size_t)l * LAYER_W;
        const __half* WL = Wlo + (size_t)l * LAYER_W;
        const size_t dO = (size_t)l * DIM, f1O = (size_t)l * FF;

        // masked self-attention (fused QKV; masked K/V tiles skipped)
        gemm_tc<<<gQKV, 256, GEMM_SMEM>>>(Xhi, Xlo, WH+OFF_Q1, WL+OFF_Q1, bQ1 + l*QKVW,
                nullptr, nullptr, QKVhi, QKVlo, QKVW, DIM, 0, msk);
        attn_tc<<<gA, 256, ATT_SMEM>>>(QKVhi, QKVlo, Ohi, Olo, msk);
        gemm_tc<<<gGD, 256, GEMM_SMEM>>>(Ohi, Olo, WH+OFF_O1, WL+OFF_O1, bo1+dO,
                X, X1, nullptr, nullptr, DIM, DIM, 0, nullptr);
        bn_q<<<SEQ, 256>>>(X1, g1+dO, be1+dO, X1hi, X1lo);

        // second (unmasked) attention; residual from block input X
        gemm_tc<<<gQKV, 256, GEMM_SMEM>>>(X1hi, X1lo, WH+OFF_Q2, WL+OFF_Q2, bQ2 + l*QKVW,
                nullptr, nullptr, QKVhi, QKVlo, QKVW, DIM, 0, nullptr);
        attn_tc<<<gA, 256, ATT_SMEM>>>(QKVhi, QKVlo, Ohi, Olo, nullptr);
        gemm_tc<<<gGD, 256, GEMM_SMEM>>>(Ohi, Olo, WH+OFF_O2, WL+OFF_O2, bo2+dO,
                X, Y, nullptr, nullptr, DIM, DIM, 0, nullptr);
        bn_q<<<SEQ, 256>>>(Y, g2+dO, be2+dO, Yhi, Ylo);

        // FFN; residual from X1
        gemm_tc<<<gGF, 256, GEMM_SMEM>>>(Yhi, Ylo, WH+OFF_W1, WL+OFF_W1, bf1+f1O,
                nullptr, nullptr, Hhi, Hlo, FF, DIM, 1, nullptr);
        gemm_tc<<<gGD, 256, GEMM_SMEM>>>(Hhi, Hlo, WH+OFF_W2, WL+OFF_W2, bf2+dO,
                X1, X, nullptr, nullptr, DIM, FF, 0, nullptr);
        bn_q<<<SEQ, 256>>>(X, g3+dO, be3+dO, Xhi, Xlo);
    }

    cudaMemcpyAsync(d_out, X, bytesD, cudaMemcpyDeviceToDevice);
}

// round 10
// speedup vs baseline: 2.3071x; 1.0055x over previous
#include <cuda_runtime.h>
#include <cuda_fp16.h>
#include <cstdint>

#define NB  2
#define SEQ 1024
#define DIM 1024
#define NH  16
#define DK  64
#define FF  4096
#define NL  4
#define MROWS (NB*SEQ)
#define QKVW 3072

// ---------------- PTX helpers ------------------------------------------------
__device__ __forceinline__ uint32_t smem_to_u32(const void* p) {
    uint32_t a;
    asm("{ .reg .u64 t; cvta.to.shared.u64 t, %1; cvt.u32.u64 %0, t; }" : "=r"(a) : "l"(p));
    return a;
}
__device__ __forceinline__ void cpasync16(uint32_t dst, const void* src) {
    asm volatile("cp.async.cg.shared.global [%0], [%1], 16;"
                 :: "r"(dst), "l"(__cvta_generic_to_global(src)) : "memory");
}
__device__ __forceinline__ void cpcommit() { asm volatile("cp.async.commit_group;" ::: "memory"); }
__device__ __forceinline__ void cpwait0()  { asm volatile("cp.async.wait_group 0;" ::: "memory"); }
__device__ __forceinline__ void cpwait1()  { asm volatile("cp.async.wait_group 1;" ::: "memory"); }
__device__ __forceinline__ void ldsm4(uint32_t& r0, uint32_t& r1, uint32_t& r2, uint32_t& r3, uint32_t a) {
    asm volatile("ldmatrix.sync.aligned.m8n8.x4.shared.b16 {%0,%1,%2,%3}, [%4];"
                 : "=r"(r0), "=r"(r1), "=r"(r2), "=r"(r3) : "r"(a));
}
__device__ __forceinline__ void ldsm2(uint32_t& r0, uint32_t& r1, uint32_t a) {
    asm volatile("ldmatrix.sync.aligned.m8n8.x2.shared.b16 {%0,%1}, [%2];"
                 : "=r"(r0), "=r"(r1) : "r"(a));
}
__device__ __forceinline__ void ldsm4t(uint32_t& r0, uint32_t& r1, uint32_t& r2, uint32_t& r3, uint32_t a) {
    asm volatile("ldmatrix.sync.aligned.m8n8.x4.trans.shared.b16 {%0,%1,%2,%3}, [%4];"
                 : "=r"(r0), "=r"(r1), "=r"(r2), "=r"(r3) : "r"(a));
}
__device__ __forceinline__ void mmaF(float* d, const uint32_t* a, const uint32_t* b) {
    asm volatile("mma.sync.aligned.m16n8k16.row.col.f32.f16.f16.f32 "
                 "{%0,%1,%2,%3}, {%4,%5,%6,%7}, {%8,%9}, {%0,%1,%2,%3};"
                 : "+f"(d[0]), "+f"(d[1]), "+f"(d[2]), "+f"(d[3])
                 : "r"(a[0]), "r"(a[1]), "r"(a[2]), "r"(a[3]), "r"(b[0]), "r"(b[1]));
}
__device__ __forceinline__ uint32_t packh(float a, float b) {
    __half2 h = __floats2half2_rn(a, b);
    return *(uint32_t*)&h;
}

// ---------------- scratch -----------------------------------------------------
__device__ float g_X  [MROWS*DIM];
__device__ float g_X1 [MROWS*DIM];
__device__ float g_Yb [MROWS*DIM];
__device__ __half g_Xhi [MROWS*DIM],  g_Xlo [MROWS*DIM];
__device__ __half g_X1hi[MROWS*DIM],  g_X1lo[MROWS*DIM];
__device__ __half g_Yhi [MROWS*DIM],  g_Ylo [MROWS*DIM];
__device__ __half g_QKVhi[MROWS*QKVW], g_QKVlo[MROWS*QKVW];
__device__ __half g_Ohi [MROWS*DIM],  g_Olo [MROWS*DIM];
__device__ __half g_Hhi [MROWS*FF],   g_Hlo [MROWS*FF];
__device__ __half g_Whi[64u*1024*1024];
__device__ __half g_Wlo[64u*1024*1024];
__device__ float  g_bQKV1[NL*QKVW], g_bQKV2[NL*QKVW];

#define LAYER_W  (16u*1024*1024)
#define OFF_Q1   (0u)
#define OFF_O1   (3u*1024*1024)
#define OFF_Q2   (4u*1024*1024)
#define OFF_O2   (7u*1024*1024)
#define OFF_W1   (8u*1024*1024)
#define OFF_W2   (12u*1024*1024)

// ---------------- activation split: fp32 -> (hi, lo) f16 ----------------------
__global__ __launch_bounds__(256) void split_f32(const float* __restrict__ x,
        __half* __restrict__ h, __half* __restrict__ l, int n4)
{
    int i = blockIdx.x * 256 + threadIdx.x;
    if (i >= n4) return;
    float4 v = ((const float4*)x)[i];
    __half h0 = __float2half(v.x), h1 = __float2half(v.y);
    __half h2 = __float2half(v.z), h3 = __float2half(v.w);
    uint2 hp, lp;
    hp.x = packh(v.x, v.y); hp.y = packh(v.z, v.w);
    lp.x = packh(v.x - __half2float(h0), v.y - __half2float(h1));
    lp.y = packh(v.z - __half2float(h2), v.w - __half2float(h3));
    ((uint2*)h)[i] = hp;
    ((uint2*)l)[i] = lp;
}

// ------------- merged weight transpose+split (single launch, 10 jobs) ----------
struct WJobs {
    const float* W[10];
    int K[10], N[10];
    unsigned long long stride[10];
    unsigned outOff[10];
    int headMode[10];
    int start[10];          // starting block id of each job
};

__global__ __launch_bounds__(256) void wsplit_all(WJobs jobs,
        __half* __restrict__ oh, __half* __restrict__ ol)
{
    const int bid = blockIdx.x;
    int j = 0;
#pragma unroll
    for (int q = 1; q < 10; q++) if (bid >= jobs.start[q]) j = q;
    const int K = jobs.K[j], N = jobs.N[j];
    const int headMode = jobs.headMode[j];
    const int local = bid - jobs.start[j];
    const int nbk = K >> 5;
    const int perLayer = nbk * (N >> 5);
    const int z = local / perLayer;
    const int rem = local - z * perLayer;
    const int k0 = (rem % nbk) << 5;
    const int n0 = (rem / nbk) << 5;
    const float* Win = jobs.W[j] + (size_t)z * jobs.stride[j];
    const size_t ob = (size_t)z * LAYER_W + jobs.outOff[j];

    __shared__ float t[32][33];
    const int tx = threadIdx.x & 31, ty = threadIdx.x >> 5;
#pragma unroll
    for (int i = 0; i < 4; i++) {
        int k = k0 + ty + 8*i, n = n0 + tx;
        size_t idx = headMode ? ((size_t)(n >> 6) * K * 64 + (size_t)k * 64 + (n & 63))
                              : ((size_t)k * N + n);
        t[ty + 8*i][tx] = Win[idx];
    }
    __syncthreads();
    // vectorized store: each thread packs 4 consecutive k-halves -> one uint2 per buffer
    const int nl = threadIdx.x >> 3;        // 0..31 (n within tile)
    const int kq = threadIdx.x & 7;         // 0..7  (k quad)
    const int n = n0 + nl;
    float v0 = t[kq*4 + 0][nl], v1 = t[kq*4 + 1][nl];
    float v2 = t[kq*4 + 2][nl], v3 = t[kq*4 + 3][nl];
    float h0 = __half2float(__float2half(v0)), h1 = __half2float(__float2half(v1));
    float h2 = __half2float(__float2half(v2)), h3 = __half2float(__float2half(v3));
    uint2 hp, lp;
    hp.x = packh(v0, v1);       hp.y = packh(v2, v3);
    lp.x = packh(v0-h0, v1-h1); lp.y = packh(v2-h2, v3-h3);
    size_t base = ob + (size_t)n * K + k0 + kq*4;
    *(uint2*)(oh + base) = hp;
    *(uint2*)(ol + base) = lp;
}

__global__ __launch_bounds__(256) void pack_bias(const float* __restrict__ bq,
        const float* __restrict__ bk, const float* __restrict__ bv, float* __restrict__ out)
{
    int l = blockIdx.y;
    int i = blockIdx.x * 256 + threadIdx.x;
    out[l*QKVW + i]        = bq[l*1024 + i];
    out[l*QKVW + 1024 + i] = bk[l*1024 + i];
    out[l*QKVW + 2048 + i] = bv[l*1024 + i];
}

// ---------------- split-f16 HMMA GEMM: CTA 64x128, 2 CTAs/SM -------------------
#define RSB 144
#define SA_LO 9216
#define SB_HI 18432
#define SB_LO 36864
#define STAGE 55296
#define GEMM_SMEM (2*STAGE)   // 110592

__global__ __launch_bounds__(256, 2) void gemm_tc(
        const __half* __restrict__ Ah, const __half* __restrict__ Al,
        const __half* __restrict__ Bh, const __half* __restrict__ Bl,
        const float* __restrict__ bias, const float* __restrict__ R,
        float* __restrict__ C,
        __half* __restrict__ Chi, __half* __restrict__ Clo,
        int N, int K, int relu, const int* __restrict__ mskp)
{
    const int m0 = blockIdx.y * 64, n0 = blockIdx.x * 128;
    if (mskp && ((m0 & 1023) >= *mskp) && (n0 >= 1024)) return;  // masked K/V tokens
    extern __shared__ char smem[];
    const uint32_t sb = smem_to_u32(smem);
    const int tid = threadIdx.x, lane = tid & 31, wn = tid >> 5;

    float acc[4][2][4];
#pragma unroll
    for (int i = 0; i < 4; i++)
#pragma unroll
        for (int j = 0; j < 2; j++)
#pragma unroll
            for (int q = 0; q < 4; q++) acc[i][j][q] = 0.f;

    const int nch = K >> 6;
    auto issue = [&](int ch, int stg) {
        const int k0 = ch << 6;
        const uint32_t base = sb + stg * STAGE;
#pragma unroll
        for (int i = tid; i < 3072; i += 256) {
            if (i < 1024) {
                int t = i >> 9, j = i & 511, r = j >> 3, c = j & 7;
                const __half* src = (t ? Al : Ah) + (size_t)(m0 + r) * K + k0 + c * 8;
                cpasync16(base + t * SA_LO + r * RSB + c * 16, src);
            } else {
                int j = i - 1024, t = j >> 10, jj = j & 1023, r = jj >> 3, c = jj & 7;
                const __half* src = (t ? Bl : Bh) + (size_t)(n0 + r) * K + k0 + c * 8;
                cpasync16(base + SB_HI + t * (SB_LO - SB_HI) + r * RSB + c * 16, src);
            }
        }
        cpcommit();
    };
    issue(0, 0);

    for (int ch = 0; ch < nch; ch++) {
        cpwait0();
        __syncthreads();
        if (ch + 1 < nch) issue(ch + 1, (ch + 1) & 1);
        const uint32_t stg = sb + (ch & 1) * STAGE;
#pragma unroll
        for (int ks = 0; ks < 4; ks++) {
            uint32_t ah[4][4], al[4][4], bh[2][2], bl[2][2];
#pragma unroll
            for (int mt = 0; mt < 4; mt++) {
                uint32_t ad = stg + (mt*16 + (lane & 15)) * RSB + (lane >> 4) * 16 + ks * 32;
                ldsm4(ah[mt][0], ah[mt][1], ah[mt][2], ah[mt][3], ad);
                ldsm4(al[mt][0], al[mt][1], al[mt][2], al[mt][3], ad + SA_LO);
            }
#pragma unroll
            for (int ng = 0; ng < 2; ng++) {
                uint32_t bd = stg + SB_HI + (wn*16 + ng*8 + (lane & 7)) * RSB
                              + ((lane >> 3) & 1) * 16 + ks * 32;
                ldsm2(bh[ng][0], bh[ng][1], bd);
                ldsm2(bl[ng][0], bl[ng][1], bd + (SB_LO - SB_HI));
            }
#pragma unroll
            for (int mt = 0; mt < 4; mt++)
#pragma unroll
                for (int ng = 0; ng < 2; ng++) {
                    mmaF(acc[mt][ng], ah[mt], bh[ng]);
                    mmaF(acc[mt][ng], ah[mt], bl[ng]);
                    mmaF(acc[mt][ng], al[mt], bh[ng]);
                }
        }
    }

    const int g = lane >> 2, qc = (lane & 3) * 2;
#pragma unroll
    for (int mt = 0; mt < 4; mt++) {
        const int row0 = m0 + mt*16 + g;
        const int row1 = row0 + 8;
#pragma unroll
        for (int ng = 0; ng < 2; ng++) {
            const int col = n0 + wn*16 + ng*8 + qc;
            const float b0 = bias[col], b1 = bias[col + 1];
            float v00 = acc[mt][ng][0] + b0, v01 = acc[mt][ng][1] + b1;
            float v10 = acc[mt][ng][2] + b0, v11 = acc[mt][ng][3] + b1;
            if (R) {
                float2 r0 = *(const float2*)&R[(size_t)row0 * N + col];
                float2 r1 = *(const float2*)&R[(size_t)row1 * N + col];
                v00 += r0.x; v01 += r0.y; v10 += r1.x; v11 += r1.y;
            }
            if (relu) {
                v00 = fmaxf(v00, 0.f); v01 = fmaxf(v01, 0.f);
                v10 = fmaxf(v10, 0.f); v11 = fmaxf(v11, 0.f);
            }
            if (Chi) {
                float h00 = __half2float(__float2half(v00));
                float h01 = __half2float(__float2half(v01));
                float h10 = __half2float(__float2half(v10));
                float h11 = __half2float(__float2half(v11));
                *(uint32_t*)&Chi[(size_t)row0 * N + col] = packh(v00, v01);
                *(uint32_t*)&Chi[(size_t)row1 * N + col] = packh(v10, v11);
                *(uint32_t*)&Clo[(size_t)row0 * N + col] = packh(v00-h00, v01-h01);
                *(uint32_t*)&Clo[(size_t)row1 * N + col] = packh(v10-h10, v11-h11);
            } else {
                *(float2*)&C[(size_t)row0 * N + col] = make_float2(v00, v01);
                *(float2*)&C[(size_t)row1 * N + col] = make_float2(v10, v11);
            }
        }
    }
}

// ---------------- HMMA flash attention (split-f16, all f32-acc) ----------------
#define ARS 144
#define AQ_LO 18432
#define AKV0  36864
#define AKV_STAGE 36864
#define ATT_SMEM (AKV0 + 2*AKV_STAGE)

__global__ __launch_bounds__(256, 2) void attn_tc(
        const __half* __restrict__ QKVh, const __half* __restrict__ QKVl,
        __half* __restrict__ Ohi, __half* __restrict__ Olo,
        const int* __restrict__ mask_ptr)
{
    extern __shared__ char smem[];
    const uint32_t sb = smem_to_u32(smem);
    const int tid = threadIdx.x, lane = tid & 31, w = tid >> 5;
    const int q0 = blockIdx.x * 128, h = blockIdx.y, b = blockIdx.z;
    const int lim = mask_ptr ? *mask_ptr : SEQ;
    const size_t tokbase = (size_t)b * SEQ;
    const int cq = h * DK, ck = 1024 + h * DK, cv = 2048 + h * DK;

    for (int i = tid; i < 1024; i += 256) {
        int r = i >> 3, c = i & 7;
        uint32_t qd = sb + r * ARS + c * 16;
        size_t gi = (tokbase + q0 + r) * QKVW + cq + c * 8;
        cpasync16(qd, QKVh + gi);
        cpasync16(qd + AQ_LO, QKVl + gi);
    }
    auto ldkv = [&](int t, int stg) {
        uint32_t base = sb + AKV0 + stg * AKV_STAGE;
        for (int i = tid; i < 512; i += 256) {
            int r = i >> 3, c = i & 7;
            uint32_t off = r * ARS + c * 16;
            size_t row = (tokbase + t * 64 + r) * QKVW;
            cpasync16(base + off,         QKVh + row + ck + c * 8);
            cpasync16(base + 9216 + off,  QKVl + row + ck + c * 8);
            cpasync16(base + 18432 + off, QKVh + row + cv + c * 8);
            cpasync16(base + 27648 + off, QKVl + row + cv + c * 8);
        }
        cpcommit();
    };
    ldkv(0, 0);

    const int nt = (lim + 63) >> 6;
    const int g = lane >> 2, qc = (lane & 3) * 2;
    const int wq = w * 16;

    float m[2] = {-1e30f, -1e30f}, l[2] = {0.f, 0.f};
    float o[8][4];
#pragma unroll
    for (int i = 0; i < 8; i++)
#pragma unroll
        for (int j = 0; j < 4; j++) o[i][j] = 0.f;

    for (int t = 0; t < nt; t++) {
        __syncthreads();
        if (t + 1 < nt) { ldkv(t + 1, (t + 1) & 1); cpwait1(); }
        else           { cpwait0(); }
        __syncthreads();
        const uint32_t kb = sb + AKV0 + (t & 1) * AKV_STAGE;

        float sc[8][4];
#pragma unroll
        for (int i = 0; i < 8; i++)
#pragma unroll
            for (int j = 0; j < 4; j++) sc[i][j] = 0.f;

#pragma unroll
        for (int ks = 0; ks < 4; ks++) {
            uint32_t qa = sb + (wq + (lane & 15)) * ARS + (lane >> 4) * 16 + ks * 32;
            uint32_t qh[4], ql[4];
            ldsm4(qh[0], qh[1], qh[2], qh[3], qa);
            ldsm4(ql[0], ql[1], ql[2], ql[3], qa + AQ_LO);
#pragma unroll
            for (int p = 0; p < 4; p++) {
                uint32_t ka = kb + (p*16 + (lane & 7) + ((lane >> 4) & 1) * 8) * ARS
                              + ((lane >> 3) & 1) * 16 + ks * 32;
                uint32_t kh[4], kl[4];
                ldsm4(kh[0], kh[1], kh[2], kh[3], ka);
                ldsm4(kl[0], kl[1], kl[2], kl[3], ka + 9216);
                const uint32_t kh01[2] = {kh[0], kh[1]}, kh23[2] = {kh[2], kh[3]};
                const uint32_t kl01[2] = {kl[0], kl[1]}, kl23[2] = {kl[2], kl[3]};
                mmaF(sc[2*p],   qh, kh01);
                mmaF(sc[2*p],   qh, kl01);
                mmaF(sc[2*p],   ql, kh01);
                mmaF(sc[2*p+1], qh, kh23);
                mmaF(sc[2*p+1], qh, kl23);
                mmaF(sc[2*p+1], ql, kh23);
            }
        }

        const int t0 = t * 64;
#pragma unroll
        for (int na = 0; na < 8; na++) {
            int c0 = t0 + na*8 + qc, c1 = c0 + 1;
#pragma unroll
            for (int j = 0; j < 2; j++) {
                float s0 = sc[na][2*j]   * 0.125f;
                float s1 = sc[na][2*j+1] * 0.125f;
                sc[na][2*j]   = (c0 < lim) ? s0 : -1e30f;
                sc[na][2*j+1] = (c1 < lim) ? s1 : -1e30f;
            }
        }

#pragma unroll
        for (int j = 0; j < 2; j++) {
            float mx = -1e30f;
#pragma unroll
            for (int na = 0; na < 8; na++)
                mx = fmaxf(mx, fmaxf(sc[na][2*j], sc[na][2*j+1]));
            mx = fmaxf(mx, __shfl_xor_sync(0xffffffffu, mx, 1));
            mx = fmaxf(mx, __shfl_xor_sync(0xffffffffu, mx, 2));
            float mnew = fmaxf(m[j], mx);
            float corr = __expf(m[j] - mnew);
            l[j] *= corr;
            m[j] = mnew;
#pragma unroll
            for (int nd = 0; nd < 8; nd++) { o[nd][2*j] *= corr; o[nd][2*j+1] *= corr; }
            float sum = 0.f;
#pragma unroll
            for (int na = 0; na < 8; na++) {
                float p0 = __expf(sc[na][2*j]   - mnew);
                float p1 = __expf(sc[na][2*j+1] - mnew);
                sc[na][2*j] = p0; sc[na][2*j+1] = p1;
                sum += p0 + p1;
            }
            sum += __shfl_xor_sync(0xffffffffu, sum, 1);
            sum += __shfl_xor_sync(0xffffffffu, sum, 2);
            l[j] += sum;
        }

#pragma unroll
        for (int kp = 0; kp < 4; kp++) {
            float p00 = sc[2*kp][0],   p01 = sc[2*kp][1];
            float p02 = sc[2*kp][2],   p03 = sc[2*kp][3];
            float p10 = sc[2*kp+1][0], p11 = sc[2*kp+1][1];
            float p12 = sc[2*kp+1][2], p13 = sc[2*kp+1][3];
            float h00 = __half2float(__float2half(p00));
            float h01 = __half2float(__float2half(p01));
            float h02 = __half2float(__float2half(p02));
            float h03 = __half2float(__float2half(p03));
            float h10 = __half2float(__float2half(p10));
            float h11 = __half2float(__float2half(p11));
            float h12 = __half2float(__float2half(p12));
            float h13 = __half2float(__float2half(p13));
            uint32_t aph[4] = { packh(p00, p01), packh(p02, p03),
                                packh(p10, p11), packh(p12, p13) };
            uint32_t apl[4] = { packh(p00-h00, p01-h01), packh(p02-h02, p03-h03),
                                packh(p10-h10, p11-h11), packh(p12-h12, p13-h13) };
#pragma unroll
            for (int vp = 0; vp < 4; vp++) {
                uint32_t va = kb + 18432 + (kp*16 + (lane & 15)) * ARS
                              + (vp*2 + (lane >> 4)) * 16;
                uint32_t vh[4], vl[4];
                ldsm4t(vh[0], vh[1], vh[2], vh[3], va);
                ldsm4t(vl[0], vl[1], vl[2], vl[3], va + 9216);
                const uint32_t vh01[2] = {vh[0], vh[1]}, vh23[2] = {vh[2], vh[3]};
                const uint32_t vl01[2] = {vl[0], vl[1]}, vl23[2] = {vl[2], vl[3]};
                mmaF(o[2*vp],   aph, vh01);
                mmaF(o[2*vp],   aph, vl01);
                mmaF(o[2*vp],   apl, vh01);
                mmaF(o[2*vp+1], aph, vh23);
                mmaF(o[2*vp+1], aph, vl23);
                mmaF(o[2*vp+1], apl, vh23);
            }
        }
    }

#pragma unroll
    for (int j = 0; j < 2; j++) {
        float inv = 1.f / l[j];
        int row = q0 + wq + g + j*8;
        size_t gb = (tokbase + row) * DIM + h * DK;
#pragma unroll
        for (int nd = 0; nd < 8; nd++) {
            float v0 = o[nd][2*j] * inv, v1 = o[nd][2*j+1] * inv;
            float h0 = __half2float(__float2half(v0));
            float h1 = __half2float(__float2half(v1));
            *(uint32_t*)&Ohi[gb + nd*8 + qc] = packh(v0, v1);
            *(uint32_t*)&Olo[gb + nd*8 + qc] = packh(v0-h0, v1-h1);
        }
    }
}

// ---------------- BatchNorm1d + fused f16 split --------------------------------
__global__ __launch_bounds__(256)
void bn_q(float* __restrict__ X, const float* __restrict__ g, const float* __restrict__ be,
          __half* __restrict__ Xh, __half* __restrict__ Xl)
{
    const int s = blockIdx.x, tid = threadIdx.x;
    const int lane = tid & 31, w = tid >> 5;
    const size_t r0 = (size_t)s * DIM, r1 = (size_t)(SEQ + s) * DIM;
    float4 v0 = ((const float4*)(X + r0))[tid];
    float4 v1 = ((const float4*)(X + r1))[tid];
    float sum = v0.x+v0.y+v0.z+v0.w + v1.x+v1.y+v1.z+v1.w;
    float sq  = v0.x*v0.x+v0.y*v0.y+v0.z*v0.z+v0.w*v0.w
              + v1.x*v1.x+v1.y*v1.y+v1.z*v1.z+v1.w*v1.w;
#pragma unroll
    for (int off = 16; off; off >>= 1) {
        sum += __shfl_xor_sync(0xffffffffu, sum, off);
        sq  += __shfl_xor_sync(0xffffffffu, sq,  off);
    }
    __shared__ float s1[8], s2[8];
    if (lane == 0) { s1[w] = sum; s2[w] = sq; }
    __syncthreads();
    sum = 0.f; sq = 0.f;
#pragma unroll
    for (int k = 0; k < 8; k++) { sum += s1[k]; sq += s2[k]; }
    const float mean = sum * (1.f/2048.f);
    const float var  = sq  * (1.f/2048.f) - mean*mean;
    const float scl  = g[s] * rsqrtf(var + 1e-5f);
    const float sh   = be[s] - mean * scl;
    v0.x = v0.x*scl + sh; v0.y = v0.y*scl + sh; v0.z = v0.z*scl + sh; v0.w = v0.w*scl + sh;
    v1.x = v1.x*scl + sh; v1.y = v1.y*scl + sh; v1.z = v1.z*scl + sh; v1.w = v1.w*scl + sh;
    ((float4*)(X + r0))[tid] = v0;
    ((float4*)(X + r1))[tid] = v1;
    float h0 = __half2float(__float2half(v0.x)), h1 = __half2float(__float2half(v0.y));
    float h2 = __half2float(__float2half(v0.z)), h3 = __half2float(__float2half(v0.w));
    uint2 hp, lp;
    hp.x = packh(v0.x, v0.y); hp.y = packh(v0.z, v0.w);
    lp.x = packh(v0.x-h0, v0.y-h1); lp.y = packh(v0.z-h2, v0.w-h3);
    ((uint2*)(Xh + r0))[tid] = hp;
    ((uint2*)(Xl + r0))[tid] = lp;
    h0 = __half2float(__float2half(v1.x)); h1 = __half2float(__float2half(v1.y));
    h2 = __half2float(__float2half(v1.z)); h3 = __half2float(__float2half(v1.w));
    hp.x = packh(v1.x, v1.y); hp.y = packh(v1.z, v1.w);
    lp.x = packh(v1.x-h0, v1.y-h1); lp.y = packh(v1.z-h2, v1.w-h3);
    ((uint2*)(Xh + r1))[tid] = hp;
    ((uint2*)(Xl + r1))[tid] = lp;
}

// ---------------- host orchestration -------------------------------------------
extern "C" void kernel_launch(void* const* d_in, const int* in_sizes, int n_in,
                              void* d_out, int out_size)
{
    const float* x   = (const float*)d_in[0];
    const float* Wq1 = (const float*)d_in[1];  const float* bq1 = (const float*)d_in[2];
    const float* Wk1 = (const float*)d_in[3];  const float* bk1 = (const float*)d_in[4];
    const float* Wv1 = (const float*)d_in[5];  const float* bv1 = (const float*)d_in[6];
    const float* Wo1 = (const float*)d_in[7];  const float* bo1 = (const float*)d_in[8];
    const float* Wq2 = (const float*)d_in[9];  const float* bq2 = (const float*)d_in[10];
    const float* Wk2 = (const float*)d_in[11]; const float* bk2 = (const float*)d_in[12];
    const float* Wv2 = (const float*)d_in[13]; const float* bv2 = (const float*)d_in[14];
    const float* Wo2 = (const float*)d_in[15]; const float* bo2 = (const float*)d_in[16];
    const float* g1  = (const float*)d_in[17]; const float* be1 = (const float*)d_in[18];
    const float* g2  = (const float*)d_in[19]; const float* be2 = (const float*)d_in[20];
    const float* g3  = (const float*)d_in[21]; const float* be3 = (const float*)d_in[22];
    const float* W1  = (const float*)d_in[23]; const float* bf1 = (const float*)d_in[24];
    const float* W2  = (const float*)d_in[25]; const float* bf2 = (const float*)d_in[26];
    const int*   msk = (const int*)d_in[27];

    float *X, *X1, *Y, *bQ1, *bQ2;
    __half *Whi, *Wlo, *Xhi, *Xlo, *X1hi, *X1lo, *Yhi, *Ylo;
    __half *QKVhi, *QKVlo, *Ohi, *Olo, *Hhi, *Hlo;
    cudaGetSymbolAddress((void**)&X, g_X);       cudaGetSymbolAddress((void**)&X1, g_X1);
    cudaGetSymbolAddress((void**)&Y, g_Yb);
    cudaGetSymbolAddress((void**)&Whi, g_Whi);   cudaGetSymbolAddress((void**)&Wlo, g_Wlo);
    cudaGetSymbolAddress((void**)&Xhi, g_Xhi);   cudaGetSymbolAddress((void**)&Xlo, g_Xlo);
    cudaGetSymbolAddress((void**)&X1hi, g_X1hi); cudaGetSymbolAddress((void**)&X1lo, g_X1lo);
    cudaGetSymbolAddress((void**)&Yhi, g_Yhi);   cudaGetSymbolAddress((void**)&Ylo, g_Ylo);
    cudaGetSymbolAddress((void**)&QKVhi, g_QKVhi); cudaGetSymbolAddress((void**)&QKVlo, g_QKVlo);
    cudaGetSymbolAddress((void**)&Ohi, g_Ohi);   cudaGetSymbolAddress((void**)&Olo, g_Olo);
    cudaGetSymbolAddress((void**)&Hhi, g_Hhi);   cudaGetSymbolAddress((void**)&Hlo, g_Hlo);
    cudaGetSymbolAddress((void**)&bQ1, g_bQKV1); cudaGetSymbolAddress((void**)&bQ2, g_bQKV2);

    cudaFuncSetAttribute(gemm_tc, cudaFuncAttributeMaxDynamicSharedMemorySize, GEMM_SMEM);
    cudaFuncSetAttribute(attn_tc, cudaFuncAttributeMaxDynamicSharedMemorySize, ATT_SMEM);

    const size_t bytesD = (size_t)MROWS * DIM * sizeof(float);
    cudaMemcpyAsync(X, x, bytesD, cudaMemcpyDeviceToDevice);

    // ---- merged weight prep (1 launch) + bias concat ----
    {
        const size_t sQ = (size_t)NH * DIM * DK;   // 1M elems
        const size_t sO = (size_t)DIM * DIM;
        WJobs jobs;
        const float* Ws[10]  = {Wq1, Wk1, Wv1, Wo1, Wq2, Wk2, Wv2, Wo2, W1, W2};
        const int Ks[10]     = {1024,1024,1024,1024,1024,1024,1024,1024,1024,4096};
        const int Ns[10]     = {1024,1024,1024,1024,1024,1024,1024,1024,4096,1024};
        const unsigned long long st[10] = {sQ,sQ,sQ,sO,sQ,sQ,sQ,sO,(size_t)DIM*FF,(size_t)FF*DIM};
        const unsigned off[10] = {OFF_Q1, OFF_Q1+(1u<<20), OFF_Q1+(2u<<20), OFF_O1,
                                  OFF_Q2, OFF_Q2+(1u<<20), OFF_Q2+(2u<<20), OFF_O2,
                                  OFF_W1, OFF_W2};
        const int hm[10] = {1,1,1,0,1,1,1,0,0,0};
        int cum = 0;
        for (int j = 0; j < 10; j++) {
            jobs.W[j] = Ws[j]; jobs.K[j] = Ks[j]; jobs.N[j] = Ns[j];
            jobs.stride[j] = st[j]; jobs.outOff[j] = off[j]; jobs.headMode[j] = hm[j];
            jobs.start[j] = cum;
            cum += (Ks[j] >> 5) * (Ns[j] >> 5) * NL;
        }
        wsplit_all<<<cum, 256>>>(jobs, Whi, Wlo);   // cum = 65536
        pack_bias<<<dim3(4, NL), 256>>>(bq1, bk1, bv1, bQ1);
        pack_bias<<<dim3(4, NL), 256>>>(bq2, bk2, bv2, bQ2);
    }

    const int n4D = MROWS * DIM / 4;
    split_f32<<<n4D/256, 256>>>(X, Xhi, Xlo, n4D);

    dim3 gQKV(QKVW/128, MROWS/64);   // (24,32)
    dim3 gGD(DIM/128,  MROWS/64);    // (8,32)
    dim3 gGF(FF/128,   MROWS/64);    // (32,32)
    dim3 gA(SEQ/128, NH, NB);        // (8,16,2)

    for (int l = 0; l < NL; l++) {
        const __half* WH = Whi + (size_t)l * LAYER_W;
        const __half* WL = Wlo + (size_t)l * LAYER_W;
        const size_t dO = (size_t)l * DIM, f1O = (size_t)l * FF;

        // masked self-attention (fused QKV; masked K/V tiles skipped)
        gemm_tc<<<gQKV, 256, GEMM_SMEM>>>(Xhi, Xlo, WH+OFF_Q1, WL+OFF_Q1, bQ1 + l*QKVW,
                nullptr, nullptr, QKVhi, QKVlo, QKVW, DIM, 0, msk);
        attn_tc<<<gA, 256, ATT_SMEM>>>(QKVhi, QKVlo, Ohi, Olo, msk);
        gemm_tc<<<gGD, 256, GEMM_SMEM>>>(Ohi, Olo, WH+OFF_O1, WL+OFF_O1, bo1+dO,
                X, X1, nullptr, nullptr, DIM, DIM, 0, nullptr);
        bn_q<<<SEQ, 256>>>(X1, g1+dO, be1+dO, X1hi, X1lo);

        // second (unmasked) attention; residual from block input X
        gemm_tc<<<gQKV, 256, GEMM_SMEM>>>(X1hi, X1lo, WH+OFF_Q2, WL+OFF_Q2, bQ2 + l*QKVW,
                nullptr, nullptr, QKVhi, QKVlo, QKVW, DIM, 0, nullptr);
        attn_tc<<<gA, 256, ATT_SMEM>>>(QKVhi, QKVlo, Ohi, Olo, nullptr);
        gemm_tc<<<gGD, 256, GEMM_SMEM>>>(Ohi, Olo, WH+OFF_O2, WL+OFF_O2, bo2+dO,
                X, Y, nullptr, nullptr, DIM, DIM, 0, nullptr);
        bn_q<<<SEQ, 256>>>(Y, g2+dO, be2+dO, Yhi, Ylo);

        // FFN; residual from X1
        gemm_tc<<<gGF, 256, GEMM_SMEM>>>(Yhi, Ylo, WH+OFF_W1, WL+OFF_W1, bf1+f1O,
                nullptr, nullptr, Hhi, Hlo, FF, DIM, 1, nullptr);
        gemm_tc<<<gGD, 256, GEMM_SMEM>>>(Hhi, Hlo, WH+OFF_W2, WL+OFF_W2, bf2+dO,
                X1, X, nullptr, nullptr, DIM, FF, 0, nullptr);
        bn_q<<<SEQ, 256>>>(X, g3+dO, be3+dO, Xhi, Xlo);
    }

    cudaMemcpyAsync(d_out, X, bytesD, cudaMemcpyDeviceToDevice);
}

// round 11
// speedup vs baseline: 2.8903x; 1.2528x over previous
#include <cuda_runtime.h>
#include <cuda_fp16.h>
#include <cstdint>

#define NB  2
#define SEQ 1024
#define DIM 1024
#define NH  16
#define DK  64
#define FF  4096
#define NL  4
#define MROWS (NB*SEQ)
#define QKVW 3072

// ---------------- PTX helpers ------------------------------------------------
__device__ __forceinline__ uint32_t smem_to_u32(const void* p) {
    uint32_t a;
    asm("{ .reg .u64 t; cvta.to.shared.u64 t, %1; cvt.u32.u64 %0, t; }" : "=r"(a) : "l"(p));
    return a;
}
__device__ __forceinline__ void cpasync16(uint32_t dst, const void* src) {
    asm volatile("cp.async.cg.shared.global [%0], [%1], 16;"
                 :: "r"(dst), "l"(__cvta_generic_to_global(src)) : "memory");
}
__device__ __forceinline__ void cpcommit() { asm volatile("cp.async.commit_group;" ::: "memory"); }
__device__ __forceinline__ void cpwait0()  { asm volatile("cp.async.wait_group 0;" ::: "memory"); }
__device__ __forceinline__ void cpwait1()  { asm volatile("cp.async.wait_group 1;" ::: "memory"); }
__device__ __forceinline__ void ldsm4(uint32_t& r0, uint32_t& r1, uint32_t& r2, uint32_t& r3, uint32_t a) {
    asm volatile("ldmatrix.sync.aligned.m8n8.x4.shared.b16 {%0,%1,%2,%3}, [%4];"
                 : "=r"(r0), "=r"(r1), "=r"(r2), "=r"(r3) : "r"(a));
}
__device__ __forceinline__ void ldsm2(uint32_t& r0, uint32_t& r1, uint32_t a) {
    asm volatile("ldmatrix.sync.aligned.m8n8.x2.shared.b16 {%0,%1}, [%2];"
                 : "=r"(r0), "=r"(r1) : "r"(a));
}
__device__ __forceinline__ void ldsm4t(uint32_t& r0, uint32_t& r1, uint32_t& r2, uint32_t& r3, uint32_t a) {
    asm volatile("ldmatrix.sync.aligned.m8n8.x4.trans.shared.b16 {%0,%1,%2,%3}, [%4];"
                 : "=r"(r0), "=r"(r1), "=r"(r2), "=r"(r3) : "r"(a));
}
__device__ __forceinline__ void mmaF(float* d, const uint32_t* a, const uint32_t* b) {
    asm volatile("mma.sync.aligned.m16n8k16.row.col.f32.f16.f16.f32 "
                 "{%0,%1,%2,%3}, {%4,%5,%6,%7}, {%8,%9}, {%0,%1,%2,%3};"
                 : "+f"(d[0]), "+f"(d[1]), "+f"(d[2]), "+f"(d[3])
                 : "r"(a[0]), "r"(a[1]), "r"(a[2]), "r"(a[3]), "r"(b[0]), "r"(b[1]));
}
__device__ __forceinline__ uint32_t packh(float a, float b) {
    __half2 h = __floats2half2_rn(a, b);
    return *(uint32_t*)&h;
}

// ---------------- scratch -----------------------------------------------------
__device__ float g_X  [MROWS*DIM];
__device__ float g_X1 [MROWS*DIM];
__device__ float g_Yb [MROWS*DIM];
__device__ __half g_Xhi [MROWS*DIM],  g_Xlo [MROWS*DIM];
__device__ __half g_X1hi[MROWS*DIM],  g_X1lo[MROWS*DIM];
__device__ __half g_Yhi [MROWS*DIM],  g_Ylo [MROWS*DIM];
__device__ __half g_QKVhi[MROWS*QKVW], g_QKVlo[MROWS*QKVW];
__device__ __half g_Ohi [MROWS*DIM],  g_Olo [MROWS*DIM];
__device__ __half g_Hhi [MROWS*FF],   g_Hlo [MROWS*FF];
__device__ __half g_Whi[64u*1024*1024];     // weights: hi only (B-rounded scheme)
__device__ float  g_bQKV1[NL*QKVW], g_bQKV2[NL*QKVW];

#define LAYER_W  (16u*1024*1024)
#define OFF_Q1   (0u)
#define OFF_O1   (3u*1024*1024)
#define OFF_Q2   (4u*1024*1024)
#define OFF_O2   (7u*1024*1024)
#define OFF_W1   (8u*1024*1024)
#define OFF_W2   (12u*1024*1024)

// ---------------- activation split: fp32 -> (hi, lo) f16 ----------------------
__global__ __launch_bounds__(256) void split_f32(const float* __restrict__ x,
        __half* __restrict__ h, __half* __restrict__ l, int n4)
{
    int i = blockIdx.x * 256 + threadIdx.x;
    if (i >= n4) return;
    float4 v = ((const float4*)x)[i];
    __half h0 = __float2half(v.x), h1 = __float2half(v.y);
    __half h2 = __float2half(v.z), h3 = __float2half(v.w);
    uint2 hp, lp;
    hp.x = packh(v.x, v.y); hp.y = packh(v.z, v.w);
    lp.x = packh(v.x - __half2float(h0), v.y - __half2float(h1));
    lp.y = packh(v.z - __half2float(h2), v.w - __half2float(h3));
    ((uint2*)h)[i] = hp;
    ((uint2*)l)[i] = lp;
}

// ------------- merged weight transpose+round (single launch, 10 jobs) ----------
struct WJobs {
    const float* W[10];
    int K[10], N[10];
    unsigned long long stride[10];
    unsigned outOff[10];
    int headMode[10];
    int start[10];
};

__global__ __launch_bounds__(256) void wsplit_all(WJobs jobs, __half* __restrict__ oh)
{
    const int bid = blockIdx.x;
    int j = 0;
#pragma unroll
    for (int q = 1; q < 10; q++) if (bid >= jobs.start[q]) j = q;
    const int K = jobs.K[j], N = jobs.N[j];
    const int headMode = jobs.headMode[j];
    const int local = bid - jobs.start[j];
    const int nbk = K >> 5;
    const int perLayer = nbk * (N >> 5);
    const int z = local / perLayer;
    const int rem = local - z * perLayer;
    const int k0 = (rem % nbk) << 5;
    const int n0 = (rem / nbk) << 5;
    const float* Win = jobs.W[j] + (size_t)z * jobs.stride[j];
    const size_t ob = (size_t)z * LAYER_W + jobs.outOff[j];

    __shared__ float t[32][33];
    const int tx = threadIdx.x & 31, ty = threadIdx.x >> 5;
#pragma unroll
    for (int i = 0; i < 4; i++) {
        int k = k0 + ty + 8*i, n = n0 + tx;
        size_t idx = headMode ? ((size_t)(n >> 6) * K * 64 + (size_t)k * 64 + (n & 63))
                              : ((size_t)k * N + n);
        t[ty + 8*i][tx] = Win[idx];
    }
    __syncthreads();
    const int nl = threadIdx.x >> 3;
    const int kq = threadIdx.x & 7;
    const int n = n0 + nl;
    uint2 hp;
    hp.x = packh(t[kq*4 + 0][nl], t[kq*4 + 1][nl]);
    hp.y = packh(t[kq*4 + 2][nl], t[kq*4 + 3][nl]);
    *(uint2*)(oh + ob + (size_t)n * K + k0 + kq*4) = hp;
}

__global__ __launch_bounds__(256) void pack_bias(const float* __restrict__ bq,
        const float* __restrict__ bk, const float* __restrict__ bv, float* __restrict__ out)
{
    int l = blockIdx.y;
    int i = blockIdx.x * 256 + threadIdx.x;
    out[l*QKVW + i]        = bq[l*1024 + i];
    out[l*QKVW + 1024 + i] = bk[l*1024 + i];
    out[l*QKVW + 2048 + i] = bv[l*1024 + i];
}

// ------- split-A x rounded-B HMMA GEMM: CTA 64x128, 2 terms, 2 CTAs/SM ---------
#define RSB 144
#define SA_LO 9216
#define SB_HI 18432
#define STAGE 36864
#define GEMM_SMEM (2*STAGE)   // 73728

__global__ __launch_bounds__(256, 2) void gemm_tc(
        const __half* __restrict__ Ah, const __half* __restrict__ Al,
        const __half* __restrict__ Bh,
        const float* __restrict__ bias, const float* __restrict__ R,
        float* __restrict__ C,
        __half* __restrict__ Chi, __half* __restrict__ Clo,
        int N, int K, int relu, const int* __restrict__ mskp)
{
    const int m0 = blockIdx.y * 64, n0 = blockIdx.x * 128;
    if (mskp && ((m0 & 1023) >= *mskp) && (n0 >= 1024)) return;  // masked K/V tokens
    extern __shared__ char smem[];
    const uint32_t sb = smem_to_u32(smem);
    const int tid = threadIdx.x, lane = tid & 31, wn = tid >> 5;

    float acc[4][2][4];
#pragma unroll
    for (int i = 0; i < 4; i++)
#pragma unroll
        for (int j = 0; j < 2; j++)
#pragma unroll
            for (int q = 0; q < 4; q++) acc[i][j][q] = 0.f;

    const int nch = K >> 6;
    auto issue = [&](int ch, int stg) {
        const int k0 = ch << 6;
        const uint32_t base = sb + stg * STAGE;
#pragma unroll
        for (int i = tid; i < 2048; i += 256) {
            if (i < 1024) {                       // Ah/Al: 64 rows x 8 vecs x 2
                int t = i >> 9, j = i & 511, r = j >> 3, c = j & 7;
                const __half* src = (t ? Al : Ah) + (size_t)(m0 + r) * K + k0 + c * 8;
                cpasync16(base + t * SA_LO + r * RSB + c * 16, src);
            } else {                              // Bh: 128 rows x 8 vecs
                int j = i - 1024, r = j >> 3, c = j & 7;
                cpasync16(base + SB_HI + r * RSB + c * 16,
                          Bh + (size_t)(n0 + r) * K + k0 + c * 8);
            }
        }
        cpcommit();
    };
    issue(0, 0);

    for (int ch = 0; ch < nch; ch++) {
        cpwait0();
        __syncthreads();
        if (ch + 1 < nch) issue(ch + 1, (ch + 1) & 1);
        const uint32_t stg = sb + (ch & 1) * STAGE;
#pragma unroll
        for (int ks = 0; ks < 4; ks++) {
            uint32_t ah[4][4], al[4][4], bh[2][2];
#pragma unroll
            for (int mt = 0; mt < 4; mt++) {
                uint32_t ad = stg + (mt*16 + (lane & 15)) * RSB + (lane >> 4) * 16 + ks * 32;
                ldsm4(ah[mt][0], ah[mt][1], ah[mt][2], ah[mt][3], ad);
                ldsm4(al[mt][0], al[mt][1], al[mt][2], al[mt][3], ad + SA_LO);
            }
#pragma unroll
            for (int ng = 0; ng < 2; ng++) {
                uint32_t bd = stg + SB_HI + (wn*16 + ng*8 + (lane & 7)) * RSB
                              + ((lane >> 3) & 1) * 16 + ks * 32;
                ldsm2(bh[ng][0], bh[ng][1], bd);
            }
#pragma unroll
            for (int mt = 0; mt < 4; mt++)
#pragma unroll
                for (int ng = 0; ng < 2; ng++) {
                    mmaF(acc[mt][ng], ah[mt], bh[ng]);
                    mmaF(acc[mt][ng], al[mt], bh[ng]);
                }
        }
    }

    const int g = lane >> 2, qc = (lane & 3) * 2;
#pragma unroll
    for (int mt = 0; mt < 4; mt++) {
        const int row0 = m0 + mt*16 + g;
        const int row1 = row0 + 8;
#pragma unroll
        for (int ng = 0; ng < 2; ng++) {
            const int col = n0 + wn*16 + ng*8 + qc;
            const float b0 = bias[col], b1 = bias[col + 1];
            float v00 = acc[mt][ng][0] + b0, v01 = acc[mt][ng][1] + b1;
            float v10 = acc[mt][ng][2] + b0, v11 = acc[mt][ng][3] + b1;
            if (R) {
                float2 r0 = *(const float2*)&R[(size_t)row0 * N + col];
                float2 r1 = *(const float2*)&R[(size_t)row1 * N + col];
                v00 += r0.x; v01 += r0.y; v10 += r1.x; v11 += r1.y;
            }
            if (relu) {
                v00 = fmaxf(v00, 0.f); v01 = fmaxf(v01, 0.f);
                v10 = fmaxf(v10, 0.f); v11 = fmaxf(v11, 0.f);
            }
            if (Chi) {
                float h00 = __half2float(__float2half(v00));
                float h01 = __half2float(__float2half(v01));
                float h10 = __half2float(__float2half(v10));
                float h11 = __half2float(__float2half(v11));
                *(uint32_t*)&Chi[(size_t)row0 * N + col] = packh(v00, v01);
                *(uint32_t*)&Chi[(size_t)row1 * N + col] = packh(v10, v11);
                *(uint32_t*)&Clo[(size_t)row0 * N + col] = packh(v00-h00, v01-h01);
                *(uint32_t*)&Clo[(size_t)row1 * N + col] = packh(v10-h10, v11-h11);
            } else {
                *(float2*)&C[(size_t)row0 * N + col] = make_float2(v00, v01);
                *(float2*)&C[(size_t)row1 * N + col] = make_float2(v10, v11);
            }
        }
    }
}

// ---------------- HMMA flash attention (split-f16, all f32-acc, 3-term) --------
#define ARS 144
#define AQ_LO 18432
#define AKV0  36864
#define AKV_STAGE 36864
#define ATT_SMEM (AKV0 + 2*AKV_STAGE)

__global__ __launch_bounds__(256, 2) void attn_tc(
        const __half* __restrict__ QKVh, const __half* __restrict__ QKVl,
        __half* __restrict__ Ohi, __half* __restrict__ Olo,
        const int* __restrict__ mask_ptr)
{
    extern __shared__ char smem[];
    const uint32_t sb = smem_to_u32(smem);
    const int tid = threadIdx.x, lane = tid & 31, w = tid >> 5;
    const int q0 = blockIdx.x * 128, h = blockIdx.y, b = blockIdx.z;
    const int lim = mask_ptr ? *mask_ptr : SEQ;
    const size_t tokbase = (size_t)b * SEQ;
    const int cq = h * DK, ck = 1024 + h * DK, cv = 2048 + h * DK;

    for (int i = tid; i < 1024; i += 256) {
        int r = i >> 3, c = i & 7;
        uint32_t qd = sb + r * ARS + c * 16;
        size_t gi = (tokbase + q0 + r) * QKVW + cq + c * 8;
        cpasync16(qd, QKVh + gi);
        cpasync16(qd + AQ_LO, QKVl + gi);
    }
    auto ldkv = [&](int t, int stg) {
        uint32_t base = sb + AKV0 + stg * AKV_STAGE;
        for (int i = tid; i < 512; i += 256) {
            int r = i >> 3, c = i & 7;
            uint32_t off = r * ARS + c * 16;
            size_t row = (tokbase + t * 64 + r) * QKVW;
            cpasync16(base + off,         QKVh + row + ck + c * 8);
            cpasync16(base + 9216 + off,  QKVl + row + ck + c * 8);
            cpasync16(base + 18432 + off, QKVh + row + cv + c * 8);
            cpasync16(base + 27648 + off, QKVl + row + cv + c * 8);
        }
        cpcommit();
    };
    ldkv(0, 0);

    const int nt = (lim + 63) >> 6;
    const int g = lane >> 2, qc = (lane & 3) * 2;
    const int wq = w * 16;

    float m[2] = {-1e30f, -1e30f}, l[2] = {0.f, 0.f};
    float o[8][4];
#pragma unroll
    for (int i = 0; i < 8; i++)
#pragma unroll
        for (int j = 0; j < 4; j++) o[i][j] = 0.f;

    for (int t = 0; t < nt; t++) {
        __syncthreads();
        if (t + 1 < nt) { ldkv(t + 1, (t + 1) & 1); cpwait1(); }
        else           { cpwait0(); }
        __syncthreads();
        const uint32_t kb = sb + AKV0 + (t & 1) * AKV_STAGE;

        float sc[8][4];
#pragma unroll
        for (int i = 0; i < 8; i++)
#pragma unroll
            for (int j = 0; j < 4; j++) sc[i][j] = 0.f;

#pragma unroll
        for (int ks = 0; ks < 4; ks++) {
            uint32_t qa = sb + (wq + (lane & 15)) * ARS + (lane >> 4) * 16 + ks * 32;
            uint32_t qh[4], ql[4];
            ldsm4(qh[0], qh[1], qh[2], qh[3], qa);
            ldsm4(ql[0], ql[1], ql[2], ql[3], qa + AQ_LO);
#pragma unroll
            for (int p = 0; p < 4; p++) {
                uint32_t ka = kb + (p*16 + (lane & 7) + ((lane >> 4) & 1) * 8) * ARS
                              + ((lane >> 3) & 1) * 16 + ks * 32;
                uint32_t kh[4], kl[4];
                ldsm4(kh[0], kh[1], kh[2], kh[3], ka);
                ldsm4(kl[0], kl[1], kl[2], kl[3], ka + 9216);
                const uint32_t kh01[2] = {kh[0], kh[1]}, kh23[2] = {kh[2], kh[3]};
                const uint32_t kl01[2] = {kl[0], kl[1]}, kl23[2] = {kl[2], kl[3]};
                mmaF(sc[2*p],   qh, kh01);
                mmaF(sc[2*p],   qh, kl01);
                mmaF(sc[2*p],   ql, kh01);
                mmaF(sc[2*p+1], qh, kh23);
                mmaF(sc[2*p+1], qh, kl23);
                mmaF(sc[2*p+1], ql, kh23);
            }
        }

        const int t0 = t * 64;
#pragma unroll
        for (int na = 0; na < 8; na++) {
            int c0 = t0 + na*8 + qc, c1 = c0 + 1;
#pragma unroll
            for (int j = 0; j < 2; j++) {
                float s0 = sc[na][2*j]   * 0.125f;
                float s1 = sc[na][2*j+1] * 0.125f;
                sc[na][2*j]   = (c0 < lim) ? s0 : -1e30f;
                sc[na][2*j+1] = (c1 < lim) ? s1 : -1e30f;
            }
        }

#pragma unroll
        for (int j = 0; j < 2; j++) {
            float mx = -1e30f;
#pragma unroll
            for (int na = 0; na < 8; na++)
                mx = fmaxf(mx, fmaxf(sc[na][2*j], sc[na][2*j+1]));
            mx = fmaxf(mx, __shfl_xor_sync(0xffffffffu, mx, 1));
            mx = fmaxf(mx, __shfl_xor_sync(0xffffffffu, mx, 2));
            float mnew = fmaxf(m[j], mx);
            float corr = __expf(m[j] - mnew);
            l[j] *= corr;
            m[j] = mnew;
#pragma unroll
            for (int nd = 0; nd < 8; nd++) { o[nd][2*j] *= corr; o[nd][2*j+1] *= corr; }
            float sum = 0.f;
#pragma unroll
            for (int na = 0; na < 8; na++) {
                float p0 = __expf(sc[na][2*j]   - mnew);
                float p1 = __expf(sc[na][2*j+1] - mnew);
                sc[na][2*j] = p0; sc[na][2*j+1] = p1;
                sum += p0 + p1;
            }
            sum += __shfl_xor_sync(0xffffffffu, sum, 1);
            sum += __shfl_xor_sync(0xffffffffu, sum, 2);
            l[j] += sum;
        }

#pragma unroll
        for (int kp = 0; kp < 4; kp++) {
            float p00 = sc[2*kp][0],   p01 = sc[2*kp][1];
            float p02 = sc[2*kp][2],   p03 = sc[2*kp][3];
            float p10 = sc[2*kp+1][0], p11 = sc[2*kp+1][1];
            float p12 = sc[2*kp+1][2], p13 = sc[2*kp+1][3];
            float h00 = __half2float(__float2half(p00));
            float h01 = __half2float(__float2half(p01));
            float h02 = __half2float(__float2half(p02));
            float h03 = __half2float(__float2half(p03));
            float h10 = __half2float(__float2half(p10));
            float h11 = __half2float(__float2half(p11));
            float h12 = __half2float(__float2half(p12));
            float h13 = __half2float(__float2half(p13));
            uint32_t aph[4] = { packh(p00, p01), packh(p02, p03),
                                packh(p10, p11), packh(p12, p13) };
            uint32_t apl[4] = { packh(p00-h00, p01-h01), packh(p02-h02, p03-h03),
                                packh(p10-h10, p11-h11), packh(p12-h12, p13-h13) };
#pragma unroll
            for (int vp = 0; vp < 4; vp++) {
                uint32_t va = kb + 18432 + (kp*16 + (lane & 15)) * ARS
                              + (vp*2 + (lane >> 4)) * 16;
                uint32_t vh[4], vl[4];
                ldsm4t(vh[0], vh[1], vh[2], vh[3], va);
                ldsm4t(vl[0], vl[1], vl[2], vl[3], va + 9216);
                const uint32_t vh01[2] = {vh[0], vh[1]}, vh23[2] = {vh[2], vh[3]};
                const uint32_t vl01[2] = {vl[0], vl[1]}, vl23[2] = {vl[2], vl[3]};
                mmaF(o[2*vp],   aph, vh01);
                mmaF(o[2*vp],   aph, vl01);
                mmaF(o[2*vp],   apl, vh01);
                mmaF(o[2*vp+1], aph, vh23);
                mmaF(o[2*vp+1], aph, vl23);
                mmaF(o[2*vp+1], apl, vh23);
            }
        }
    }

#pragma unroll
    for (int j = 0; j < 2; j++) {
        float inv = 1.f / l[j];
        int row = q0 + wq + g + j*8;
        size_t gb = (tokbase + row) * DIM + h * DK;
#pragma unroll
        for (int nd = 0; nd < 8; nd++) {
            float v0 = o[nd][2*j] * inv, v1 = o[nd][2*j+1] * inv;
            float h0 = __half2float(__float2half(v0));
            float h1 = __half2float(__float2half(v1));
            *(uint32_t*)&Ohi[gb + nd*8 + qc] = packh(v0, v1);
            *(uint32_t*)&Olo[gb + nd*8 + qc] = packh(v0-h0, v1-h1);
        }
    }
}

// ---------------- BatchNorm1d + fused f16 split --------------------------------
__global__ __launch_bounds__(256)
void bn_q(float* __restrict__ X, const float* __restrict__ g, const float* __restrict__ be,
          __half* __restrict__ Xh, __half* __restrict__ Xl)
{
    const int s = blockIdx.x, tid = threadIdx.x;
    const int lane = tid & 31, w = tid >> 5;
    const size_t r0 = (size_t)s * DIM, r1 = (size_t)(SEQ + s) * DIM;
    float4 v0 = ((const float4*)(X + r0))[tid];
    float4 v1 = ((const float4*)(X + r1))[tid];
    float sum = v0.x+v0.y+v0.z+v0.w + v1.x+v1.y+v1.z+v1.w;
    float sq  = v0.x*v0.x+v0.y*v0.y+v0.z*v0.z+v0.w*v0.w
              + v1.x*v1.x+v1.y*v1.y+v1.z*v1.z+v1.w*v1.w;
#pragma unroll
    for (int off = 16; off; off >>= 1) {
        sum += __shfl_xor_sync(0xffffffffu, sum, off);
        sq  += __shfl_xor_sync(0xffffffffu, sq,  off);
    }
    __shared__ float s1[8], s2[8];
    if (lane == 0) { s1[w] = sum; s2[w] = sq; }
    __syncthreads();
    sum = 0.f; sq = 0.f;
#pragma unroll
    for (int k = 0; k < 8; k++) { sum += s1[k]; sq += s2[k]; }
    const float mean = sum * (1.f/2048.f);
    const float var  = sq  * (1.f/2048.f) - mean*mean;
    const float scl  = g[s] * rsqrtf(var + 1e-5f);
    const float sh   = be[s] - mean * scl;
    v0.x = v0.x*scl + sh; v0.y = v0.y*scl + sh; v0.z = v0.z*scl + sh; v0.w = v0.w*scl + sh;
    v1.x = v1.x*scl + sh; v1.y = v1.y*scl + sh; v1.z = v1.z*scl + sh; v1.w = v1.w*scl + sh;
    ((float4*)(X + r0))[tid] = v0;
    ((float4*)(X + r1))[tid] = v1;
    float h0 = __half2float(__float2half(v0.x)), h1 = __half2float(__float2half(v0.y));
    float h2 = __half2float(__float2half(v0.z)), h3 = __half2float(__float2half(v0.w));
    uint2 hp, lp;
    hp.x = packh(v0.x, v0.y); hp.y = packh(v0.z, v0.w);
    lp.x = packh(v0.x-h0, v0.y-h1); lp.y = packh(v0.z-h2, v0.w-h3);
    ((uint2*)(Xh + r0))[tid] = hp;
    ((uint2*)(Xl + r0))[tid] = lp;
    h0 = __half2float(__float2half(v1.x)); h1 = __half2float(__float2half(v1.y));
    h2 = __half2float(__float2half(v1.z)); h3 = __half2float(__float2half(v1.w));
    hp.x = packh(v1.x, v1.y); hp.y = packh(v1.z, v1.w);
    lp.x = packh(v1.x-h0, v1.y-h1); lp.y = packh(v1.z-h2, v1.w-h3);
    ((uint2*)(Xh + r1))[tid] = hp;
    ((uint2*)(Xl + r1))[tid] = lp;
}

// ---------------- host orchestration -------------------------------------------
extern "C" void kernel_launch(void* const* d_in, const int* in_sizes, int n_in,
                              void* d_out, int out_size)
{
    const float* x   = (const float*)d_in[0];
    const float* Wq1 = (const float*)d_in[1];  const float* bq1 = (const float*)d_in[2];
    const float* Wk1 = (const float*)d_in[3];  const float* bk1 = (const float*)d_in[4];
    const float* Wv1 = (const float*)d_in[5];  const float* bv1 = (const float*)d_in[6];
    const float* Wo1 = (const float*)d_in[7];  const float* bo1 = (const float*)d_in[8];
    const float* Wq2 = (const float*)d_in[9];  const float* bq2 = (const float*)d_in[10];
    const float* Wk2 = (const float*)d_in[11]; const float* bk2 = (const float*)d_in[12];
    const float* Wv2 = (const float*)d_in[13]; const float* bv2 = (const float*)d_in[14];
    const float* Wo2 = (const float*)d_in[15]; const float* bo2 = (const float*)d_in[16];
    const float* g1  = (const float*)d_in[17]; const float* be1 = (const float*)d_in[18];
    const float* g2  = (const float*)d_in[19]; const float* be2 = (const float*)d_in[20];
    const float* g3  = (const float*)d_in[21]; const float* be3 = (const float*)d_in[22];
    const float* W1  = (const float*)d_in[23]; const float* bf1 = (const float*)d_in[24];
    const float* W2  = (const float*)d_in[25]; const float* bf2 = (const float*)d_in[26];
    const int*   msk = (const int*)d_in[27];

    float *X, *X1, *Y, *bQ1, *bQ2;
    __half *Whi, *Xhi, *Xlo, *X1hi, *X1lo, *Yhi, *Ylo;
    __half *QKVhi, *QKVlo, *Ohi, *Olo, *Hhi, *Hlo;
    cudaGetSymbolAddress((void**)&X, g_X);       cudaGetSymbolAddress((void**)&X1, g_X1);
    cudaGetSymbolAddress((void**)&Y, g_Yb);
    cudaGetSymbolAddress((void**)&Whi, g_Whi);
    cudaGetSymbolAddress((void**)&Xhi, g_Xhi);   cudaGetSymbolAddress((void**)&Xlo, g_Xlo);
    cudaGetSymbolAddress((void**)&X1hi, g_X1hi); cudaGetSymbolAddress((void**)&X1lo, g_X1lo);
    cudaGetSymbolAddress((void**)&Yhi, g_Yhi);   cudaGetSymbolAddress((void**)&Ylo, g_Ylo);
    cudaGetSymbolAddress((void**)&QKVhi, g_QKVhi); cudaGetSymbolAddress((void**)&QKVlo, g_QKVlo);
    cudaGetSymbolAddress((void**)&Ohi, g_Ohi);   cudaGetSymbolAddress((void**)&Olo, g_Olo);
    cudaGetSymbolAddress((void**)&Hhi, g_Hhi);   cudaGetSymbolAddress((void**)&Hlo, g_Hlo);
    cudaGetSymbolAddress((void**)&bQ1, g_bQKV1); cudaGetSymbolAddress((void**)&bQ2, g_bQKV2);

    cudaFuncSetAttribute(gemm_tc, cudaFuncAttributeMaxDynamicSharedMemorySize, GEMM_SMEM);
    cudaFuncSetAttribute(attn_tc, cudaFuncAttributeMaxDynamicSharedMemorySize, ATT_SMEM);

    const size_t bytesD = (size_t)MROWS * DIM * sizeof(float);
    cudaMemcpyAsync(X, x, bytesD, cudaMemcpyDeviceToDevice);

    // ---- merged weight prep (1 launch) + bias concat ----
    {
        const size_t sQ = (size_t)NH * DIM * DK;
        const size_t sO = (size_t)DIM * DIM;
        WJobs jobs;
        const float* Ws[10]  = {Wq1, Wk1, Wv1, Wo1, Wq2, Wk2, Wv2, Wo2, W1, W2};
        const int Ks[10]     = {1024,1024,1024,1024,1024,1024,1024,1024,1024,4096};
        const int Ns[10]     = {1024,1024,1024,1024,1024,1024,1024,1024,4096,1024};
        const unsigned long long st[10] = {sQ,sQ,sQ,sO,sQ,sQ,sQ,sO,(size_t)DIM*FF,(size_t)FF*DIM};
        const unsigned off[10] = {OFF_Q1, OFF_Q1+(1u<<20), OFF_Q1+(2u<<20), OFF_O1,
                                  OFF_Q2, OFF_Q2+(1u<<20), OFF_Q2+(2u<<20), OFF_O2,
                                  OFF_W1, OFF_W2};
        const int hm[10] = {1,1,1,0,1,1,1,0,0,0};
        int cum = 0;
        for (int j = 0; j < 10; j++) {
            jobs.W[j] = Ws[j]; jobs.K[j] = Ks[j]; jobs.N[j] = Ns[j];
            jobs.stride[j] = st[j]; jobs.outOff[j] = off[j]; jobs.headMode[j] = hm[j];
            jobs.start[j] = cum;
            cum += (Ks[j] >> 5) * (Ns[j] >> 5) * NL;
        }
        wsplit_all<<<cum, 256>>>(jobs, Whi);
        pack_bias<<<dim3(4, NL), 256>>>(bq1, bk1, bv1, bQ1);
        pack_bias<<<dim3(4, NL), 256>>>(bq2, bk2, bv2, bQ2);
    }

    const int n4D = MROWS * DIM / 4;
    split_f32<<<n4D/256, 256>>>(X, Xhi, Xlo, n4D);

    dim3 gQKV(QKVW/128, MROWS/64);   // (24,32)
    dim3 gGD(DIM/128,  MROWS/64);    // (8,32)
    dim3 gGF(FF/128,   MROWS/64);    // (32,32)
    dim3 gA(SEQ/128, NH, NB);        // (8,16,2)

    for (int l = 0; l < NL; l++) {
        const __half* WH = Whi + (size_t)l * LAYER_W;
        const size_t dO = (size_t)l * DIM, f1O = (size_t)l * FF;

        // masked self-attention (fused QKV; masked K/V tiles skipped)
        gemm_tc<<<gQKV, 256, GEMM_SMEM>>>(Xhi, Xlo, WH+OFF_Q1, bQ1 + l*QKVW,
                nullptr, nullptr, QKVhi, QKVlo, QKVW, DIM, 0, msk);
        attn_tc<<<gA, 256, ATT_SMEM>>>(QKVhi, QKVlo, Ohi, Olo, msk);
        gemm_tc<<<gGD, 256, GEMM_SMEM>>>(Ohi, Olo, WH+OFF_O1, bo1+dO,
                X, X1, nullptr, nullptr, DIM, DIM, 0, nullptr);
        bn_q<<<SEQ, 256>>>(X1, g1+dO, be1+dO, X1hi, X1lo);

        // second (unmasked) attention; residual from block input X
        gemm_tc<<<gQKV, 256, GEMM_SMEM>>>(X1hi, X1lo, WH+OFF_Q2, bQ2 + l*QKVW,
                nullptr, nullptr, QKVhi, QKVlo, QKVW, DIM, 0, nullptr);
        attn_tc<<<gA, 256, ATT_SMEM>>>(QKVhi, QKVlo, Ohi, Olo, nullptr);
        gemm_tc<<<gGD, 256, GEMM_SMEM>>>(Ohi, Olo, WH+OFF_O2, bo2+dO,
                X, Y, nullptr, nullptr, DIM, DIM, 0, nullptr);
        bn_q<<<SEQ, 256>>>(Y, g2+dO, be2+dO, Yhi, Ylo);

        // FFN; residual from X1
        gemm_tc<<<gGF, 256, GEMM_SMEM>>>(Yhi, Ylo, WH+OFF_W1, bf1+f1O,
                nullptr, nullptr, Hhi, Hlo, FF, DIM, 1, nullptr);
        gemm_tc<<<gGD, 256, GEMM_SMEM>>>(Hhi, Hlo, WH+OFF_W2, bf2+dO,
                X1, X, nullptr, nullptr, DIM, FF, 0, nullptr);
        bn_q<<<SEQ, 256>>>(X, g3+dO, be3+dO, Xhi, Xlo);
    }

    cudaMemcpyAsync(d_out, X, bytesD, cudaMemcpyDeviceToDevice);
}

// round 12
// speedup vs baseline: 3.0378x; 1.0510x over previous
#include <cuda_runtime.h>
#include <cuda_fp16.h>
#include <cstdint>

#define NB  2
#define SEQ 1024
#define DIM 1024
#define NH  16
#define DK  64
#define FF  4096
#define NL  4
#define MROWS (NB*SEQ)
#define QKVW 3072

// ---------------- PTX helpers ------------------------------------------------
__device__ __forceinline__ uint32_t smem_to_u32(const void* p) {
    uint32_t a;
    asm("{ .reg .u64 t; cvta.to.shared.u64 t, %1; cvt.u32.u64 %0, t; }" : "=r"(a) : "l"(p));
    return a;
}
__device__ __forceinline__ void cpasync16(uint32_t dst, const void* src) {
    asm volatile("cp.async.cg.shared.global [%0], [%1], 16;"
                 :: "r"(dst), "l"(__cvta_generic_to_global(src)) : "memory");
}
__device__ __forceinline__ void cpcommit() { asm volatile("cp.async.commit_group;" ::: "memory"); }
__device__ __forceinline__ void cpwait0()  { asm volatile("cp.async.wait_group 0;" ::: "memory"); }
__device__ __forceinline__ void cpwait1()  { asm volatile("cp.async.wait_group 1;" ::: "memory"); }
__device__ __forceinline__ void ldsm4(uint32_t& r0, uint32_t& r1, uint32_t& r2, uint32_t& r3, uint32_t a) {
    asm volatile("ldmatrix.sync.aligned.m8n8.x4.shared.b16 {%0,%1,%2,%3}, [%4];"
                 : "=r"(r0), "=r"(r1), "=r"(r2), "=r"(r3) : "r"(a));
}
__device__ __forceinline__ void ldsm2(uint32_t& r0, uint32_t& r1, uint32_t a) {
    asm volatile("ldmatrix.sync.aligned.m8n8.x2.shared.b16 {%0,%1}, [%2];"
                 : "=r"(r0), "=r"(r1) : "r"(a));
}
__device__ __forceinline__ void ldsm4t(uint32_t& r0, uint32_t& r1, uint32_t& r2, uint32_t& r3, uint32_t a) {
    asm volatile("ldmatrix.sync.aligned.m8n8.x4.trans.shared.b16 {%0,%1,%2,%3}, [%4];"
                 : "=r"(r0), "=r"(r1), "=r"(r2), "=r"(r3) : "r"(a));
}
__device__ __forceinline__ void mmaF(float* d, const uint32_t* a, const uint32_t* b) {
    asm volatile("mma.sync.aligned.m16n8k16.row.col.f32.f16.f16.f32 "
                 "{%0,%1,%2,%3}, {%4,%5,%6,%7}, {%8,%9}, {%0,%1,%2,%3};"
                 : "+f"(d[0]), "+f"(d[1]), "+f"(d[2]), "+f"(d[3])
                 : "r"(a[0]), "r"(a[1]), "r"(a[2]), "r"(a[3]), "r"(b[0]), "r"(b[1]));
}
__device__ __forceinline__ uint32_t packh(float a, float b) {
    __half2 h = __floats2half2_rn(a, b);
    return *(uint32_t*)&h;
}

// ---------------- scratch -----------------------------------------------------
__device__ float g_X  [MROWS*DIM];
__device__ float g_X1 [MROWS*DIM];
__device__ float g_Yb [MROWS*DIM];
__device__ __half g_Xhi [MROWS*DIM],  g_Xlo [MROWS*DIM];
__device__ __half g_X1hi[MROWS*DIM],  g_X1lo[MROWS*DIM];
__device__ __half g_Yhi [MROWS*DIM],  g_Ylo [MROWS*DIM];
__device__ __half g_QKVhi[MROWS*QKVW], g_QKVlo[MROWS*QKVW];
__device__ __half g_Ohi [MROWS*DIM],  g_Olo [MROWS*DIM];
__device__ __half g_Hhi [MROWS*FF],   g_Hlo [MROWS*FF];
__device__ __half g_Whi[64u*1024*1024];     // weights: hi only (B-rounded scheme)
__device__ float  g_bQKV1[NL*QKVW], g_bQKV2[NL*QKVW];

#define LAYER_W  (16u*1024*1024)
#define OFF_Q1   (0u)
#define OFF_O1   (3u*1024*1024)
#define OFF_Q2   (4u*1024*1024)
#define OFF_O2   (7u*1024*1024)
#define OFF_W1   (8u*1024*1024)
#define OFF_W2   (12u*1024*1024)

// ---------------- activation split: fp32 -> (hi, lo) f16 ----------------------
__global__ __launch_bounds__(256) void split_f32(const float* __restrict__ x,
        __half* __restrict__ h, __half* __restrict__ l, int n4)
{
    int i = blockIdx.x * 256 + threadIdx.x;
    if (i >= n4) return;
    float4 v = ((const float4*)x)[i];
    __half h0 = __float2half(v.x), h1 = __float2half(v.y);
    __half h2 = __float2half(v.z), h3 = __float2half(v.w);
    uint2 hp, lp;
    hp.x = packh(v.x, v.y); hp.y = packh(v.z, v.w);
    lp.x = packh(v.x - __half2float(h0), v.y - __half2float(h1));
    lp.y = packh(v.z - __half2float(h2), v.w - __half2float(h3));
    ((uint2*)h)[i] = hp;
    ((uint2*)l)[i] = lp;
}

// ------------- merged weight transpose+round (single launch, 10 jobs) ----------
struct WJobs {
    const float* W[10];
    int K[10], N[10];
    unsigned long long stride[10];
    unsigned outOff[10];
    int headMode[10];
    int start[10];
};

__global__ __launch_bounds__(256) void wsplit_all(WJobs jobs, __half* __restrict__ oh)
{
    const int bid = blockIdx.x;
    int j = 0;
#pragma unroll
    for (int q = 1; q < 10; q++) if (bid >= jobs.start[q]) j = q;
    const int K = jobs.K[j], N = jobs.N[j];
    const int headMode = jobs.headMode[j];
    const int local = bid - jobs.start[j];
    const int nbk = K >> 5;
    const int perLayer = nbk * (N >> 5);
    const int z = local / perLayer;
    const int rem = local - z * perLayer;
    const int k0 = (rem % nbk) << 5;
    const int n0 = (rem / nbk) << 5;
    const float* Win = jobs.W[j] + (size_t)z * jobs.stride[j];
    const size_t ob = (size_t)z * LAYER_W + jobs.outOff[j];

    __shared__ float t[32][33];
    const int tx = threadIdx.x & 31, ty = threadIdx.x >> 5;
#pragma unroll
    for (int i = 0; i < 4; i++) {
        int k = k0 + ty + 8*i, n = n0 + tx;
        size_t idx = headMode ? ((size_t)(n >> 6) * K * 64 + (size_t)k * 64 + (n & 63))
                              : ((size_t)k * N + n);
        t[ty + 8*i][tx] = Win[idx];
    }
    __syncthreads();
    const int nl = threadIdx.x >> 3;
    const int kq = threadIdx.x & 7;
    const int n = n0 + nl;
    uint2 hp;
    hp.x = packh(t[kq*4 + 0][nl], t[kq*4 + 1][nl]);
    hp.y = packh(t[kq*4 + 2][nl], t[kq*4 + 3][nl]);
    *(uint2*)(oh + ob + (size_t)n * K + k0 + kq*4) = hp;
}

__global__ __launch_bounds__(256) void pack_bias(const float* __restrict__ bq,
        const float* __restrict__ bk, const float* __restrict__ bv, float* __restrict__ out)
{
    int l = blockIdx.y;
    int i = blockIdx.x * 256 + threadIdx.x;
    out[l*QKVW + i]        = bq[l*1024 + i];
    out[l*QKVW + 1024 + i] = bk[l*1024 + i];
    out[l*QKVW + 2048 + i] = bv[l*1024 + i];
}

// ------- split-A x rounded-B HMMA GEMM: CTA 64x128, 2 terms, 2 CTAs/SM ---------
#define RSB 144
#define SA_LO 9216
#define SB_HI 18432
#define STAGE 36864
#define GEMM_SMEM (2*STAGE)   // 73728

__global__ __launch_bounds__(256, 2) void gemm_tc(
        const __half* __restrict__ Ah, const __half* __restrict__ Al,
        const __half* __restrict__ Bh,
        const float* __restrict__ bias, const float* __restrict__ R,
        float* __restrict__ C,
        __half* __restrict__ Chi, __half* __restrict__ Clo,
        int N, int K, int relu, const int* __restrict__ mskp)
{
    const int m0 = blockIdx.y * 64, n0 = blockIdx.x * 128;
    if (mskp && ((m0 & 1023) >= *mskp) && (n0 >= 1024)) return;  // masked K/V tokens
    extern __shared__ char smem[];
    const uint32_t sb = smem_to_u32(smem);
    const int tid = threadIdx.x, lane = tid & 31, wn = tid >> 5;

    float acc[4][2][4];
#pragma unroll
    for (int i = 0; i < 4; i++)
#pragma unroll
        for (int j = 0; j < 2; j++)
#pragma unroll
            for (int q = 0; q < 4; q++) acc[i][j][q] = 0.f;

    const int nch = K >> 6;
    auto issue = [&](int ch, int stg) {
        const int k0 = ch << 6;
        const uint32_t base = sb + stg * STAGE;
#pragma unroll
        for (int i = tid; i < 2048; i += 256) {
            if (i < 1024) {
                int t = i >> 9, j = i & 511, r = j >> 3, c = j & 7;
                const __half* src = (t ? Al : Ah) + (size_t)(m0 + r) * K + k0 + c * 8;
                cpasync16(base + t * SA_LO + r * RSB + c * 16, src);
            } else {
                int j = i - 1024, r = j >> 3, c = j & 7;
                cpasync16(base + SB_HI + r * RSB + c * 16,
                          Bh + (size_t)(n0 + r) * K + k0 + c * 8);
            }
        }
        cpcommit();
    };
    issue(0, 0);

    for (int ch = 0; ch < nch; ch++) {
        cpwait0();
        __syncthreads();
        if (ch + 1 < nch) issue(ch + 1, (ch + 1) & 1);
        const uint32_t stg = sb + (ch & 1) * STAGE;
#pragma unroll
        for (int ks = 0; ks < 4; ks++) {
            uint32_t ah[4][4], al[4][4], bh[2][2];
#pragma unroll
            for (int mt = 0; mt < 4; mt++) {
                uint32_t ad = stg + (mt*16 + (lane & 15)) * RSB + (lane >> 4) * 16 + ks * 32;
                ldsm4(ah[mt][0], ah[mt][1], ah[mt][2], ah[mt][3], ad);
                ldsm4(al[mt][0], al[mt][1], al[mt][2], al[mt][3], ad + SA_LO);
            }
#pragma unroll
            for (int ng = 0; ng < 2; ng++) {
                uint32_t bd = stg + SB_HI + (wn*16 + ng*8 + (lane & 7)) * RSB
                              + ((lane >> 3) & 1) * 16 + ks * 32;
                ldsm2(bh[ng][0], bh[ng][1], bd);
            }
#pragma unroll
            for (int mt = 0; mt < 4; mt++)
#pragma unroll
                for (int ng = 0; ng < 2; ng++) {
                    mmaF(acc[mt][ng], ah[mt], bh[ng]);
                    mmaF(acc[mt][ng], al[mt], bh[ng]);
                }
        }
    }

    const int g = lane >> 2, qc = (lane & 3) * 2;
#pragma unroll
    for (int mt = 0; mt < 4; mt++) {
        const int row0 = m0 + mt*16 + g;
        const int row1 = row0 + 8;
#pragma unroll
        for (int ng = 0; ng < 2; ng++) {
            const int col = n0 + wn*16 + ng*8 + qc;
            const float b0 = bias[col], b1 = bias[col + 1];
            float v00 = acc[mt][ng][0] + b0, v01 = acc[mt][ng][1] + b1;
            float v10 = acc[mt][ng][2] + b0, v11 = acc[mt][ng][3] + b1;
            if (R) {
                float2 r0 = *(const float2*)&R[(size_t)row0 * N + col];
                float2 r1 = *(const float2*)&R[(size_t)row1 * N + col];
                v00 += r0.x; v01 += r0.y; v10 += r1.x; v11 += r1.y;
            }
            if (relu) {
                v00 = fmaxf(v00, 0.f); v01 = fmaxf(v01, 0.f);
                v10 = fmaxf(v10, 0.f); v11 = fmaxf(v11, 0.f);
            }
            if (Chi) {
                float h00 = __half2float(__float2half(v00));
                float h01 = __half2float(__float2half(v01));
                float h10 = __half2float(__float2half(v10));
                float h11 = __half2float(__float2half(v11));
                *(uint32_t*)&Chi[(size_t)row0 * N + col] = packh(v00, v01);
                *(uint32_t*)&Chi[(size_t)row1 * N + col] = packh(v10, v11);
                *(uint32_t*)&Clo[(size_t)row0 * N + col] = packh(v00-h00, v01-h01);
                *(uint32_t*)&Clo[(size_t)row1 * N + col] = packh(v10-h10, v11-h11);
            } else {
                *(float2*)&C[(size_t)row0 * N + col] = make_float2(v00, v01);
                *(float2*)&C[(size_t)row1 * N + col] = make_float2(v10, v11);
            }
        }
    }
}

// ------- HMMA flash attention: split Q/P, rounded K/V (2-term), f32-acc --------
#define ARS 144
#define AQ_LO 18432
#define AKV0  36864
#define AKV_STAGE 18432          // Khi 9216 + Vhi 9216
#define ATT_SMEM (AKV0 + 2*AKV_STAGE)   // 73728

__global__ __launch_bounds__(256, 2) void attn_tc(
        const __half* __restrict__ QKVh, const __half* __restrict__ QKVl,
        __half* __restrict__ Ohi, __half* __restrict__ Olo,
        const int* __restrict__ mask_ptr)
{
    extern __shared__ char smem[];
    const uint32_t sb = smem_to_u32(smem);
    const int tid = threadIdx.x, lane = tid & 31, w = tid >> 5;
    const int q0 = blockIdx.x * 128, h = blockIdx.y, b = blockIdx.z;
    const int lim = mask_ptr ? *mask_ptr : SEQ;
    const size_t tokbase = (size_t)b * SEQ;
    const int cq = h * DK, ck = 1024 + h * DK, cv = 2048 + h * DK;

    for (int i = tid; i < 1024; i += 256) {
        int r = i >> 3, c = i & 7;
        uint32_t qd = sb + r * ARS + c * 16;
        size_t gi = (tokbase + q0 + r) * QKVW + cq + c * 8;
        cpasync16(qd, QKVh + gi);
        cpasync16(qd + AQ_LO, QKVl + gi);
    }
    auto ldkv = [&](int t, int stg) {
        uint32_t base = sb + AKV0 + stg * AKV_STAGE;
        for (int i = tid; i < 512; i += 256) {
            int r = i >> 3, c = i & 7;
            uint32_t off = r * ARS + c * 16;
            size_t row = (tokbase + t * 64 + r) * QKVW;
            cpasync16(base + off,        QKVh + row + ck + c * 8);
            cpasync16(base + 9216 + off, QKVh + row + cv + c * 8);
        }
        cpcommit();
    };
    ldkv(0, 0);

    const int nt = (lim + 63) >> 6;
    const int g = lane >> 2, qc = (lane & 3) * 2;
    const int wq = w * 16;

    float m[2] = {-1e30f, -1e30f}, l[2] = {0.f, 0.f};
    float o[8][4];
#pragma unroll
    for (int i = 0; i < 8; i++)
#pragma unroll
        for (int j = 0; j < 4; j++) o[i][j] = 0.f;

    for (int t = 0; t < nt; t++) {
        __syncthreads();
        if (t + 1 < nt) { ldkv(t + 1, (t + 1) & 1); cpwait1(); }
        else           { cpwait0(); }
        __syncthreads();
        const uint32_t kb = sb + AKV0 + (t & 1) * AKV_STAGE;

        float sc[8][4];
#pragma unroll
        for (int i = 0; i < 8; i++)
#pragma unroll
            for (int j = 0; j < 4; j++) sc[i][j] = 0.f;

#pragma unroll
        for (int ks = 0; ks < 4; ks++) {
            uint32_t qa = sb + (wq + (lane & 15)) * ARS + (lane >> 4) * 16 + ks * 32;
            uint32_t qh[4], ql[4];
            ldsm4(qh[0], qh[1], qh[2], qh[3], qa);
            ldsm4(ql[0], ql[1], ql[2], ql[3], qa + AQ_LO);
#pragma unroll
            for (int p = 0; p < 4; p++) {
                uint32_t ka = kb + (p*16 + (lane & 7) + ((lane >> 4) & 1) * 8) * ARS
                              + ((lane >> 3) & 1) * 16 + ks * 32;
                uint32_t kh[4];
                ldsm4(kh[0], kh[1], kh[2], kh[3], ka);
                const uint32_t kh01[2] = {kh[0], kh[1]}, kh23[2] = {kh[2], kh[3]};
                mmaF(sc[2*p],   qh, kh01);
                mmaF(sc[2*p],   ql, kh01);
                mmaF(sc[2*p+1], qh, kh23);
                mmaF(sc[2*p+1], ql, kh23);
            }
        }

        const int t0 = t * 64;
#pragma unroll
        for (int na = 0; na < 8; na++) {
            int c0 = t0 + na*8 + qc, c1 = c0 + 1;
#pragma unroll
            for (int j = 0; j < 2; j++) {
                float s0 = sc[na][2*j]   * 0.125f;
                float s1 = sc[na][2*j+1] * 0.125f;
                sc[na][2*j]   = (c0 < lim) ? s0 : -1e30f;
                sc[na][2*j+1] = (c1 < lim) ? s1 : -1e30f;
            }
        }

#pragma unroll
        for (int j = 0; j < 2; j++) {
            float mx = -1e30f;
#pragma unroll
            for (int na = 0; na < 8; na++)
                mx = fmaxf(mx, fmaxf(sc[na][2*j], sc[na][2*j+1]));
            mx = fmaxf(mx, __shfl_xor_sync(0xffffffffu, mx, 1));
            mx = fmaxf(mx, __shfl_xor_sync(0xffffffffu, mx, 2));
            float mnew = fmaxf(m[j], mx);
            float corr = __expf(m[j] - mnew);
            l[j] *= corr;
            m[j] = mnew;
#pragma unroll
            for (int nd = 0; nd < 8; nd++) { o[nd][2*j] *= corr; o[nd][2*j+1] *= corr; }
            float sum = 0.f;
#pragma unroll
            for (int na = 0; na < 8; na++) {
                float p0 = __expf(sc[na][2*j]   - mnew);
                float p1 = __expf(sc[na][2*j+1] - mnew);
                sc[na][2*j] = p0; sc[na][2*j+1] = p1;
                sum += p0 + p1;
            }
            sum += __shfl_xor_sync(0xffffffffu, sum, 1);
            sum += __shfl_xor_sync(0xffffffffu, sum, 2);
            l[j] += sum;
        }

#pragma unroll
        for (int kp = 0; kp < 4; kp++) {
            float p00 = sc[2*kp][0],   p01 = sc[2*kp][1];
            float p02 = sc[2*kp][2],   p03 = sc[2*kp][3];
            float p10 = sc[2*kp+1][0], p11 = sc[2*kp+1][1];
            float p12 = sc[2*kp+1][2], p13 = sc[2*kp+1][3];
            float h00 = __half2float(__float2half(p00));
            float h01 = __half2float(__float2half(p01));
            float h02 = __half2float(__float2half(p02));
            float h03 = __half2float(__float2half(p03));
            float h10 = __half2float(__float2half(p10));
            float h11 = __half2float(__float2half(p11));
            float h12 = __half2float(__float2half(p12));
            float h13 = __half2float(__float2half(p13));
            uint32_t aph[4] = { packh(p00, p01), packh(p02, p03),
                                packh(p10, p11), packh(p12, p13) };
            uint32_t apl[4] = { packh(p00-h00, p01-h01), packh(p02-h02, p03-h03),
                                packh(p10-h10, p11-h11), packh(p12-h12, p13-h13) };
#pragma unroll
            for (int vp = 0; vp < 4; vp++) {
                uint32_t va = kb + 9216 + (kp*16 + (lane & 15)) * ARS
                              + (vp*2 + (lane >> 4)) * 16;
                uint32_t vh[4];
                ldsm4t(vh[0], vh[1], vh[2], vh[3], va);
                const uint32_t vh01[2] = {vh[0], vh[1]}, vh23[2] = {vh[2], vh[3]};
                mmaF(o[2*vp],   aph, vh01);
                mmaF(o[2*vp],   apl, vh01);
                mmaF(o[2*vp+1], aph, vh23);
                mmaF(o[2*vp+1], apl, vh23);
            }
        }
    }

#pragma unroll
    for (int j = 0; j < 2; j++) {
        float inv = 1.f / l[j];
        int row = q0 + wq + g + j*8;
        size_t gb = (tokbase + row) * DIM + h * DK;
#pragma unroll
        for (int nd = 0; nd < 8; nd++) {
            float v0 = o[nd][2*j] * inv, v1 = o[nd][2*j+1] * inv;
            float h0 = __half2float(__float2half(v0));
            float h1 = __half2float(__float2half(v1));
            *(uint32_t*)&Ohi[gb + nd*8 + qc] = packh(v0, v1);
            *(uint32_t*)&Olo[gb + nd*8 + qc] = packh(v0-h0, v1-h1);
        }
    }
}

// ---------------- BatchNorm1d + fused f16 split --------------------------------
__global__ __launch_bounds__(256)
void bn_q(float* __restrict__ X, const float* __restrict__ g, const float* __restrict__ be,
          __half* __restrict__ Xh, __half* __restrict__ Xl)
{
    const int s = blockIdx.x, tid = threadIdx.x;
    const int lane = tid & 31, w = tid >> 5;
    const size_t r0 = (size_t)s * DIM, r1 = (size_t)(SEQ + s) * DIM;
    float4 v0 = ((const float4*)(X + r0))[tid];
    float4 v1 = ((const float4*)(X + r1))[tid];
    float sum = v0.x+v0.y+v0.z+v0.w + v1.x+v1.y+v1.z+v1.w;
    float sq  = v0.x*v0.x+v0.y*v0.y+v0.z*v0.z+v0.w*v0.w
              + v1.x*v1.x+v1.y*v1.y+v1.z*v1.z+v1.w*v1.w;
#pragma unroll
    for (int off = 16; off; off >>= 1) {
        sum += __shfl_xor_sync(0xffffffffu, sum, off);
        sq  += __shfl_xor_sync(0xffffffffu, sq,  off);
    }
    __shared__ float s1[8], s2[8];
    if (lane == 0) { s1[w] = sum; s2[w] = sq; }
    __syncthreads();
    sum = 0.f; sq = 0.f;
#pragma unroll
    for (int k = 0; k < 8; k++) { sum += s1[k]; sq += s2[k]; }
    const float mean = sum * (1.f/2048.f);
    const float var  = sq  * (1.f/2048.f) - mean*mean;
    const float scl  = g[s] * rsqrtf(var + 1e-5f);
    const float sh   = be[s] - mean * scl;
    v0.x = v0.x*scl + sh; v0.y = v0.y*scl + sh; v0.z = v0.z*scl + sh; v0.w = v0.w*scl + sh;
    v1.x = v1.x*scl + sh; v1.y = v1.y*scl + sh; v1.z = v1.z*scl + sh; v1.w = v1.w*scl + sh;
    ((float4*)(X + r0))[tid] = v0;
    ((float4*)(X + r1))[tid] = v1;
    float h0 = __half2float(__float2half(v0.x)), h1 = __half2float(__float2half(v0.y));
    float h2 = __half2float(__float2half(v0.z)), h3 = __half2float(__float2half(v0.w));
    uint2 hp, lp;
    hp.x = packh(v0.x, v0.y); hp.y = packh(v0.z, v0.w);
    lp.x = packh(v0.x-h0, v0.y-h1); lp.y = packh(v0.z-h2, v0.w-h3);
    ((uint2*)(Xh + r0))[tid] = hp;
    ((uint2*)(Xl + r0))[tid] = lp;
    h0 = __half2float(__float2half(v1.x)); h1 = __half2float(__float2half(v1.y));
    h2 = __half2float(__float2half(v1.z)); h3 = __half2float(__float2half(v1.w));
    hp.x = packh(v1.x, v1.y); hp.y = packh(v1.z, v1.w);
    lp.x = packh(v1.x-h0, v1.y-h1); lp.y = packh(v1.z-h2, v1.w-h3);
    ((uint2*)(Xh + r1))[tid] = hp;
    ((uint2*)(Xl + r1))[tid] = lp;
}

// ---------------- host orchestration -------------------------------------------
extern "C" void kernel_launch(void* const* d_in, const int* in_sizes, int n_in,
                              void* d_out, int out_size)
{
    const float* x   = (const float*)d_in[0];
    const float* Wq1 = (const float*)d_in[1];  const float* bq1 = (const float*)d_in[2];
    const float* Wk1 = (const float*)d_in[3];  const float* bk1 = (const float*)d_in[4];
    const float* Wv1 = (const float*)d_in[5];  const float* bv1 = (const float*)d_in[6];
    const float* Wo1 = (const float*)d_in[7];  const float* bo1 = (const float*)d_in[8];
    const float* Wq2 = (const float*)d_in[9];  const float* bq2 = (const float*)d_in[10];
    const float* Wk2 = (const float*)d_in[11]; const float* bk2 = (const float*)d_in[12];
    const float* Wv2 = (const float*)d_in[13]; const float* bv2 = (const float*)d_in[14];
    const float* Wo2 = (const float*)d_in[15]; const float* bo2 = (const float*)d_in[16];
    const float* g1  = (const float*)d_in[17]; const float* be1 = (const float*)d_in[18];
    const float* g2  = (const float*)d_in[19]; const float* be2 = (const float*)d_in[20];
    const float* g3  = (const float*)d_in[21]; const float* be3 = (const float*)d_in[22];
    const float* W1  = (const float*)d_in[23]; const float* bf1 = (const float*)d_in[24];
    const float* W2  = (const float*)d_in[25]; const float* bf2 = (const float*)d_in[26];
    const int*   msk = (const int*)d_in[27];

    float *X, *X1, *Y, *bQ1, *bQ2;
    __half *Whi, *Xhi, *Xlo, *X1hi, *X1lo, *Yhi, *Ylo;
    __half *QKVhi, *QKVlo, *Ohi, *Olo, *Hhi, *Hlo;
    cudaGetSymbolAddress((void**)&X, g_X);       cudaGetSymbolAddress((void**)&X1, g_X1);
    cudaGetSymbolAddress((void**)&Y, g_Yb);
    cudaGetSymbolAddress((void**)&Whi, g_Whi);
    cudaGetSymbolAddress((void**)&Xhi, g_Xhi);   cudaGetSymbolAddress((void**)&Xlo, g_Xlo);
    cudaGetSymbolAddress((void**)&X1hi, g_X1hi); cudaGetSymbolAddress((void**)&X1lo, g_X1lo);
    cudaGetSymbolAddress((void**)&Yhi, g_Yhi);   cudaGetSymbolAddress((void**)&Ylo, g_Ylo);
    cudaGetSymbolAddress((void**)&QKVhi, g_QKVhi); cudaGetSymbolAddress((void**)&QKVlo, g_QKVlo);
    cudaGetSymbolAddress((void**)&Ohi, g_Ohi);   cudaGetSymbolAddress((void**)&Olo, g_Olo);
    cudaGetSymbolAddress((void**)&Hhi, g_Hhi);   cudaGetSymbolAddress((void**)&Hlo, g_Hlo);
    cudaGetSymbolAddress((void**)&bQ1, g_bQKV1); cudaGetSymbolAddress((void**)&bQ2, g_bQKV2);

    cudaFuncSetAttribute(gemm_tc, cudaFuncAttributeMaxDynamicSharedMemorySize, GEMM_SMEM);
    cudaFuncSetAttribute(attn_tc, cudaFuncAttributeMaxDynamicSharedMemorySize, ATT_SMEM);

    const size_t bytesD = (size_t)MROWS * DIM * sizeof(float);
    cudaMemcpyAsync(X, x, bytesD, cudaMemcpyDeviceToDevice);

    // ---- merged weight prep (1 launch) + bias concat ----
    {
        const size_t sQ = (size_t)NH * DIM * DK;
        const size_t sO = (size_t)DIM * DIM;
        WJobs jobs;
        const float* Ws[10]  = {Wq1, Wk1, Wv1, Wo1, Wq2, Wk2, Wv2, Wo2, W1, W2};
        const int Ks[10]     = {1024,1024,1024,1024,1024,1024,1024,1024,1024,4096};
        const int Ns[10]     = {1024,1024,1024,1024,1024,1024,1024,1024,4096,1024};
        const unsigned long long st[10] = {sQ,sQ,sQ,sO,sQ,sQ,sQ,sO,(size_t)DIM*FF,(size_t)FF*DIM};
        const unsigned off[10] = {OFF_Q1, OFF_Q1+(1u<<20), OFF_Q1+(2u<<20), OFF_O1,
                                  OFF_Q2, OFF_Q2+(1u<<20), OFF_Q2+(2u<<20), OFF_O2,
                                  OFF_W1, OFF_W2};
        const int hm[10] = {1,1,1,0,1,1,1,0,0,0};
        int cum = 0;
        for (int j = 0; j < 10; j++) {
            jobs.W[j] = Ws[j]; jobs.K[j] = Ks[j]; jobs.N[j] = Ns[j];
            jobs.stride[j] = st[j]; jobs.outOff[j] = off[j]; jobs.headMode[j] = hm[j];
            jobs.start[j] = cum;
            cum += (Ks[j] >> 5) * (Ns[j] >> 5) * NL;
        }
        wsplit_all<<<cum, 256>>>(jobs, Whi);
        pack_bias<<<dim3(4, NL), 256>>>(bq1, bk1, bv1, bQ1);
        pack_bias<<<dim3(4, NL), 256>>>(bq2, bk2, bv2, bQ2);
    }

    const int n4D = MROWS * DIM / 4;
    split_f32<<<n4D/256, 256>>>(X, Xhi, Xlo, n4D);

    dim3 gQKV(QKVW/128, MROWS/64);   // (24,32)
    dim3 gGD(DIM/128,  MROWS/64);    // (8,32)
    dim3 gGF(FF/128,   MROWS/64);    // (32,32)
    dim3 gA(SEQ/128, NH, NB);        // (8,16,2)

    for (int l = 0; l < NL; l++) {
        const __half* WH = Whi + (size_t)l * LAYER_W;
        const size_t dO = (size_t)l * DIM, f1O = (size_t)l * FF;

        // masked self-attention (fused QKV; masked K/V tiles skipped)
        gemm_tc<<<gQKV, 256, GEMM_SMEM>>>(Xhi, Xlo, WH+OFF_Q1, bQ1 + l*QKVW,
                nullptr, nullptr, QKVhi, QKVlo, QKVW, DIM, 0, msk);
        attn_tc<<<gA, 256, ATT_SMEM>>>(QKVhi, QKVlo, Ohi, Olo, msk);
        gemm_tc<<<gGD, 256, GEMM_SMEM>>>(Ohi, Olo, WH+OFF_O1, bo1+dO,
                X, X1, nullptr, nullptr, DIM, DIM, 0, nullptr);
        bn_q<<<SEQ, 256>>>(X1, g1+dO, be1+dO, X1hi, X1lo);

        // second (unmasked) attention; residual from block input X
        gemm_tc<<<gQKV, 256, GEMM_SMEM>>>(X1hi, X1lo, WH+OFF_Q2, bQ2 + l*QKVW,
                nullptr, nullptr, QKVhi, QKVlo, QKVW, DIM, 0, nullptr);
        attn_tc<<<gA, 256, ATT_SMEM>>>(QKVhi, QKVlo, Ohi, Olo, nullptr);
        gemm_tc<<<gGD, 256, GEMM_SMEM>>>(Ohi, Olo, WH+OFF_O2, bo2+dO,
                X, Y, nullptr, nullptr, DIM, DIM, 0, nullptr);
        bn_q<<<SEQ, 256>>>(Y, g2+dO, be2+dO, Yhi, Ylo);

        // FFN; residual from X1
        gemm_tc<<<gGF, 256, GEMM_SMEM>>>(Yhi, Ylo, WH+OFF_W1, bf1+f1O,
                nullptr, nullptr, Hhi, Hlo, FF, DIM, 1, nullptr);
        gemm_tc<<<gGD, 256, GEMM_SMEM>>>(Hhi, Hlo, WH+OFF_W2, bf2+dO,
                X1, X, nullptr, nullptr, DIM, FF, 0, nullptr);
        bn_q<<<SEQ, 256>>>(X, g3+dO, be3+dO, Xhi, Xlo);
    }

    cudaMemcpyAsync(d_out, X, bytesD, cudaMemcpyDeviceToDevice);
}

// round 13
// speedup vs baseline: 4.5684x; 1.5038x over previous
#include <cuda_runtime.h>
#include <cuda_fp16.h>
#include <cstdint>

#define NB  2
#define SEQ 1024
#define DIM 1024
#define NH  16
#define DK  64
#define FF  4096
#define NL  4
#define MROWS (NB*SEQ)
#define QKVW 3072

// ---------------- PTX helpers ------------------------------------------------
__device__ __forceinline__ uint32_t smem_to_u32(const void* p) {
    uint32_t a;
    asm("{ .reg .u64 t; cvta.to.shared.u64 t, %1; cvt.u32.u64 %0, t; }" : "=r"(a) : "l"(p));
    return a;
}
__device__ __forceinline__ void cpasync16(uint32_t dst, const void* src) {
    asm volatile("cp.async.cg.shared.global [%0], [%1], 16;"
                 :: "r"(dst), "l"(__cvta_generic_to_global(src)) : "memory");
}
__device__ __forceinline__ void cpcommit() { asm volatile("cp.async.commit_group;" ::: "memory"); }
__device__ __forceinline__ void cpwait0()  { asm volatile("cp.async.wait_group 0;" ::: "memory"); }
__device__ __forceinline__ void cpwait1()  { asm volatile("cp.async.wait_group 1;" ::: "memory"); }
__device__ __forceinline__ void ldsm4(uint32_t& r0, uint32_t& r1, uint32_t& r2, uint32_t& r3, uint32_t a) {
    asm volatile("ldmatrix.sync.aligned.m8n8.x4.shared.b16 {%0,%1,%2,%3}, [%4];"
                 : "=r"(r0), "=r"(r1), "=r"(r2), "=r"(r3) : "r"(a));
}
__device__ __forceinline__ void ldsm2(uint32_t& r0, uint32_t& r1, uint32_t a) {
    asm volatile("ldmatrix.sync.aligned.m8n8.x2.shared.b16 {%0,%1}, [%2];"
                 : "=r"(r0), "=r"(r1) : "r"(a));
}
__device__ __forceinline__ void ldsm4t(uint32_t& r0, uint32_t& r1, uint32_t& r2, uint32_t& r3, uint32_t a) {
    asm volatile("ldmatrix.sync.aligned.m8n8.x4.trans.shared.b16 {%0,%1,%2,%3}, [%4];"
                 : "=r"(r0), "=r"(r1), "=r"(r2), "=r"(r3) : "r"(a));
}
__device__ __forceinline__ void mmaF(float* d, const uint32_t* a, const uint32_t* b) {
    asm volatile("mma.sync.aligned.m16n8k16.row.col.f32.f16.f16.f32 "
                 "{%0,%1,%2,%3}, {%4,%5,%6,%7}, {%8,%9}, {%0,%1,%2,%3};"
                 : "+f"(d[0]), "+f"(d[1]), "+f"(d[2]), "+f"(d[3])
                 : "r"(a[0]), "r"(a[1]), "r"(a[2]), "r"(a[3]), "r"(b[0]), "r"(b[1]));
}
__device__ __forceinline__ uint32_t packh(float a, float b) {
    __half2 h = __floats2half2_rn(a, b);
    return *(uint32_t*)&h;
}

// ---------------- scratch -----------------------------------------------------
__device__ float g_X  [MROWS*DIM];
__device__ float g_X1 [MROWS*DIM];
__device__ float g_Yb [MROWS*DIM];
__device__ __half g_Xhi [MROWS*DIM];
__device__ __half g_X1hi[MROWS*DIM];
__device__ __half g_Yhi [MROWS*DIM];
__device__ __half g_QKVhi[MROWS*QKVW];
__device__ __half g_Ohi [MROWS*DIM];
__device__ __half g_Hhi [MROWS*FF];
__device__ __half g_Whi[64u*1024*1024];
__device__ float  g_bQKV1[NL*QKVW], g_bQKV2[NL*QKVW];

#define LAYER_W  (16u*1024*1024)
#define OFF_Q1   (0u)
#define OFF_O1   (3u*1024*1024)
#define OFF_Q2   (4u*1024*1024)
#define OFF_O2   (7u*1024*1024)
#define OFF_W1   (8u*1024*1024)
#define OFF_W2   (12u*1024*1024)

// ---------------- activation round: fp32 -> f16 --------------------------------
__global__ __launch_bounds__(256) void round_f32(const float* __restrict__ x,
        __half* __restrict__ h, int n4)
{
    int i = blockIdx.x * 256 + threadIdx.x;
    if (i >= n4) return;
    float4 v = ((const float4*)x)[i];
    uint2 hp;
    hp.x = packh(v.x, v.y); hp.y = packh(v.z, v.w);
    ((uint2*)h)[i] = hp;
}

// ------------- merged weight transpose+round (single launch, 10 jobs) ----------
struct WJobs {
    const float* W[10];
    int K[10], N[10];
    unsigned long long stride[10];
    unsigned outOff[10];
    int headMode[10];
    int start[10];
};

__global__ __launch_bounds__(256) void wsplit_all(WJobs jobs, __half* __restrict__ oh)
{
    const int bid = blockIdx.x;
    int j = 0;
#pragma unroll
    for (int q = 1; q < 10; q++) if (bid >= jobs.start[q]) j = q;
    const int K = jobs.K[j], N = jobs.N[j];
    const int headMode = jobs.headMode[j];
    const int local = bid - jobs.start[j];
    const int nbk = K >> 5;
    const int perLayer = nbk * (N >> 5);
    const int z = local / perLayer;
    const int rem = local - z * perLayer;
    const int k0 = (rem % nbk) << 5;
    const int n0 = (rem / nbk) << 5;
    const float* Win = jobs.W[j] + (size_t)z * jobs.stride[j];
    const size_t ob = (size_t)z * LAYER_W + jobs.outOff[j];

    __shared__ float t[32][33];
    const int tx = threadIdx.x & 31, ty = threadIdx.x >> 5;
#pragma unroll
    for (int i = 0; i < 4; i++) {
        int k = k0 + ty + 8*i, n = n0 + tx;
        size_t idx = headMode ? ((size_t)(n >> 6) * K * 64 + (size_t)k * 64 + (n & 63))
                              : ((size_t)k * N + n);
        t[ty + 8*i][tx] = Win[idx];
    }
    __syncthreads();
    const int nl = threadIdx.x >> 3;
    const int kq = threadIdx.x & 7;
    const int n = n0 + nl;
    uint2 hp;
    hp.x = packh(t[kq*4 + 0][nl], t[kq*4 + 1][nl]);
    hp.y = packh(t[kq*4 + 2][nl], t[kq*4 + 3][nl]);
    *(uint2*)(oh + ob + (size_t)n * K + k0 + kq*4) = hp;
}

__global__ __launch_bounds__(256) void pack_bias(const float* __restrict__ bq,
        const float* __restrict__ bk, const float* __restrict__ bv, float* __restrict__ out)
{
    int l = blockIdx.y;
    int i = blockIdx.x * 256 + threadIdx.x;
    out[l*QKVW + i]        = bq[l*1024 + i];
    out[l*QKVW + 1024 + i] = bk[l*1024 + i];
    out[l*QKVW + 2048 + i] = bv[l*1024 + i];
}

// ----------- pure-f16 HMMA GEMM (f32 acc): CTA 64x128, 2 CTAs/SM ---------------
#define RSB 144
#define SB_HI 9216
#define STAGE 27648
#define GEMM_SMEM (2*STAGE)   // 55296

__global__ __launch_bounds__(256, 2) void gemm_tc(
        const __half* __restrict__ Ah,
        const __half* __restrict__ Bh,
        const float* __restrict__ bias, const float* __restrict__ R,
        float* __restrict__ C,
        __half* __restrict__ Chi,
        int N, int K, int relu, const int* __restrict__ mskp)
{
    const int m0 = blockIdx.y * 64, n0 = blockIdx.x * 128;
    if (mskp && ((m0 & 1023) >= *mskp) && (n0 >= 1024)) return;  // masked K/V tokens
    extern __shared__ char smem[];
    const uint32_t sb = smem_to_u32(smem);
    const int tid = threadIdx.x, lane = tid & 31, wn = tid >> 5;

    float acc[4][2][4];
#pragma unroll
    for (int i = 0; i < 4; i++)
#pragma unroll
        for (int j = 0; j < 2; j++)
#pragma unroll
            for (int q = 0; q < 4; q++) acc[i][j][q] = 0.f;

    const int nch = K >> 6;
    auto issue = [&](int ch, int stg) {
        const int k0 = ch << 6;
        const uint32_t base = sb + stg * STAGE;
#pragma unroll
        for (int i = tid; i < 1536; i += 256) {
            if (i < 512) {                        // A: 64 rows x 8 vecs
                int r = i >> 3, c = i & 7;
                cpasync16(base + r * RSB + c * 16,
                          Ah + (size_t)(m0 + r) * K + k0 + c * 8);
            } else {                              // B: 128 rows x 8 vecs
                int j = i - 512, r = j >> 3, c = j & 7;
                cpasync16(base + SB_HI + r * RSB + c * 16,
                          Bh + (size_t)(n0 + r) * K + k0 + c * 8);
            }
        }
        cpcommit();
    };
    issue(0, 0);

    for (int ch = 0; ch < nch; ch++) {
        cpwait0();
        __syncthreads();
        if (ch + 1 < nch) issue(ch + 1, (ch + 1) & 1);
        const uint32_t stg = sb + (ch & 1) * STAGE;
#pragma unroll
        for (int ks = 0; ks < 4; ks++) {
            uint32_t ah[4][4], bh[2][2];
#pragma unroll
            for (int mt = 0; mt < 4; mt++) {
                uint32_t ad = stg + (mt*16 + (lane & 15)) * RSB + (lane >> 4) * 16 + ks * 32;
                ldsm4(ah[mt][0], ah[mt][1], ah[mt][2], ah[mt][3], ad);
            }
#pragma unroll
            for (int ng = 0; ng < 2; ng++) {
                uint32_t bd = stg + SB_HI + (wn*16 + ng*8 + (lane & 7)) * RSB
                              + ((lane >> 3) & 1) * 16 + ks * 32;
                ldsm2(bh[ng][0], bh[ng][1], bd);
            }
#pragma unroll
            for (int mt = 0; mt < 4; mt++)
#pragma unroll
                for (int ng = 0; ng < 2; ng++)
                    mmaF(acc[mt][ng], ah[mt], bh[ng]);
        }
    }

    const int g = lane >> 2, qc = (lane & 3) * 2;
#pragma unroll
    for (int mt = 0; mt < 4; mt++) {
        const int row0 = m0 + mt*16 + g;
        const int row1 = row0 + 8;
#pragma unroll
        for (int ng = 0; ng < 2; ng++) {
            const int col = n0 + wn*16 + ng*8 + qc;
            const float b0 = bias[col], b1 = bias[col + 1];
            float v00 = acc[mt][ng][0] + b0, v01 = acc[mt][ng][1] + b1;
            float v10 = acc[mt][ng][2] + b0, v11 = acc[mt][ng][3] + b1;
            if (R) {
                float2 r0 = *(const float2*)&R[(size_t)row0 * N + col];
                float2 r1 = *(const float2*)&R[(size_t)row1 * N + col];
                v00 += r0.x; v01 += r0.y; v10 += r1.x; v11 += r1.y;
            }
            if (relu) {
                v00 = fmaxf(v00, 0.f); v01 = fmaxf(v01, 0.f);
                v10 = fmaxf(v10, 0.f); v11 = fmaxf(v11, 0.f);
            }
            if (Chi) {
                *(uint32_t*)&Chi[(size_t)row0 * N + col] = packh(v00, v01);
                *(uint32_t*)&Chi[(size_t)row1 * N + col] = packh(v10, v11);
            } else {
                *(float2*)&C[(size_t)row0 * N + col] = make_float2(v00, v01);
                *(float2*)&C[(size_t)row1 * N + col] = make_float2(v10, v11);
            }
        }
    }
}

// ----------- HMMA flash attention: pure f16 inputs, f32 acc --------------------
#define ARS 144
#define AKV0  18432
#define AKV_STAGE 18432          // Khi 9216 + Vhi 9216
#define ATT_SMEM (AKV0 + 2*AKV_STAGE)   // 55296

__global__ __launch_bounds__(256, 2) void attn_tc(
        const __half* __restrict__ QKVh,
        __half* __restrict__ Ohi,
        const int* __restrict__ mask_ptr)
{
    extern __shared__ char smem[];
    const uint32_t sb = smem_to_u32(smem);
    const int tid = threadIdx.x, lane = tid & 31, w = tid >> 5;
    const int q0 = blockIdx.x * 128, h = blockIdx.y, b = blockIdx.z;
    const int lim = mask_ptr ? *mask_ptr : SEQ;
    const size_t tokbase = (size_t)b * SEQ;
    const int cq = h * DK, ck = 1024 + h * DK, cv = 2048 + h * DK;

    for (int i = tid; i < 1024; i += 256) {
        int r = i >> 3, c = i & 7;
        cpasync16(sb + r * ARS + c * 16,
                  QKVh + (tokbase + q0 + r) * QKVW + cq + c * 8);
    }
    auto ldkv = [&](int t, int stg) {
        uint32_t base = sb + AKV0 + stg * AKV_STAGE;
        for (int i = tid; i < 512; i += 256) {
            int r = i >> 3, c = i & 7;
            uint32_t off = r * ARS + c * 16;
            size_t row = (tokbase + t * 64 + r) * QKVW;
            cpasync16(base + off,        QKVh + row + ck + c * 8);
            cpasync16(base + 9216 + off, QKVh + row + cv + c * 8);
        }
        cpcommit();
    };
    ldkv(0, 0);

    const int nt = (lim + 63) >> 6;
    const int g = lane >> 2, qc = (lane & 3) * 2;
    const int wq = w * 16;

    float m[2] = {-1e30f, -1e30f}, l[2] = {0.f, 0.f};
    float o[8][4];
#pragma unroll
    for (int i = 0; i < 8; i++)
#pragma unroll
        for (int j = 0; j < 4; j++) o[i][j] = 0.f;

    for (int t = 0; t < nt; t++) {
        __syncthreads();
        if (t + 1 < nt) { ldkv(t + 1, (t + 1) & 1); cpwait1(); }
        else           { cpwait0(); }
        __syncthreads();
        const uint32_t kb = sb + AKV0 + (t & 1) * AKV_STAGE;

        float sc[8][4];
#pragma unroll
        for (int i = 0; i < 8; i++)
#pragma unroll
            for (int j = 0; j < 4; j++) sc[i][j] = 0.f;

#pragma unroll
        for (int ks = 0; ks < 4; ks++) {
            uint32_t qa = sb + (wq + (lane & 15)) * ARS + (lane >> 4) * 16 + ks * 32;
            uint32_t qh[4];
            ldsm4(qh[0], qh[1], qh[2], qh[3], qa);
#pragma unroll
            for (int p = 0; p < 4; p++) {
                uint32_t ka = kb + (p*16 + (lane & 7) + ((lane >> 4) & 1) * 8) * ARS
                              + ((lane >> 3) & 1) * 16 + ks * 32;
                uint32_t kh[4];
                ldsm4(kh[0], kh[1], kh[2], kh[3], ka);
                const uint32_t kh01[2] = {kh[0], kh[1]}, kh23[2] = {kh[2], kh[3]};
                mmaF(sc[2*p],   qh, kh01);
                mmaF(sc[2*p+1], qh, kh23);
            }
        }

        const int t0 = t * 64;
#pragma unroll
        for (int na = 0; na < 8; na++) {
            int c0 = t0 + na*8 + qc, c1 = c0 + 1;
#pragma unroll
            for (int j = 0; j < 2; j++) {
                float s0 = sc[na][2*j]   * 0.125f;
                float s1 = sc[na][2*j+1] * 0.125f;
                sc[na][2*j]   = (c0 < lim) ? s0 : -1e30f;
                sc[na][2*j+1] = (c1 < lim) ? s1 : -1e30f;
            }
        }

#pragma unroll
        for (int j = 0; j < 2; j++) {
            float mx = -1e30f;
#pragma unroll
            for (int na = 0; na < 8; na++)
                mx = fmaxf(mx, fmaxf(sc[na][2*j], sc[na][2*j+1]));
            mx = fmaxf(mx, __shfl_xor_sync(0xffffffffu, mx, 1));
            mx = fmaxf(mx, __shfl_xor_sync(0xffffffffu, mx, 2));
            float mnew = fmaxf(m[j], mx);
            float corr = __expf(m[j] - mnew);
            l[j] *= corr;
            m[j] = mnew;
#pragma unroll
            for (int nd = 0; nd < 8; nd++) { o[nd][2*j] *= corr; o[nd][2*j+1] *= corr; }
            float sum = 0.f;
#pragma unroll
            for (int na = 0; na < 8; na++) {
                float p0 = __expf(sc[na][2*j]   - mnew);
                float p1 = __expf(sc[na][2*j+1] - mnew);
                sc[na][2*j] = p0; sc[na][2*j+1] = p1;
                sum += p0 + p1;
            }
            sum += __shfl_xor_sync(0xffffffffu, sum, 1);
            sum += __shfl_xor_sync(0xffffffffu, sum, 2);
            l[j] += sum;
        }

#pragma unroll
        for (int kp = 0; kp < 4; kp++) {
            uint32_t aph[4] = { packh(sc[2*kp][0],   sc[2*kp][1]),
                                packh(sc[2*kp][2],   sc[2*kp][3]),
                                packh(sc[2*kp+1][0], sc[2*kp+1][1]),
                                packh(sc[2*kp+1][2], sc[2*kp+1][3]) };
#pragma unroll
            for (int vp = 0; vp < 4; vp++) {
                uint32_t va = kb + 9216 + (kp*16 + (lane & 15)) * ARS
                              + (vp*2 + (lane >> 4)) * 16;
                uint32_t vh[4];
                ldsm4t(vh[0], vh[1], vh[2], vh[3], va);
                const uint32_t vh01[2] = {vh[0], vh[1]}, vh23[2] = {vh[2], vh[3]};
                mmaF(o[2*vp],   aph, vh01);
                mmaF(o[2*vp+1], aph, vh23);
            }
        }
    }

#pragma unroll
    for (int j = 0; j < 2; j++) {
        float inv = 1.f / l[j];
        int row = q0 + wq + g + j*8;
        size_t gb = (tokbase + row) * DIM + h * DK;
#pragma unroll
        for (int nd = 0; nd < 8; nd++)
            *(uint32_t*)&Ohi[gb + nd*8 + qc] = packh(o[nd][2*j]*inv, o[nd][2*j+1]*inv);
    }
}

// ---------------- BatchNorm1d + fused f16 round --------------------------------
__global__ __launch_bounds__(256)
void bn_q(float* __restrict__ X, const float* __restrict__ g, const float* __restrict__ be,
          __half* __restrict__ Xh)
{
    const int s = blockIdx.x, tid = threadIdx.x;
    const int lane = tid & 31, w = tid >> 5;
    const size_t r0 = (size_t)s * DIM, r1 = (size_t)(SEQ + s) * DIM;
    float4 v0 = ((const float4*)(X + r0))[tid];
    float4 v1 = ((const float4*)(X + r1))[tid];
    float sum = v0.x+v0.y+v0.z+v0.w + v1.x+v1.y+v1.z+v1.w;
    float sq  = v0.x*v0.x+v0.y*v0.y+v0.z*v0.z+v0.w*v0.w
              + v1.x*v1.x+v1.y*v1.y+v1.z*v1.z+v1.w*v1.w;
#pragma unroll
    for (int off = 16; off; off >>= 1) {
        sum += __shfl_xor_sync(0xffffffffu, sum, off);
        sq  += __shfl_xor_sync(0xffffffffu, sq,  off);
    }
    __shared__ float s1[8], s2[8];
    if (lane == 0) { s1[w] = sum; s2[w] = sq; }
    __syncthreads();
    sum = 0.f; sq = 0.f;
#pragma unroll
    for (int k = 0; k < 8; k++) { sum += s1[k]; sq += s2[k]; }
    const float mean = sum * (1.f/2048.f);
    const float var  = sq  * (1.f/2048.f) - mean*mean;
    const float scl  = g[s] * rsqrtf(var + 1e-5f);
    const float sh   = be[s] - mean * scl;
    v0.x = v0.x*scl + sh; v0.y = v0.y*scl + sh; v0.z = v0.z*scl + sh; v0.w = v0.w*scl + sh;
    v1.x = v1.x*scl + sh; v1.y = v1.y*scl + sh; v1.z = v1.z*scl + sh; v1.w = v1.w*scl + sh;
    ((float4*)(X + r0))[tid] = v0;
    ((float4*)(X + r1))[tid] = v1;
    uint2 hp;
    hp.x = packh(v0.x, v0.y); hp.y = packh(v0.z, v0.w);
    ((uint2*)(Xh + r0))[tid] = hp;
    hp.x = packh(v1.x, v1.y); hp.y = packh(v1.z, v1.w);
    ((uint2*)(Xh + r1))[tid] = hp;
}

// ---------------- host orchestration -------------------------------------------
extern "C" void kernel_launch(void* const* d_in, const int* in_sizes, int n_in,
                              void* d_out, int out_size)
{
    const float* x   = (const float*)d_in[0];
    const float* Wq1 = (const float*)d_in[1];  const float* bq1 = (const float*)d_in[2];
    const float* Wk1 = (const float*)d_in[3];  const float* bk1 = (const float*)d_in[4];
    const float* Wv1 = (const float*)d_in[5];  const float* bv1 = (const float*)d_in[6];
    const float* Wo1 = (const float*)d_in[7];  const float* bo1 = (const float*)d_in[8];
    const float* Wq2 = (const float*)d_in[9];  const float* bq2 = (const float*)d_in[10];
    const float* Wk2 = (const float*)d_in[11]; const float* bk2 = (const float*)d_in[12];
    const float* Wv2 = (const float*)d_in[13]; const float* bv2 = (const float*)d_in[14];
    const float* Wo2 = (const float*)d_in[15]; const float* bo2 = (const float*)d_in[16];
    const float* g1  = (const float*)d_in[17]; const float* be1 = (const float*)d_in[18];
    const float* g2  = (const float*)d_in[19]; const float* be2 = (const float*)d_in[20];
    const float* g3  = (const float*)d_in[21]; const float* be3 = (const float*)d_in[22];
    const float* W1  = (const float*)d_in[23]; const float* bf1 = (const float*)d_in[24];
    const float* W2  = (const float*)d_in[25]; const float* bf2 = (const float*)d_in[26];
    const int*   msk = (const int*)d_in[27];

    float *X, *X1, *Y, *bQ1, *bQ2;
    __half *Whi, *Xhi, *X1hi, *Yhi, *QKVhi, *Ohi, *Hhi;
    cudaGetSymbolAddress((void**)&X, g_X);       cudaGetSymbolAddress((void**)&X1, g_X1);
    cudaGetSymbolAddress((void**)&Y, g_Yb);
    cudaGetSymbolAddress((void**)&Whi, g_Whi);
    cudaGetSymbolAddress((void**)&Xhi, g_Xhi);
    cudaGetSymbolAddress((void**)&X1hi, g_X1hi);
    cudaGetSymbolAddress((void**)&Yhi, g_Yhi);
    cudaGetSymbolAddress((void**)&QKVhi, g_QKVhi);
    cudaGetSymbolAddress((void**)&Ohi, g_Ohi);
    cudaGetSymbolAddress((void**)&Hhi, g_Hhi);
    cudaGetSymbolAddress((void**)&bQ1, g_bQKV1); cudaGetSymbolAddress((void**)&bQ2, g_bQKV2);

    cudaFuncSetAttribute(gemm_tc, cudaFuncAttributeMaxDynamicSharedMemorySize, GEMM_SMEM);
    cudaFuncSetAttribute(attn_tc, cudaFuncAttributeMaxDynamicSharedMemorySize, ATT_SMEM);

    const size_t bytesD = (size_t)MROWS * DIM * sizeof(float);
    cudaMemcpyAsync(X, x, bytesD, cudaMemcpyDeviceToDevice);

    // ---- merged weight prep (1 launch) + bias concat ----
    {
        const size_t sQ = (size_t)NH * DIM * DK;
        const size_t sO = (size_t)DIM * DIM;
        WJobs jobs;
        const float* Ws[10]  = {Wq1, Wk1, Wv1, Wo1, Wq2, Wk2, Wv2, Wo2, W1, W2};
        const int Ks[10]     = {1024,1024,1024,1024,1024,1024,1024,1024,1024,4096};
        const int Ns[10]     = {1024,1024,1024,1024,1024,1024,1024,1024,4096,1024};
        const unsigned long long st[10] = {sQ,sQ,sQ,sO,sQ,sQ,sQ,sO,(size_t)DIM*FF,(size_t)FF*DIM};
        const unsigned off[10] = {OFF_Q1, OFF_Q1+(1u<<20), OFF_Q1+(2u<<20), OFF_O1,
                                  OFF_Q2, OFF_Q2+(1u<<20), OFF_Q2+(2u<<20), OFF_O2,
                                  OFF_W1, OFF_W2};
        const int hm[10] = {1,1,1,0,1,1,1,0,0,0};
        int cum = 0;
        for (int j = 0; j < 10; j++) {
            jobs.W[j] = Ws[j]; jobs.K[j] = Ks[j]; jobs.N[j] = Ns[j];
            jobs.stride[j] = st[j]; jobs.outOff[j] = off[j]; jobs.headMode[j] = hm[j];
            jobs.start[j] = cum;
            cum += (Ks[j] >> 5) * (Ns[j] >> 5) * NL;
        }
        wsplit_all<<<cum, 256>>>(jobs, Whi);
        pack_bias<<<dim3(4, NL), 256>>>(bq1, bk1, bv1, bQ1);
        pack_bias<<<dim3(4, NL), 256>>>(bq2, bk2, bv2, bQ2);
    }

    const int n4D = MROWS * DIM / 4;
    round_f32<<<n4D/256, 256>>>(X, Xhi, n4D);

    dim3 gQKV(QKVW/128, MROWS/64);   // (24,32)
    dim3 gGD(DIM/128,  MROWS/64);    // (8,32)
    dim3 gGF(FF/128,   MROWS/64);    // (32,32)
    dim3 gA(SEQ/128, NH, NB);        // (8,16,2)

    for (int l = 0; l < NL; l++) {
        const __half* WH = Whi + (size_t)l * LAYER_W;
        const size_t dO = (size_t)l * DIM, f1O = (size_t)l * FF;

        // masked self-attention (fused QKV; masked K/V tiles skipped)
        gemm_tc<<<gQKV, 256, GEMM_SMEM>>>(Xhi, WH+OFF_Q1, bQ1 + l*QKVW,
                nullptr, nullptr, QKVhi, QKVW, DIM, 0, msk);
        attn_tc<<<gA, 256, ATT_SMEM>>>(QKVhi, Ohi, msk);
        gemm_tc<<<gGD, 256, GEMM_SMEM>>>(Ohi, WH+OFF_O1, bo1+dO,
                X, X1, nullptr, DIM, DIM, 0, nullptr);
        bn_q<<<SEQ, 256>>>(X1, g1+dO, be1+dO, X1hi);

        // second (unmasked) attention; residual from block input X
        gemm_tc<<<gQKV, 256, GEMM_SMEM>>>(X1hi, WH+OFF_Q2, bQ2 + l*QKVW,
                nullptr, nullptr, QKVhi, QKVW, DIM, 0, nullptr);
        attn_tc<<<gA, 256, ATT_SMEM>>>(QKVhi, Ohi, nullptr);
        gemm_tc<<<gGD, 256, GEMM_SMEM>>>(Ohi, WH+OFF_O2, bo2+dO,
                X, Y, nullptr, DIM, DIM, 0, nullptr);
        bn_q<<<SEQ, 256>>>(Y, g2+dO, be2+dO, Yhi);

        // FFN; residual from X1
        gemm_tc<<<gGF, 256, GEMM_SMEM>>>(Yhi, WH+OFF_W1, bf1+f1O,
                nullptr, nullptr, Hhi, FF, DIM, 1, nullptr);
        gemm_tc<<<gGD, 256, GEMM_SMEM>>>(Hhi, WH+OFF_W2, bf2+dO,
                X1, X, nullptr, DIM, FF, 0, nullptr);
        bn_q<<<SEQ, 256>>>(X, g3+dO, be3+dO, Xhi);
    }

    cudaMemcpyAsync(d_out, X, bytesD, cudaMemcpyDeviceToDevice);
}

// round 14
// speedup vs baseline: 4.9003x; 1.0727x over previous
#include <cuda_runtime.h>
#include <cuda_fp16.h>
#include <cstdint>

#define NB  2
#define SEQ 1024
#define DIM 1024
#define NH  16
#define DK  64
#define FF  4096
#define NL  4
#define MROWS (NB*SEQ)
#define QKVW 3072

// ---------------- PTX helpers ------------------------------------------------
__device__ __forceinline__ uint32_t smem_to_u32(const void* p) {
    uint32_t a;
    asm("{ .reg .u64 t; cvta.to.shared.u64 t, %1; cvt.u32.u64 %0, t; }" : "=r"(a) : "l"(p));
    return a;
}
__device__ __forceinline__ void cpasync16(uint32_t dst, const void* src) {
    asm volatile("cp.async.cg.shared.global [%0], [%1], 16;"
                 :: "r"(dst), "l"(__cvta_generic_to_global(src)) : "memory");
}
__device__ __forceinline__ void cpcommit() { asm volatile("cp.async.commit_group;" ::: "memory"); }
__device__ __forceinline__ void cpwait0()  { asm volatile("cp.async.wait_group 0;" ::: "memory"); }
__device__ __forceinline__ void cpwait1()  { asm volatile("cp.async.wait_group 1;" ::: "memory"); }
__device__ __forceinline__ void ldsm4(uint32_t& r0, uint32_t& r1, uint32_t& r2, uint32_t& r3, uint32_t a) {
    asm volatile("ldmatrix.sync.aligned.m8n8.x4.shared.b16 {%0,%1,%2,%3}, [%4];"
                 : "=r"(r0), "=r"(r1), "=r"(r2), "=r"(r3) : "r"(a));
}
__device__ __forceinline__ void ldsm2(uint32_t& r0, uint32_t& r1, uint32_t a) {
    asm volatile("ldmatrix.sync.aligned.m8n8.x2.shared.b16 {%0,%1}, [%2];"
                 : "=r"(r0), "=r"(r1) : "r"(a));
}
__device__ __forceinline__ void ldsm4t(uint32_t& r0, uint32_t& r1, uint32_t& r2, uint32_t& r3, uint32_t a) {
    asm volatile("ldmatrix.sync.aligned.m8n8.x4.trans.shared.b16 {%0,%1,%2,%3}, [%4];"
                 : "=r"(r0), "=r"(r1), "=r"(r2), "=r"(r3) : "r"(a));
}
__device__ __forceinline__ void mmaF(float* d, const uint32_t* a, const uint32_t* b) {
    asm volatile("mma.sync.aligned.m16n8k16.row.col.f32.f16.f16.f32 "
                 "{%0,%1,%2,%3}, {%4,%5,%6,%7}, {%8,%9}, {%0,%1,%2,%3};"
                 : "+f"(d[0]), "+f"(d[1]), "+f"(d[2]), "+f"(d[3])
                 : "r"(a[0]), "r"(a[1]), "r"(a[2]), "r"(a[3]), "r"(b[0]), "r"(b[1]));
}
__device__ __forceinline__ uint32_t packh(float a, float b) {
    __half2 h = __floats2half2_rn(a, b);
    return *(uint32_t*)&h;
}

// ---------------- scratch -----------------------------------------------------
__device__ float g_X  [MROWS*DIM];
__device__ float g_X1 [MROWS*DIM];
__device__ float g_Yb [MROWS*DIM];
__device__ __half g_Xhi [MROWS*DIM];
__device__ __half g_X1hi[MROWS*DIM];
__device__ __half g_Yhi [MROWS*DIM];
__device__ __half g_QKVhi[MROWS*QKVW];
__device__ __half g_Ohi [MROWS*DIM];
__device__ __half g_Hhi [MROWS*FF];
__device__ __half g_Whi[64u*1024*1024];
__device__ float  g_bQKV1[NL*QKVW], g_bQKV2[NL*QKVW];

#define LAYER_W  (16u*1024*1024)
#define OFF_Q1   (0u)
#define OFF_O1   (3u*1024*1024)
#define OFF_Q2   (4u*1024*1024)
#define OFF_O2   (7u*1024*1024)
#define OFF_W1   (8u*1024*1024)
#define OFF_W2   (12u*1024*1024)

// ---------------- activation round: fp32 -> f16 --------------------------------
__global__ __launch_bounds__(256) void round_f32(const float* __restrict__ x,
        __half* __restrict__ h, int n4)
{
    int i = blockIdx.x * 256 + threadIdx.x;
    if (i >= n4) return;
    float4 v = ((const float4*)x)[i];
    uint2 hp;
    hp.x = packh(v.x, v.y); hp.y = packh(v.z, v.w);
    ((uint2*)h)[i] = hp;
}

// ------------- merged weight transpose+round (single launch, 10 jobs) ----------
struct WJobs {
    const float* W[10];
    int K[10], N[10];
    unsigned long long stride[10];
    unsigned outOff[10];
    int headMode[10];
    int start[10];
};

__global__ __launch_bounds__(256) void wsplit_all(WJobs jobs, __half* __restrict__ oh)
{
    const int bid = blockIdx.x;
    int j = 0;
#pragma unroll
    for (int q = 1; q < 10; q++) if (bid >= jobs.start[q]) j = q;
    const int K = jobs.K[j], N = jobs.N[j];
    const int headMode = jobs.headMode[j];
    const int local = bid - jobs.start[j];
    const int nbk = K >> 5;
    const int perLayer = nbk * (N >> 5);
    const int z = local / perLayer;
    const int rem = local - z * perLayer;
    const int k0 = (rem % nbk) << 5;
    const int n0 = (rem / nbk) << 5;
    const float* Win = jobs.W[j] + (size_t)z * jobs.stride[j];
    const size_t ob = (size_t)z * LAYER_W + jobs.outOff[j];

    __shared__ float t[32][33];
    const int tx = threadIdx.x & 31, ty = threadIdx.x >> 5;
#pragma unroll
    for (int i = 0; i < 4; i++) {
        int k = k0 + ty + 8*i, n = n0 + tx;
        size_t idx = headMode ? ((size_t)(n >> 6) * K * 64 + (size_t)k * 64 + (n & 63))
                              : ((size_t)k * N + n);
        t[ty + 8*i][tx] = Win[idx];
    }
    __syncthreads();
    const int nl = threadIdx.x >> 3;
    const int kq = threadIdx.x & 7;
    const int n = n0 + nl;
    uint2 hp;
    hp.x = packh(t[kq*4 + 0][nl], t[kq*4 + 1][nl]);
    hp.y = packh(t[kq*4 + 2][nl], t[kq*4 + 3][nl]);
    *(uint2*)(oh + ob + (size_t)n * K + k0 + kq*4) = hp;
}

__global__ __launch_bounds__(256) void pack_bias(const float* __restrict__ bq,
        const float* __restrict__ bk, const float* __restrict__ bv, float* __restrict__ out)
{
    int l = blockIdx.y;
    int i = blockIdx.x * 256 + threadIdx.x;
    out[l*QKVW + i]        = bq[l*1024 + i];
    out[l*QKVW + 1024 + i] = bk[l*1024 + i];
    out[l*QKVW + 2048 + i] = bv[l*1024 + i];
}

// ----------- pure-f16 HMMA GEMM (f32 acc): CTA 64x128, 3 CTAs/SM ---------------
#define RSB 144
#define SB_HI 9216
#define STAGE 27648
#define GEMM_SMEM (2*STAGE)   // 55296

__global__ __launch_bounds__(256, 3) void gemm_tc(
        const __half* __restrict__ Ah,
        const __half* __restrict__ Bh,
        const float* __restrict__ bias, const float* __restrict__ R,
        float* __restrict__ C,
        __half* __restrict__ Chi,
        int N, int K, int relu, const int* __restrict__ mskp)
{
    const int m0 = blockIdx.y * 64, n0 = blockIdx.x * 128;
    if (mskp && ((m0 & 1023) >= *mskp) && (n0 >= 1024)) return;  // masked K/V tokens
    extern __shared__ char smem[];
    const uint32_t sb = smem_to_u32(smem);
    const int tid = threadIdx.x, lane = tid & 31, wn = tid >> 5;

    float acc[4][2][4];
#pragma unroll
    for (int i = 0; i < 4; i++)
#pragma unroll
        for (int j = 0; j < 2; j++)
#pragma unroll
            for (int q = 0; q < 4; q++) acc[i][j][q] = 0.f;

    const int nch = K >> 6;
    auto issue = [&](int ch, int stg) {
        const int k0 = ch << 6;
        const uint32_t base = sb + stg * STAGE;
#pragma unroll
        for (int i = tid; i < 1536; i += 256) {
            if (i < 512) {                        // A: 64 rows x 8 vecs
                int r = i >> 3, c = i & 7;
                cpasync16(base + r * RSB + c * 16,
                          Ah + (size_t)(m0 + r) * K + k0 + c * 8);
            } else {                              // B: 128 rows x 8 vecs
                int j = i - 512, r = j >> 3, c = j & 7;
                cpasync16(base + SB_HI + r * RSB + c * 16,
                          Bh + (size_t)(n0 + r) * K + k0 + c * 8);
            }
        }
        cpcommit();
    };
    issue(0, 0);

    for (int ch = 0; ch < nch; ch++) {
        cpwait0();
        __syncthreads();
        if (ch + 1 < nch) issue(ch + 1, (ch + 1) & 1);
        const uint32_t stg = sb + (ch & 1) * STAGE;
#pragma unroll
        for (int ks = 0; ks < 4; ks++) {
            uint32_t ah[4][4], bh[2][2];
#pragma unroll
            for (int mt = 0; mt < 4; mt++) {
                uint32_t ad = stg + (mt*16 + (lane & 15)) * RSB + (lane >> 4) * 16 + ks * 32;
                ldsm4(ah[mt][0], ah[mt][1], ah[mt][2], ah[mt][3], ad);
            }
#pragma unroll
            for (int ng = 0; ng < 2; ng++) {
                uint32_t bd = stg + SB_HI + (wn*16 + ng*8 + (lane & 7)) * RSB
                              + ((lane >> 3) & 1) * 16 + ks * 32;
                ldsm2(bh[ng][0], bh[ng][1], bd);
            }
#pragma unroll
            for (int mt = 0; mt < 4; mt++)
#pragma unroll
                for (int ng = 0; ng < 2; ng++)
                    mmaF(acc[mt][ng], ah[mt], bh[ng]);
        }
    }

    const int g = lane >> 2, qc = (lane & 3) * 2;
#pragma unroll
    for (int mt = 0; mt < 4; mt++) {
        const int row0 = m0 + mt*16 + g;
        const int row1 = row0 + 8;
#pragma unroll
        for (int ng = 0; ng < 2; ng++) {
            const int col = n0 + wn*16 + ng*8 + qc;
            const float b0 = bias[col], b1 = bias[col + 1];
            float v00 = acc[mt][ng][0] + b0, v01 = acc[mt][ng][1] + b1;
            float v10 = acc[mt][ng][2] + b0, v11 = acc[mt][ng][3] + b1;
            if (R) {
                float2 r0 = *(const float2*)&R[(size_t)row0 * N + col];
                float2 r1 = *(const float2*)&R[(size_t)row1 * N + col];
                v00 += r0.x; v01 += r0.y; v10 += r1.x; v11 += r1.y;
            }
            if (relu) {
                v00 = fmaxf(v00, 0.f); v01 = fmaxf(v01, 0.f);
                v10 = fmaxf(v10, 0.f); v11 = fmaxf(v11, 0.f);
            }
            if (Chi) {
                *(uint32_t*)&Chi[(size_t)row0 * N + col] = packh(v00, v01);
                *(uint32_t*)&Chi[(size_t)row1 * N + col] = packh(v10, v11);
            } else {
                *(float2*)&C[(size_t)row0 * N + col] = make_float2(v00, v01);
                *(float2*)&C[(size_t)row1 * N + col] = make_float2(v10, v11);
            }
        }
    }
}

// ----------- HMMA flash attention: pure f16 inputs, f32 acc --------------------
#define ARS 144
#define AKV0  18432
#define AKV_STAGE 18432
#define ATT_SMEM (AKV0 + 2*AKV_STAGE)   // 55296

__global__ __launch_bounds__(256, 2) void attn_tc(
        const __half* __restrict__ QKVh,
        __half* __restrict__ Ohi,
        const int* __restrict__ mask_ptr)
{
    extern __shared__ char smem[];
    const uint32_t sb = smem_to_u32(smem);
    const int tid = threadIdx.x, lane = tid & 31, w = tid >> 5;
    const int q0 = blockIdx.x * 128, h = blockIdx.y, b = blockIdx.z;
    const int lim = mask_ptr ? *mask_ptr : SEQ;
    const size_t tokbase = (size_t)b * SEQ;
    const int cq = h * DK, ck = 1024 + h * DK, cv = 2048 + h * DK;

    for (int i = tid; i < 1024; i += 256) {
        int r = i >> 3, c = i & 7;
        cpasync16(sb + r * ARS + c * 16,
                  QKVh + (tokbase + q0 + r) * QKVW + cq + c * 8);
    }
    auto ldkv = [&](int t, int stg) {
        uint32_t base = sb + AKV0 + stg * AKV_STAGE;
        for (int i = tid; i < 512; i += 256) {
            int r = i >> 3, c = i & 7;
            uint32_t off = r * ARS + c * 16;
            size_t row = (tokbase + t * 64 + r) * QKVW;
            cpasync16(base + off,        QKVh + row + ck + c * 8);
            cpasync16(base + 9216 + off, QKVh + row + cv + c * 8);
        }
        cpcommit();
    };
    ldkv(0, 0);

    const int nt = (lim + 63) >> 6;
    const int g = lane >> 2, qc = (lane & 3) * 2;
    const int wq = w * 16;

    float m[2] = {-1e30f, -1e30f}, l[2] = {0.f, 0.f};
    float o[8][4];
#pragma unroll
    for (int i = 0; i < 8; i++)
#pragma unroll
        for (int j = 0; j < 4; j++) o[i][j] = 0.f;

    for (int t = 0; t < nt; t++) {
        __syncthreads();
        if (t + 1 < nt) { ldkv(t + 1, (t + 1) & 1); cpwait1(); }
        else           { cpwait0(); }
        __syncthreads();
        const uint32_t kb = sb + AKV0 + (t & 1) * AKV_STAGE;

        float sc[8][4];
#pragma unroll
        for (int i = 0; i < 8; i++)
#pragma unroll
            for (int j = 0; j < 4; j++) sc[i][j] = 0.f;

#pragma unroll
        for (int ks = 0; ks < 4; ks++) {
            uint32_t qa = sb + (wq + (lane & 15)) * ARS + (lane >> 4) * 16 + ks * 32;
            uint32_t qh[4];
            ldsm4(qh[0], qh[1], qh[2], qh[3], qa);
#pragma unroll
            for (int p = 0; p < 4; p++) {
                uint32_t ka = kb + (p*16 + (lane & 7) + ((lane >> 4) & 1) * 8) * ARS
                              + ((lane >> 3) & 1) * 16 + ks * 32;
                uint32_t kh[4];
                ldsm4(kh[0], kh[1], kh[2], kh[3], ka);
                const uint32_t kh01[2] = {kh[0], kh[1]}, kh23[2] = {kh[2], kh[3]};
                mmaF(sc[2*p],   qh, kh01);
                mmaF(sc[2*p+1], qh, kh23);
            }
        }

        const int t0 = t * 64;
#pragma unroll
        for (int na = 0; na < 8; na++) {
            int c0 = t0 + na*8 + qc, c1 = c0 + 1;
#pragma unroll
            for (int j = 0; j < 2; j++) {
                float s0 = sc[na][2*j]   * 0.125f;
                float s1 = sc[na][2*j+1] * 0.125f;
                sc[na][2*j]   = (c0 < lim) ? s0 : -1e30f;
                sc[na][2*j+1] = (c1 < lim) ? s1 : -1e30f;
            }
        }

#pragma unroll
        for (int j = 0; j < 2; j++) {
            float mx = -1e30f;
#pragma unroll
            for (int na = 0; na < 8; na++)
                mx = fmaxf(mx, fmaxf(sc[na][2*j], sc[na][2*j+1]));
            mx = fmaxf(mx, __shfl_xor_sync(0xffffffffu, mx, 1));
            mx = fmaxf(mx, __shfl_xor_sync(0xffffffffu, mx, 2));
            float mnew = fmaxf(m[j], mx);
            float corr = __expf(m[j] - mnew);
            l[j] *= corr;
            m[j] = mnew;
#pragma unroll
            for (int nd = 0; nd < 8; nd++) { o[nd][2*j] *= corr; o[nd][2*j+1] *= corr; }
            float sum = 0.f;
#pragma unroll
            for (int na = 0; na < 8; na++) {
                float p0 = __expf(sc[na][2*j]   - mnew);
                float p1 = __expf(sc[na][2*j+1] - mnew);
                sc[na][2*j] = p0; sc[na][2*j+1] = p1;
                sum += p0 + p1;
            }
            sum += __shfl_xor_sync(0xffffffffu, sum, 1);
            sum += __shfl_xor_sync(0xffffffffu, sum, 2);
            l[j] += sum;
        }

#pragma unroll
        for (int kp = 0; kp < 4; kp++) {
            uint32_t aph[4] = { packh(sc[2*kp][0],   sc[2*kp][1]),
                                packh(sc[2*kp][2],   sc[2*kp][3]),
                                packh(sc[2*kp+1][0], sc[2*kp+1][1]),
                                packh(sc[2*kp+1][2], sc[2*kp+1][3]) };
#pragma unroll
            for (int vp = 0; vp < 4; vp++) {
                uint32_t va = kb + 9216 + (kp*16 + (lane & 15)) * ARS
                              + (vp*2 + (lane >> 4)) * 16;
                uint32_t vh[4];
                ldsm4t(vh[0], vh[1], vh[2], vh[3], va);
                const uint32_t vh01[2] = {vh[0], vh[1]}, vh23[2] = {vh[2], vh[3]};
                mmaF(o[2*vp],   aph, vh01);
                mmaF(o[2*vp+1], aph, vh23);
            }
        }
    }

#pragma unroll
    for (int j = 0; j < 2; j++) {
        float inv = 1.f / l[j];
        int row = q0 + wq + g + j*8;
        size_t gb = (tokbase + row) * DIM + h * DK;
#pragma unroll
        for (int nd = 0; nd < 8; nd++)
            *(uint32_t*)&Ohi[gb + nd*8 + qc] = packh(o[nd][2*j]*inv, o[nd][2*j+1]*inv);
    }
}

// ---------------- BatchNorm1d + fused f16 round --------------------------------
__global__ __launch_bounds__(256)
void bn_q(float* __restrict__ X, const float* __restrict__ g, const float* __restrict__ be,
          __half* __restrict__ Xh)
{
    const int s = blockIdx.x, tid = threadIdx.x;
    const int lane = tid & 31, w = tid >> 5;
    const size_t r0 = (size_t)s * DIM, r1 = (size_t)(SEQ + s) * DIM;
    float4 v0 = ((const float4*)(X + r0))[tid];
    float4 v1 = ((const float4*)(X + r1))[tid];
    float sum = v0.x+v0.y+v0.z+v0.w + v1.x+v1.y+v1.z+v1.w;
    float sq  = v0.x*v0.x+v0.y*v0.y+v0.z*v0.z+v0.w*v0.w
              + v1.x*v1.x+v1.y*v1.y+v1.z*v1.z+v1.w*v1.w;
#pragma unroll
    for (int off = 16; off; off >>= 1) {
        sum += __shfl_xor_sync(0xffffffffu, sum, off);
        sq  += __shfl_xor_sync(0xffffffffu, sq,  off);
    }
    __shared__ float s1[8], s2[8];
    if (lane == 0) { s1[w] = sum; s2[w] = sq; }
    __syncthreads();
    sum = 0.f; sq = 0.f;
#pragma unroll
    for (int k = 0; k < 8; k++) { sum += s1[k]; sq += s2[k]; }
    const float mean = sum * (1.f/2048.f);
    const float var  = sq  * (1.f/2048.f) - mean*mean;
    const float scl  = g[s] * rsqrtf(var + 1e-5f);
    const float sh   = be[s] - mean * scl;
    v0.x = v0.x*scl + sh; v0.y = v0.y*scl + sh; v0.z = v0.z*scl + sh; v0.w = v0.w*scl + sh;
    v1.x = v1.x*scl + sh; v1.y = v1.y*scl + sh; v1.z = v1.z*scl + sh; v1.w = v1.w*scl + sh;
    ((float4*)(X + r0))[tid] = v0;
    ((float4*)(X + r1))[tid] = v1;
    uint2 hp;
    hp.x = packh(v0.x, v0.y); hp.y = packh(v0.z, v0.w);
    ((uint2*)(Xh + r0))[tid] = hp;
    hp.x = packh(v1.x, v1.y); hp.y = packh(v1.z, v1.w);
    ((uint2*)(Xh + r1))[tid] = hp;
}

// ---------------- host orchestration -------------------------------------------
extern "C" void kernel_launch(void* const* d_in, const int* in_sizes, int n_in,
                              void* d_out, int out_size)
{
    const float* x   = (const float*)d_in[0];
    const float* Wq1 = (const float*)d_in[1];  const float* bq1 = (const float*)d_in[2];
    const float* Wk1 = (const float*)d_in[3];  const float* bk1 = (const float*)d_in[4];
    const float* Wv1 = (const float*)d_in[5];  const float* bv1 = (const float*)d_in[6];
    const float* Wo1 = (const float*)d_in[7];  const float* bo1 = (const float*)d_in[8];
    const float* Wq2 = (const float*)d_in[9];  const float* bq2 = (const float*)d_in[10];
    const float* Wk2 = (const float*)d_in[11]; const float* bk2 = (const float*)d_in[12];
    const float* Wv2 = (const float*)d_in[13]; const float* bv2 = (const float*)d_in[14];
    const float* Wo2 = (const float*)d_in[15]; const float* bo2 = (const float*)d_in[16];
    const float* g1  = (const float*)d_in[17]; const float* be1 = (const float*)d_in[18];
    const float* g2  = (const float*)d_in[19]; const float* be2 = (const float*)d_in[20];
    const float* g3  = (const float*)d_in[21]; const float* be3 = (const float*)d_in[22];
    const float* W1  = (const float*)d_in[23]; const float* bf1 = (const float*)d_in[24];
    const float* W2  = (const float*)d_in[25]; const float* bf2 = (const float*)d_in[26];
    const int*   msk = (const int*)d_in[27];

    float *X, *X1, *Y, *bQ1, *bQ2;
    __half *Whi, *Xhi, *X1hi, *Yhi, *QKVhi, *Ohi, *Hhi;
    cudaGetSymbolAddress((void**)&X, g_X);       cudaGetSymbolAddress((void**)&X1, g_X1);
    cudaGetSymbolAddress((void**)&Y, g_Yb);
    cudaGetSymbolAddress((void**)&Whi, g_Whi);
    cudaGetSymbolAddress((void**)&Xhi, g_Xhi);
    cudaGetSymbolAddress((void**)&X1hi, g_X1hi);
    cudaGetSymbolAddress((void**)&Yhi, g_Yhi);
    cudaGetSymbolAddress((void**)&QKVhi, g_QKVhi);
    cudaGetSymbolAddress((void**)&Ohi, g_Ohi);
    cudaGetSymbolAddress((void**)&Hhi, g_Hhi);
    cudaGetSymbolAddress((void**)&bQ1, g_bQKV1); cudaGetSymbolAddress((void**)&bQ2, g_bQKV2);

    cudaFuncSetAttribute(gemm_tc, cudaFuncAttributeMaxDynamicSharedMemorySize, GEMM_SMEM);
    cudaFuncSetAttribute(attn_tc, cudaFuncAttributeMaxDynamicSharedMemorySize, ATT_SMEM);

    const size_t bytesD = (size_t)MROWS * DIM * sizeof(float);
    cudaMemcpyAsync(X, x, bytesD, cudaMemcpyDeviceToDevice);

    // ---- merged weight prep (1 launch) + bias concat ----
    {
        const size_t sQ = (size_t)NH * DIM * DK;
        const size_t sO = (size_t)DIM * DIM;
        WJobs jobs;
        const float* Ws[10]  = {Wq1, Wk1, Wv1, Wo1, Wq2, Wk2, Wv2, Wo2, W1, W2};
        const int Ks[10]     = {1024,1024,1024,1024,1024,1024,1024,1024,1024,4096};
        const int Ns[10]     = {1024,1024,1024,1024,1024,1024,1024,1024,4096,1024};
        const unsigned long long st[10] = {sQ,sQ,sQ,sO,sQ,sQ,sQ,sO,(size_t)DIM*FF,(size_t)FF*DIM};
        const unsigned off[10] = {OFF_Q1, OFF_Q1+(1u<<20), OFF_Q1+(2u<<20), OFF_O1,
                                  OFF_Q2, OFF_Q2+(1u<<20), OFF_Q2+(2u<<20), OFF_O2,
                                  OFF_W1, OFF_W2};
        const int hm[10] = {1,1,1,0,1,1,1,0,0,0};
        int cum = 0;
        for (int j = 0; j < 10; j++) {
            jobs.W[j] = Ws[j]; jobs.K[j] = Ks[j]; jobs.N[j] = Ns[j];
            jobs.stride[j] = st[j]; jobs.outOff[j] = off[j]; jobs.headMode[j] = hm[j];
            jobs.start[j] = cum;
            cum += (Ks[j] >> 5) * (Ns[j] >> 5) * NL;
        }
        wsplit_all<<<cum, 256>>>(jobs, Whi);
        pack_bias<<<dim3(4, NL), 256>>>(bq1, bk1, bv1, bQ1);
        pack_bias<<<dim3(4, NL), 256>>>(bq2, bk2, bv2, bQ2);
    }

    const int n4D = MROWS * DIM / 4;
    round_f32<<<n4D/256, 256>>>(X, Xhi, n4D);

    dim3 gQKV(QKVW/128, MROWS/64);   // (24,32)
    dim3 gGD(DIM/128,  MROWS/64);    // (8,32)
    dim3 gGF(FF/128,   MROWS/64);    // (32,32)
    dim3 gA(SEQ/128, NH, NB);        // (8,16,2)

    for (int l = 0; l < NL; l++) {
        const __half* WH = Whi + (size_t)l * LAYER_W;
        const size_t dO = (size_t)l * DIM, f1O = (size_t)l * FF;

        // masked self-attention (fused QKV; masked K/V tiles skipped)
        gemm_tc<<<gQKV, 256, GEMM_SMEM>>>(Xhi, WH+OFF_Q1, bQ1 + l*QKVW,
                nullptr, nullptr, QKVhi, QKVW, DIM, 0, msk);
        attn_tc<<<gA, 256, ATT_SMEM>>>(QKVhi, Ohi, msk);
        gemm_tc<<<gGD, 256, GEMM_SMEM>>>(Ohi, WH+OFF_O1, bo1+dO,
                X, X1, nullptr, DIM, DIM, 0, nullptr);
        bn_q<<<SEQ, 256>>>(X1, g1+dO, be1+dO, X1hi);

        // second (unmasked) attention; residual from block input X
        gemm_tc<<<gQKV, 256, GEMM_SMEM>>>(X1hi, WH+OFF_Q2, bQ2 + l*QKVW,
                nullptr, nullptr, QKVhi, QKVW, DIM, 0, nullptr);
        attn_tc<<<gA, 256, ATT_SMEM>>>(QKVhi, Ohi, nullptr);
        gemm_tc<<<gGD, 256, GEMM_SMEM>>>(Ohi, WH+OFF_O2, bo2+dO,
                X, Y, nullptr, DIM, DIM, 0, nullptr);
        bn_q<<<SEQ, 256>>>(Y, g2+dO, be2+dO, Yhi);

        // FFN; residual from X1
        gemm_tc<<<gGF, 256, GEMM_SMEM>>>(Yhi, WH+OFF_W1, bf1+f1O,
                nullptr, nullptr, Hhi, FF, DIM, 1, nullptr);
        gemm_tc<<<gGD, 256, GEMM_SMEM>>>(Hhi, WH+OFF_W2, bf2+dO,
                X1, X, nullptr, DIM, FF, 0, nullptr);
        bn_q<<<SEQ, 256>>>(X, g3+dO, be3+dO, Xhi);
    }

    cudaMemcpyAsync(d_out, X, bytesD, cudaMemcpyDeviceToDevice);
}

// round 15
// speedup vs baseline: 4.9410x; 1.0083x over previous
#include <cuda_runtime.h>
#include <cuda_fp16.h>
#include <cstdint>

#define NB  2
#define SEQ 1024
#define DIM 1024
#define NH  16
#define DK  64
#define FF  4096
#define NL  4
#define MROWS (NB*SEQ)
#define QKVW 3072

// ---------------- PTX helpers ------------------------------------------------
__device__ __forceinline__ uint32_t smem_to_u32(const void* p) {
    uint32_t a;
    asm("{ .reg .u64 t; cvta.to.shared.u64 t, %1; cvt.u32.u64 %0, t; }" : "=r"(a) : "l"(p));
    return a;
}
__device__ __forceinline__ void cpasync16(uint32_t dst, const void* src) {
    asm volatile("cp.async.cg.shared.global [%0], [%1], 16;"
                 :: "r"(dst), "l"(__cvta_generic_to_global(src)) : "memory");
}
__device__ __forceinline__ void cpcommit() { asm volatile("cp.async.commit_group;" ::: "memory"); }
__device__ __forceinline__ void cpwait0()  { asm volatile("cp.async.wait_group 0;" ::: "memory"); }
__device__ __forceinline__ void cpwait1()  { asm volatile("cp.async.wait_group 1;" ::: "memory"); }
__device__ __forceinline__ void ldsm4(uint32_t& r0, uint32_t& r1, uint32_t& r2, uint32_t& r3, uint32_t a) {
    asm volatile("ldmatrix.sync.aligned.m8n8.x4.shared.b16 {%0,%1,%2,%3}, [%4];"
                 : "=r"(r0), "=r"(r1), "=r"(r2), "=r"(r3) : "r"(a));
}
__device__ __forceinline__ void ldsm2(uint32_t& r0, uint32_t& r1, uint32_t a) {
    asm volatile("ldmatrix.sync.aligned.m8n8.x2.shared.b16 {%0,%1}, [%2];"
                 : "=r"(r0), "=r"(r1) : "r"(a));
}
__device__ __forceinline__ void ldsm4t(uint32_t& r0, uint32_t& r1, uint32_t& r2, uint32_t& r3, uint32_t a) {
    asm volatile("ldmatrix.sync.aligned.m8n8.x4.trans.shared.b16 {%0,%1,%2,%3}, [%4];"
                 : "=r"(r0), "=r"(r1), "=r"(r2), "=r"(r3) : "r"(a));
}
__device__ __forceinline__ void mmaF(float* d, const uint32_t* a, const uint32_t* b) {
    asm volatile("mma.sync.aligned.m16n8k16.row.col.f32.f16.f16.f32 "
                 "{%0,%1,%2,%3}, {%4,%5,%6,%7}, {%8,%9}, {%0,%1,%2,%3};"
                 : "+f"(d[0]), "+f"(d[1]), "+f"(d[2]), "+f"(d[3])
                 : "r"(a[0]), "r"(a[1]), "r"(a[2]), "r"(a[3]), "r"(b[0]), "r"(b[1]));
}
__device__ __forceinline__ uint32_t packh(float a, float b) {
    __half2 h = __floats2half2_rn(a, b);
    return *(uint32_t*)&h;
}
__device__ __forceinline__ float2 unph(uint32_t u) {
    return __half22float2(*(__half2*)&u);
}

// ---------------- scratch (all f16) --------------------------------------------
__device__ __half g_Xh  [MROWS*DIM];    // block input / post-bn3
__device__ __half g_X1h [MROWS*DIM];    // post-bn1
__device__ __half g_Yh  [MROWS*DIM];    // post-bn2
__device__ __half g_Ph  [MROWS*DIM];    // pre-BN scratch
__device__ __half g_QKVh[MROWS*QKVW];
__device__ __half g_Oh  [MROWS*DIM];
__device__ __half g_Hh  [MROWS*FF];
__device__ __half g_Whi[64u*1024*1024];
__device__ float  g_bQKV1[NL*QKVW], g_bQKV2[NL*QKVW];

#define LAYER_W  (16u*1024*1024)
#define OFF_Q1   (0u)
#define OFF_O1   (3u*1024*1024)
#define OFF_Q2   (4u*1024*1024)
#define OFF_O2   (7u*1024*1024)
#define OFF_W1   (8u*1024*1024)
#define OFF_W2   (12u*1024*1024)

// ---------------- activation round: fp32 -> f16 --------------------------------
__global__ __launch_bounds__(256) void round_f32(const float* __restrict__ x,
        __half* __restrict__ h, int n4)
{
    int i = blockIdx.x * 256 + threadIdx.x;
    if (i >= n4) return;
    float4 v = ((const float4*)x)[i];
    uint2 hp;
    hp.x = packh(v.x, v.y); hp.y = packh(v.z, v.w);
    ((uint2*)h)[i] = hp;
}

// ------------- merged weight transpose+round (single launch, 10 jobs) ----------
struct WJobs {
    const float* W[10];
    int K[10], N[10];
    unsigned long long stride[10];
    unsigned outOff[10];
    int headMode[10];
    int start[10];
};

__global__ __launch_bounds__(256) void wsplit_all(WJobs jobs, __half* __restrict__ oh)
{
    const int bid = blockIdx.x;
    int j = 0;
#pragma unroll
    for (int q = 1; q < 10; q++) if (bid >= jobs.start[q]) j = q;
    const int K = jobs.K[j], N = jobs.N[j];
    const int headMode = jobs.headMode[j];
    const int local = bid - jobs.start[j];
    const int nbk = K >> 5;
    const int perLayer = nbk * (N >> 5);
    const int z = local / perLayer;
    const int rem = local - z * perLayer;
    const int k0 = (rem % nbk) << 5;
    const int n0 = (rem / nbk) << 5;
    const float* Win = jobs.W[j] + (size_t)z * jobs.stride[j];
    const size_t ob = (size_t)z * LAYER_W + jobs.outOff[j];

    __shared__ float t[32][33];
    const int tx = threadIdx.x & 31, ty = threadIdx.x >> 5;
#pragma unroll
    for (int i = 0; i < 4; i++) {
        int k = k0 + ty + 8*i, n = n0 + tx;
        size_t idx = headMode ? ((size_t)(n >> 6) * K * 64 + (size_t)k * 64 + (n & 63))
                              : ((size_t)k * N + n);
        t[ty + 8*i][tx] = Win[idx];
    }
    __syncthreads();
    const int nl = threadIdx.x >> 3;
    const int kq = threadIdx.x & 7;
    const int n = n0 + nl;
    uint2 hp;
    hp.x = packh(t[kq*4 + 0][nl], t[kq*4 + 1][nl]);
    hp.y = packh(t[kq*4 + 2][nl], t[kq*4 + 3][nl]);
    *(uint2*)(oh + ob + (size_t)n * K + k0 + kq*4) = hp;
}

__global__ __launch_bounds__(256) void pack_bias(const float* __restrict__ bq,
        const float* __restrict__ bk, const float* __restrict__ bv, float* __restrict__ out)
{
    int l = blockIdx.y;
    int i = blockIdx.x * 256 + threadIdx.x;
    out[l*QKVW + i]        = bq[l*1024 + i];
    out[l*QKVW + 1024 + i] = bk[l*1024 + i];
    out[l*QKVW + 2048 + i] = bv[l*1024 + i];
}

// ----------- pure-f16 HMMA GEMM (f32 acc), f16 residual, f16 out ---------------
#define RSB 144
#define SB_HI 9216
#define STAGE 27648
#define GEMM_SMEM (2*STAGE)   // 55296

__global__ __launch_bounds__(256, 3) void gemm_tc(
        const __half* __restrict__ Ah,
        const __half* __restrict__ Bh,
        const float* __restrict__ bias, const __half* __restrict__ Rh,
        __half* __restrict__ Chi,
        int N, int K, int relu, const int* __restrict__ mskp)
{
    const int m0 = blockIdx.y * 64, n0 = blockIdx.x * 128;
    if (mskp && ((m0 & 1023) >= *mskp) && (n0 >= 1024)) return;  // masked K/V tokens
    extern __shared__ char smem[];
    const uint32_t sb = smem_to_u32(smem);
    const int tid = threadIdx.x, lane = tid & 31, wn = tid >> 5;

    float acc[4][2][4];
#pragma unroll
    for (int i = 0; i < 4; i++)
#pragma unroll
        for (int j = 0; j < 2; j++)
#pragma unroll
            for (int q = 0; q < 4; q++) acc[i][j][q] = 0.f;

    const int nch = K >> 6;
    auto issue = [&](int ch, int stg) {
        const int k0 = ch << 6;
        const uint32_t base = sb + stg * STAGE;
#pragma unroll
        for (int i = tid; i < 1536; i += 256) {
            if (i < 512) {
                int r = i >> 3, c = i & 7;
                cpasync16(base + r * RSB + c * 16,
                          Ah + (size_t)(m0 + r) * K + k0 + c * 8);
            } else {
                int j = i - 512, r = j >> 3, c = j & 7;
                cpasync16(base + SB_HI + r * RSB + c * 16,
                          Bh + (size_t)(n0 + r) * K + k0 + c * 8);
            }
        }
        cpcommit();
    };
    issue(0, 0);

    for (int ch = 0; ch < nch; ch++) {
        cpwait0();
        __syncthreads();
        if (ch + 1 < nch) issue(ch + 1, (ch + 1) & 1);
        const uint32_t stg = sb + (ch & 1) * STAGE;
#pragma unroll
        for (int ks = 0; ks < 4; ks++) {
            uint32_t ah[4][4], bh[2][2];
#pragma unroll
            for (int mt = 0; mt < 4; mt++) {
                uint32_t ad = stg + (mt*16 + (lane & 15)) * RSB + (lane >> 4) * 16 + ks * 32;
                ldsm4(ah[mt][0], ah[mt][1], ah[mt][2], ah[mt][3], ad);
            }
#pragma unroll
            for (int ng = 0; ng < 2; ng++) {
                uint32_t bd = stg + SB_HI + (wn*16 + ng*8 + (lane & 7)) * RSB
                              + ((lane >> 3) & 1) * 16 + ks * 32;
                ldsm2(bh[ng][0], bh[ng][1], bd);
            }
#pragma unroll
            for (int mt = 0; mt < 4; mt++)
#pragma unroll
                for (int ng = 0; ng < 2; ng++)
                    mmaF(acc[mt][ng], ah[mt], bh[ng]);
        }
    }

    const int g = lane >> 2, qc = (lane & 3) * 2;
#pragma unroll
    for (int mt = 0; mt < 4; mt++) {
        const int row0 = m0 + mt*16 + g;
        const int row1 = row0 + 8;
#pragma unroll
        for (int ng = 0; ng < 2; ng++) {
            const int col = n0 + wn*16 + ng*8 + qc;
            const float b0 = bias[col], b1 = bias[col + 1];
            float v00 = acc[mt][ng][0] + b0, v01 = acc[mt][ng][1] + b1;
            float v10 = acc[mt][ng][2] + b0, v11 = acc[mt][ng][3] + b1;
            if (Rh) {
                float2 r0 = unph(*(const uint32_t*)&Rh[(size_t)row0 * N + col]);
                float2 r1 = unph(*(const uint32_t*)&Rh[(size_t)row1 * N + col]);
                v00 += r0.x; v01 += r0.y; v10 += r1.x; v11 += r1.y;
            }
            if (relu) {
                v00 = fmaxf(v00, 0.f); v01 = fmaxf(v01, 0.f);
                v10 = fmaxf(v10, 0.f); v11 = fmaxf(v11, 0.f);
            }
            *(uint32_t*)&Chi[(size_t)row0 * N + col] = packh(v00, v01);
            *(uint32_t*)&Chi[(size_t)row1 * N + col] = packh(v10, v11);
        }
    }
}

// ----------- HMMA flash attention: pure f16 inputs, f32 acc --------------------
#define ARS 144
#define AKV0  18432
#define AKV_STAGE 18432
#define ATT_SMEM (AKV0 + 2*AKV_STAGE)   // 55296

__global__ __launch_bounds__(256, 2) void attn_tc(
        const __half* __restrict__ QKVh,
        __half* __restrict__ Ohi,
        const int* __restrict__ mask_ptr)
{
    extern __shared__ char smem[];
    const uint32_t sb = smem_to_u32(smem);
    const int tid = threadIdx.x, lane = tid & 31, w = tid >> 5;
    const int q0 = blockIdx.x * 128, h = blockIdx.y, b = blockIdx.z;
    const int lim = mask_ptr ? *mask_ptr : SEQ;
    const size_t tokbase = (size_t)b * SEQ;
    const int cq = h * DK, ck = 1024 + h * DK, cv = 2048 + h * DK;

    for (int i = tid; i < 1024; i += 256) {
        int r = i >> 3, c = i & 7;
        cpasync16(sb + r * ARS + c * 16,
                  QKVh + (tokbase + q0 + r) * QKVW + cq + c * 8);
    }
    auto ldkv = [&](int t, int stg) {
        uint32_t base = sb + AKV0 + stg * AKV_STAGE;
        for (int i = tid; i < 512; i += 256) {
            int r = i >> 3, c = i & 7;
            uint32_t off = r * ARS + c * 16;
            size_t row = (tokbase + t * 64 + r) * QKVW;
            cpasync16(base + off,        QKVh + row + ck + c * 8);
            cpasync16(base + 9216 + off, QKVh + row + cv + c * 8);
        }
        cpcommit();
    };
    ldkv(0, 0);

    const int nt = (lim + 63) >> 6;
    const int g = lane >> 2, qc = (lane & 3) * 2;
    const int wq = w * 16;

    float m[2] = {-1e30f, -1e30f}, l[2] = {0.f, 0.f};
    float o[8][4];
#pragma unroll
    for (int i = 0; i < 8; i++)
#pragma unroll
        for (int j = 0; j < 4; j++) o[i][j] = 0.f;

    for (int t = 0; t < nt; t++) {
        __syncthreads();
        if (t + 1 < nt) { ldkv(t + 1, (t + 1) & 1); cpwait1(); }
        else           { cpwait0(); }
        __syncthreads();
        const uint32_t kb = sb + AKV0 + (t & 1) * AKV_STAGE;

        float sc[8][4];
#pragma unroll
        for (int i = 0; i < 8; i++)
#pragma unroll
            for (int j = 0; j < 4; j++) sc[i][j] = 0.f;

#pragma unroll
        for (int ks = 0; ks < 4; ks++) {
            uint32_t qa = sb + (wq + (lane & 15)) * ARS + (lane >> 4) * 16 + ks * 32;
            uint32_t qh[4];
            ldsm4(qh[0], qh[1], qh[2], qh[3], qa);
#pragma unroll
            for (int p = 0; p < 4; p++) {
                uint32_t ka = kb + (p*16 + (lane & 7) + ((lane >> 4) & 1) * 8) * ARS
                              + ((lane >> 3) & 1) * 16 + ks * 32;
                uint32_t kh[4];
                ldsm4(kh[0], kh[1], kh[2], kh[3], ka);
                const uint32_t kh01[2] = {kh[0], kh[1]}, kh23[2] = {kh[2], kh[3]};
                mmaF(sc[2*p],   qh, kh01);
                mmaF(sc[2*p+1], qh, kh23);
            }
        }

        const int t0 = t * 64;
#pragma unroll
        for (int na = 0; na < 8; na++) {
            int c0 = t0 + na*8 + qc, c1 = c0 + 1;
#pragma unroll
            for (int j = 0; j < 2; j++) {
                float s0 = sc[na][2*j]   * 0.125f;
                float s1 = sc[na][2*j+1] * 0.125f;
                sc[na][2*j]   = (c0 < lim) ? s0 : -1e30f;
                sc[na][2*j+1] = (c1 < lim) ? s1 : -1e30f;
            }
        }

#pragma unroll
        for (int j = 0; j < 2; j++) {
            float mx = -1e30f;
#pragma unroll
            for (int na = 0; na < 8; na++)
                mx = fmaxf(mx, fmaxf(sc[na][2*j], sc[na][2*j+1]));
            mx = fmaxf(mx, __shfl_xor_sync(0xffffffffu, mx, 1));
            mx = fmaxf(mx, __shfl_xor_sync(0xffffffffu, mx, 2));
            float mnew = fmaxf(m[j], mx);
            float corr = __expf(m[j] - mnew);
            l[j] *= corr;
            m[j] = mnew;
#pragma unroll
            for (int nd = 0; nd < 8; nd++) { o[nd][2*j] *= corr; o[nd][2*j+1] *= corr; }
            float sum = 0.f;
#pragma unroll
            for (int na = 0; na < 8; na++) {
                float p0 = __expf(sc[na][2*j]   - mnew);
                float p1 = __expf(sc[na][2*j+1] - mnew);
                sc[na][2*j] = p0; sc[na][2*j+1] = p1;
                sum += p0 + p1;
            }
            sum += __shfl_xor_sync(0xffffffffu, sum, 1);
            sum += __shfl_xor_sync(0xffffffffu, sum, 2);
            l[j] += sum;
        }

#pragma unroll
        for (int kp = 0; kp < 4; kp++) {
            uint32_t aph[4] = { packh(sc[2*kp][0],   sc[2*kp][1]),
                                packh(sc[2*kp][2],   sc[2*kp][3]),
                                packh(sc[2*kp+1][0], sc[2*kp+1][1]),
                                packh(sc[2*kp+1][2], sc[2*kp+1][3]) };
#pragma unroll
            for (int vp = 0; vp < 4; vp++) {
                uint32_t va = kb + 9216 + (kp*16 + (lane & 15)) * ARS
                              + (vp*2 + (lane >> 4)) * 16;
                uint32_t vh[4];
                ldsm4t(vh[0], vh[1], vh[2], vh[3], va);
                const uint32_t vh01[2] = {vh[0], vh[1]}, vh23[2] = {vh[2], vh[3]};
                mmaF(o[2*vp],   aph, vh01);
                mmaF(o[2*vp+1], aph, vh23);
            }
        }
    }

#pragma unroll
    for (int j = 0; j < 2; j++) {
        float inv = 1.f / l[j];
        int row = q0 + wq + g + j*8;
        size_t gb = (tokbase + row) * DIM + h * DK;
#pragma unroll
        for (int nd = 0; nd < 8; nd++)
            *(uint32_t*)&Ohi[gb + nd*8 + qc] = packh(o[nd][2*j]*inv, o[nd][2*j+1]*inv);
    }
}

// ---------------- BatchNorm1d: f16 in, f16 out (+optional fp32 out) ------------
__global__ __launch_bounds__(256)
void bn_q(const __half* __restrict__ P, const float* __restrict__ g,
          const float* __restrict__ be,
          __half* __restrict__ Xh, float* __restrict__ Xf)
{
    const int s = blockIdx.x, tid = threadIdx.x;
    const int lane = tid & 31, w = tid >> 5;
    const size_t r0 = (size_t)s * DIM, r1 = (size_t)(SEQ + s) * DIM;
    uint2 a0 = ((const uint2*)(P + r0))[tid];
    uint2 a1 = ((const uint2*)(P + r1))[tid];
    float2 p00 = unph(a0.x), p01 = unph(a0.y);
    float2 p10 = unph(a1.x), p11 = unph(a1.y);
    float4 v0 = make_float4(p00.x, p00.y, p01.x, p01.y);
    float4 v1 = make_float4(p10.x, p10.y, p11.x, p11.y);
    float sum = v0.x+v0.y+v0.z+v0.w + v1.x+v1.y+v1.z+v1.w;
    float sq  = v0.x*v0.x+v0.y*v0.y+v0.z*v0.z+v0.w*v0.w
              + v1.x*v1.x+v1.y*v1.y+v1.z*v1.z+v1.w*v1.w;
#pragma unroll
    for (int off = 16; off; off >>= 1) {
        sum += __shfl_xor_sync(0xffffffffu, sum, off);
        sq  += __shfl_xor_sync(0xffffffffu, sq,  off);
    }
    __shared__ float s1[8], s2[8];
    if (lane == 0) { s1[w] = sum; s2[w] = sq; }
    __syncthreads();
    sum = 0.f; sq = 0.f;
#pragma unroll
    for (int k = 0; k < 8; k++) { sum += s1[k]; sq += s2[k]; }
    const float mean = sum * (1.f/2048.f);
    const float var  = sq  * (1.f/2048.f) - mean*mean;
    const float scl  = g[s] * rsqrtf(var + 1e-5f);
    const float sh   = be[s] - mean * scl;
    v0.x = v0.x*scl + sh; v0.y = v0.y*scl + sh; v0.z = v0.z*scl + sh; v0.w = v0.w*scl + sh;
    v1.x = v1.x*scl + sh; v1.y = v1.y*scl + sh; v1.z = v1.z*scl + sh; v1.w = v1.w*scl + sh;
    uint2 hp;
    hp.x = packh(v0.x, v0.y); hp.y = packh(v0.z, v0.w);
    ((uint2*)(Xh + r0))[tid] = hp;
    hp.x = packh(v1.x, v1.y); hp.y = packh(v1.z, v1.w);
    ((uint2*)(Xh + r1))[tid] = hp;
    if (Xf) {
        ((float4*)(Xf + r0))[tid] = v0;
        ((float4*)(Xf + r1))[tid] = v1;
    }
}

// ---------------- host orchestration -------------------------------------------
extern "C" void kernel_launch(void* const* d_in, const int* in_sizes, int n_in,
                              void* d_out, int out_size)
{
    const float* x   = (const float*)d_in[0];
    const float* Wq1 = (const float*)d_in[1];  const float* bq1 = (const float*)d_in[2];
    const float* Wk1 = (const float*)d_in[3];  const float* bk1 = (const float*)d_in[4];
    const float* Wv1 = (const float*)d_in[5];  const float* bv1 = (const float*)d_in[6];
    const float* Wo1 = (const float*)d_in[7];  const float* bo1 = (const float*)d_in[8];
    const float* Wq2 = (const float*)d_in[9];  const float* bq2 = (const float*)d_in[10];
    const float* Wk2 = (const float*)d_in[11]; const float* bk2 = (const float*)d_in[12];
    const float* Wv2 = (const float*)d_in[13]; const float* bv2 = (const float*)d_in[14];
    const float* Wo2 = (const float*)d_in[15]; const float* bo2 = (const float*)d_in[16];
    const float* g1  = (const float*)d_in[17]; const float* be1 = (const float*)d_in[18];
    const float* g2  = (const float*)d_in[19]; const float* be2 = (const float*)d_in[20];
    const float* g3  = (const float*)d_in[21]; const float* be3 = (const float*)d_in[22];
    const float* W1  = (const float*)d_in[23]; const float* bf1 = (const float*)d_in[24];
    const float* W2  = (const float*)d_in[25]; const float* bf2 = (const float*)d_in[26];
    const int*   msk = (const int*)d_in[27];

    float *bQ1, *bQ2;
    __half *Whi, *Xh, *X1h, *Yh, *Ph, *QKVh, *Oh, *Hh;
    cudaGetSymbolAddress((void**)&Whi, g_Whi);
    cudaGetSymbolAddress((void**)&Xh,  g_Xh);
    cudaGetSymbolAddress((void**)&X1h, g_X1h);
    cudaGetSymbolAddress((void**)&Yh,  g_Yh);
    cudaGetSymbolAddress((void**)&Ph,  g_Ph);
    cudaGetSymbolAddress((void**)&QKVh, g_QKVh);
    cudaGetSymbolAddress((void**)&Oh,  g_Oh);
    cudaGetSymbolAddress((void**)&Hh,  g_Hh);
    cudaGetSymbolAddress((void**)&bQ1, g_bQKV1); cudaGetSymbolAddress((void**)&bQ2, g_bQKV2);

    cudaFuncSetAttribute(gemm_tc, cudaFuncAttributeMaxDynamicSharedMemorySize, GEMM_SMEM);
    cudaFuncSetAttribute(attn_tc, cudaFuncAttributeMaxDynamicSharedMemorySize, ATT_SMEM);

    // ---- merged weight prep (1 launch) + bias concat ----
    {
        const size_t sQ = (size_t)NH * DIM * DK;
        const size_t sO = (size_t)DIM * DIM;
        WJobs jobs;
        const float* Ws[10]  = {Wq1, Wk1, Wv1, Wo1, Wq2, Wk2, Wv2, Wo2, W1, W2};
        const int Ks[10]     = {1024,1024,1024,1024,1024,1024,1024,1024,1024,4096};
        const int Ns[10]     = {1024,1024,1024,1024,1024,1024,1024,1024,4096,1024};
        const unsigned long long st[10] = {sQ,sQ,sQ,sO,sQ,sQ,sQ,sO,(size_t)DIM*FF,(size_t)FF*DIM};
        const unsigned off[10] = {OFF_Q1, OFF_Q1+(1u<<20), OFF_Q1+(2u<<20), OFF_O1,
                                  OFF_Q2, OFF_Q2+(1u<<20), OFF_Q2+(2u<<20), OFF_O2,
                                  OFF_W1, OFF_W2};
        const int hm[10] = {1,1,1,0,1,1,1,0,0,0};
        int cum = 0;
        for (int j = 0; j < 10; j++) {
            jobs.W[j] = Ws[j]; jobs.K[j] = Ks[j]; jobs.N[j] = Ns[j];
            jobs.stride[j] = st[j]; jobs.outOff[j] = off[j]; jobs.headMode[j] = hm[j];
            jobs.start[j] = cum;
            cum += (Ks[j] >> 5) * (Ns[j] >> 5) * NL;
        }
        wsplit_all<<<cum, 256>>>(jobs, Whi);
        pack_bias<<<dim3(4, NL), 256>>>(bq1, bk1, bv1, bQ1);
        pack_bias<<<dim3(4, NL), 256>>>(bq2, bk2, bv2, bQ2);
    }

    const int n4D = MROWS * DIM / 4;
    round_f32<<<n4D/256, 256>>>(x, Xh, n4D);

    dim3 gQKV(QKVW/128, MROWS/64);   // (24,32)
    dim3 gGD(DIM/128,  MROWS/64);    // (8,32)
    dim3 gGF(FF/128,   MROWS/64);    // (32,32)
    dim3 gA(SEQ/128, NH, NB);        // (8,16,2)

    for (int l = 0; l < NL; l++) {
        const __half* WH = Whi + (size_t)l * LAYER_W;
        const size_t dO = (size_t)l * DIM, f1O = (size_t)l * FF;
        float* outF = (l == NL-1) ? (float*)d_out : nullptr;

        // masked self-attention (fused QKV; masked K/V tiles skipped)
        gemm_tc<<<gQKV, 256, GEMM_SMEM>>>(Xh, WH+OFF_Q1, bQ1 + l*QKVW,
                nullptr, QKVh, QKVW, DIM, 0, msk);
        attn_tc<<<gA, 256, ATT_SMEM>>>(QKVh, Oh, msk);
        gemm_tc<<<gGD, 256, GEMM_SMEM>>>(Oh, WH+OFF_O1, bo1+dO,
                Xh, Ph, DIM, DIM, 0, nullptr);
        bn_q<<<SEQ, 256>>>(Ph, g1+dO, be1+dO, X1h, nullptr);

        // second (unmasked) attention; residual from block input Xh
        gemm_tc<<<gQKV, 256, GEMM_SMEM>>>(X1h, WH+OFF_Q2, bQ2 + l*QKVW,
                nullptr, QKVh, QKVW, DIM, 0, nullptr);
        attn_tc<<<gA, 256, ATT_SMEM>>>(QKVh, Oh, nullptr);
        gemm_tc<<<gGD, 256, GEMM_SMEM>>>(Oh, WH+OFF_O2, bo2+dO,
                Xh, Ph, DIM, DIM, 0, nullptr);
        bn_q<<<SEQ, 256>>>(Ph, g2+dO, be2+dO, Yh, nullptr);

        // FFN; residual from X1h
        gemm_tc<<<gGF, 256, GEMM_SMEM>>>(Yh, WH+OFF_W1, bf1+f1O,
                nullptr, Hh, FF, DIM, 1, nullptr);
        gemm_tc<<<gGD, 256, GEMM_SMEM>>>(Hh, WH+OFF_W2, bf2+dO,
                X1h, Ph, DIM, FF, 0, nullptr);
        bn_q<<<SEQ, 256>>>(Ph, g3+dO, be3+dO, Xh, outF);
    }
}